// round 2
// baseline (speedup 1.0000x reference)
#include <cuda_runtime.h>
#include <math.h>

#define B_  8
#define S_  1024
#define D_  768
#define H_  12
#define DH_ 64
#define F_  3072
#define NROWS (B_*S_)   /* 8192 */

#define EPI_NONE 0
#define EPI_GELU 1
#define EPI_ADD  2

// ---------------------------------------------------------------------------
// Scratch (device globals — no allocation allowed)
// ---------------------------------------------------------------------------
__device__ float g_h  [NROWS*D_];
__device__ float g_q  [NROWS*D_];
__device__ float g_k  [NROWS*D_];
__device__ float g_v  [NROWS*D_];
__device__ float g_ctx[NROWS*D_];
__device__ float g_x2 [NROWS*D_];
__device__ float g_ln2[NROWS*D_];
__device__ float g_act[NROWS*F_];

// ---------------------------------------------------------------------------
// LayerNorm: one block per row, 256 threads, D=768 = 3 elems/thread
// ---------------------------------------------------------------------------
__global__ __launch_bounds__(256) void ln_kernel(
    const float* __restrict__ x, const float* __restrict__ gam,
    const float* __restrict__ bet, float* __restrict__ out)
{
    int row = blockIdx.x;
    int tid = threadIdx.x;
    const float* xr = x + (size_t)row * D_;
    float v0 = xr[tid], v1 = xr[tid + 256], v2 = xr[tid + 512];
    float s  = v0 + v1 + v2;
    float ss = v0*v0 + v1*v1 + v2*v2;
    #pragma unroll
    for (int o = 16; o > 0; o >>= 1) {
        s  += __shfl_xor_sync(0xffffffffu, s,  o);
        ss += __shfl_xor_sync(0xffffffffu, ss, o);
    }
    __shared__ float rs[8], rss[8];
    __shared__ float s_mu, s_inv;
    int w = tid >> 5, lane = tid & 31;
    if (lane == 0) { rs[w] = s; rss[w] = ss; }
    __syncthreads();
    if (tid == 0) {
        float ts = 0.f, tss = 0.f;
        #pragma unroll
        for (int i = 0; i < 8; i++) { ts += rs[i]; tss += rss[i]; }
        float mu  = ts * (1.0f / D_);
        float var = tss * (1.0f / D_) - mu * mu;
        s_mu = mu;
        s_inv = rsqrtf(var + 1e-6f);
    }
    __syncthreads();
    float mu = s_mu, inv = s_inv;
    float* orow = out + (size_t)row * D_;
    orow[tid]       = (v0 - mu) * inv * gam[tid]       + bet[tid];
    orow[tid + 256] = (v1 - mu) * inv * gam[tid + 256] + bet[tid + 256];
    orow[tid + 512] = (v2 - mu) * inv * gam[tid + 512] + bet[tid + 512];
}

// ---------------------------------------------------------------------------
// SGEMM: 128x128 tile, BK=8, 256 threads, 8x8 microtile (4+4 split),
// double-buffered SMEM, fused bias + epilogue.
// C[M,N] = A[M,K] @ B[K,N] + bias; EPI: none / gelu(erf) / +residual
// ---------------------------------------------------------------------------
__device__ __forceinline__ float gelu_f(float x) {
    return 0.5f * x * (1.0f + erff(x * 0.70710678118654752f));
}

template<int EPI>
__device__ __forceinline__ void sgemm_body(
    const float* __restrict__ A, const float* __restrict__ Bm,
    const float* __restrict__ bias, const float* __restrict__ res,
    float* __restrict__ C, int M, int N, int K)
{
    __shared__ float As[2][8][128];
    __shared__ float Bs[2][8][128];
    int tid = threadIdx.x;
    int bm = blockIdx.y * 128, bn = blockIdx.x * 128;
    int arow = tid >> 1, acol = (tid & 1) * 4;     // A tile 128x8
    int brow = tid >> 5, bcol = (tid & 31) * 4;    // B tile 8x128
    const float* Ap = A  + (size_t)(bm + arow) * K + acol;
    const float* Bp = Bm + (size_t)brow * N + bn + bcol;
    int trow = (tid >> 4) * 4, tcol = (tid & 15) * 4;

    float acc[8][8];
    #pragma unroll
    for (int i = 0; i < 8; i++)
        #pragma unroll
        for (int j = 0; j < 8; j++) acc[i][j] = 0.f;

    float4 a4 = *(const float4*)Ap;
    float4 b4 = *(const float4*)Bp;
    As[0][acol+0][arow] = a4.x; As[0][acol+1][arow] = a4.y;
    As[0][acol+2][arow] = a4.z; As[0][acol+3][arow] = a4.w;
    *(float4*)&Bs[0][brow][bcol] = b4;
    __syncthreads();

    int nk = K >> 3;
    for (int kt = 0; kt < nk; kt++) {
        int cur = kt & 1;
        if (kt + 1 < nk) {
            a4 = *(const float4*)(Ap + (size_t)(kt+1)*8);
            b4 = *(const float4*)(Bp + (size_t)(kt+1)*8*N);
        }
        #pragma unroll
        for (int kk = 0; kk < 8; kk++) {
            float ar[8], br[8];
            *(float4*)&ar[0] = *(const float4*)&As[cur][kk][trow];
            *(float4*)&ar[4] = *(const float4*)&As[cur][kk][trow + 64];
            *(float4*)&br[0] = *(const float4*)&Bs[cur][kk][tcol];
            *(float4*)&br[4] = *(const float4*)&Bs[cur][kk][tcol + 64];
            #pragma unroll
            for (int i = 0; i < 8; i++)
                #pragma unroll
                for (int j = 0; j < 8; j++)
                    acc[i][j] += ar[i] * br[j];
        }
        if (kt + 1 < nk) {
            int nxt = cur ^ 1;
            As[nxt][acol+0][arow] = a4.x; As[nxt][acol+1][arow] = a4.y;
            As[nxt][acol+2][arow] = a4.z; As[nxt][acol+3][arow] = a4.w;
            *(float4*)&Bs[nxt][brow][bcol] = b4;
            __syncthreads();
        }
    }

    // epilogue
    #pragma unroll
    for (int i = 0; i < 8; i++) {
        int row = bm + trow + (i < 4 ? i : 60 + i);
        #pragma unroll
        for (int jh = 0; jh < 2; jh++) {
            int col = bn + tcol + jh * 64;
            float4 bb = *(const float4*)&bias[col];
            float vals[4];
            vals[0] = acc[i][jh*4+0] + bb.x;
            vals[1] = acc[i][jh*4+1] + bb.y;
            vals[2] = acc[i][jh*4+2] + bb.z;
            vals[3] = acc[i][jh*4+3] + bb.w;
            if (EPI == EPI_GELU) {
                #pragma unroll
                for (int j = 0; j < 4; j++) vals[j] = gelu_f(vals[j]);
            }
            if (EPI == EPI_ADD) {
                float4 rr = *(const float4*)&res[(size_t)row * N + col];
                vals[0] += rr.x; vals[1] += rr.y; vals[2] += rr.z; vals[3] += rr.w;
            }
            float4 outv = make_float4(vals[0], vals[1], vals[2], vals[3]);
            *(float4*)&C[(size_t)row * N + col] = outv;
        }
    }
}

template<int EPI>
__global__ __launch_bounds__(256) void sgemm_kernel(
    const float* __restrict__ A, const float* __restrict__ Bm,
    const float* __restrict__ bias, const float* __restrict__ res,
    float* __restrict__ C, int M, int N, int K)
{
    sgemm_body<EPI>(A, Bm, bias, res, C, M, N, K);
}

// QKV batched: blockIdx.z selects W/bias/output — one launch, better balance
__global__ __launch_bounds__(256) void sgemm_qkv_kernel(
    const float* __restrict__ A,
    const float* __restrict__ Wq, const float* __restrict__ Wk, const float* __restrict__ Wv,
    const float* __restrict__ bq, const float* __restrict__ bk, const float* __restrict__ bv,
    float* __restrict__ Cq, float* __restrict__ Ck, float* __restrict__ Cv)
{
    const float* Bm  = (blockIdx.z == 0) ? Wq : (blockIdx.z == 1) ? Wk : Wv;
    const float* bia = (blockIdx.z == 0) ? bq : (blockIdx.z == 1) ? bk : bv;
    float*       C   = (blockIdx.z == 0) ? Cq : (blockIdx.z == 1) ? Ck : Cv;
    sgemm_body<EPI_NONE>(A, Bm, bia, nullptr, C, NROWS, D_, D_);
}

// ---------------------------------------------------------------------------
// Fused attention (flash-style): block = (b, h, 64 query rows), K-tiles of 64.
// Q/K stored transposed (d-major) in SMEM so both inner GEMMs are the same
// conflict-free 4x4-microtile pattern. Online softmax in SMEM, O in registers.
// ---------------------------------------------------------------------------
struct AttnSmem {
    float Qst[64][68];   // Q^T (d-major), pre-scaled by 1/sqrt(DH)
    float Kst[64][68];   // K^T (d-major)
    float Vs [64][68];   // V natural [key][d]
    float Pst[64][68];   // scores / probs, [key][q] (S^T)
    float m[64];
    float l[64];
    float corr[64];
    float red[4][64];
};

__global__ __launch_bounds__(256) void attn_kernel(
    const float* __restrict__ q, const float* __restrict__ k,
    const float* __restrict__ v, float* __restrict__ ctx)
{
    extern __shared__ char smem_raw[];
    AttnSmem* S = (AttnSmem*)smem_raw;
    int bb = blockIdx.z, hh = blockIdx.y;
    int q0 = blockIdx.x * 64;
    int tid = threadIdx.x;
    int lr = tid >> 2;              // load row (0..63)
    int ld = (tid & 3) * 16;        // load d base

    // load Q^T, pre-scaled
    {
        const float* gq = q + ((size_t)((bb*S_ + q0 + lr)*H_ + hh))*DH_ + ld;
        #pragma unroll
        for (int c = 0; c < 4; c++) {
            float4 t = *(const float4*)(gq + c*4);
            int d = ld + c*4;
            S->Qst[d+0][lr] = t.x * 0.125f;
            S->Qst[d+1][lr] = t.y * 0.125f;
            S->Qst[d+2][lr] = t.z * 0.125f;
            S->Qst[d+3][lr] = t.w * 0.125f;
        }
    }
    if (tid < 64) { S->m[tid] = -1e30f; S->l[tid] = 0.f; }

    int tr = (tid >> 4) * 4;   // frag row base (key in phase A; query in phase C)
    int tc = (tid & 15) * 4;   // frag col base (query in phase A; d in phase C)
    int qq = tid & 63, part = tid >> 6;

    float o[4][4];
    #pragma unroll
    for (int i = 0; i < 4; i++)
        #pragma unroll
        for (int j = 0; j < 4; j++) o[i][j] = 0.f;

    __syncthreads();

    for (int kt = 0; kt < 16; kt++) {
        int k0 = kt * 64;
        // load K^T (transposed) and V (natural)
        {
            const float* gk = k + ((size_t)((bb*S_ + k0 + lr)*H_ + hh))*DH_ + ld;
            const float* gv = v + ((size_t)((bb*S_ + k0 + lr)*H_ + hh))*DH_ + ld;
            #pragma unroll
            for (int c = 0; c < 4; c++) {
                int d = ld + c*4;
                float4 t = *(const float4*)(gk + c*4);
                S->Kst[d+0][lr] = t.x;
                S->Kst[d+1][lr] = t.y;
                S->Kst[d+2][lr] = t.z;
                S->Kst[d+3][lr] = t.w;
                float4 tv = *(const float4*)(gv + c*4);
                *(float4*)&S->Vs[lr][d] = tv;
            }
        }
        __syncthreads();

        // Phase A: S^T[key][q] = (K^T)^T Q scaled — 4x4 microtile per thread
        float acc[4][4];
        #pragma unroll
        for (int i = 0; i < 4; i++)
            #pragma unroll
            for (int j = 0; j < 4; j++) acc[i][j] = 0.f;
        #pragma unroll 8
        for (int d = 0; d < 64; d++) {
            float a[4], b4[4];
            *(float4*)a  = *(const float4*)&S->Kst[d][tr];
            *(float4*)b4 = *(const float4*)&S->Qst[d][tc];
            #pragma unroll
            for (int i = 0; i < 4; i++)
                #pragma unroll
                for (int j = 0; j < 4; j++)
                    acc[i][j] += a[i] * b4[j];
        }
        #pragma unroll
        for (int i = 0; i < 4; i++)
            *(float4*)&S->Pst[tr + i][tc] =
                make_float4(acc[i][0], acc[i][1], acc[i][2], acc[i][3]);
        __syncthreads();

        // Phase B: online softmax. 4 threads per query column (part = quarter).
        float lmax = -1e30f;
        #pragma unroll
        for (int j = 0; j < 16; j++)
            lmax = fmaxf(lmax, S->Pst[part*16 + j][qq]);
        S->red[part][qq] = lmax;
        __syncthreads();
        if (part == 0) {
            float mo = S->m[qq];
            float mn = fmaxf(fmaxf(S->red[0][qq], S->red[1][qq]),
                             fmaxf(S->red[2][qq], S->red[3][qq]));
            mn = fmaxf(mn, mo);
            S->corr[qq] = __expf(mo - mn);
            S->m[qq] = mn;
        }
        __syncthreads();
        float mn = S->m[qq];
        float ls = 0.f;
        #pragma unroll
        for (int j = 0; j < 16; j++) {
            float p = __expf(S->Pst[part*16 + j][qq] - mn);
            S->Pst[part*16 + j][qq] = p;
            ls += p;
        }
        S->red[part][qq] = ls;
        __syncthreads();
        if (part == 0)
            S->l[qq] = S->l[qq] * S->corr[qq]
                     + S->red[0][qq] + S->red[1][qq] + S->red[2][qq] + S->red[3][qq];

        // Phase C: O = O*corr + P^T-indexed @ V — same microtile pattern
        float cr[4];
        #pragma unroll
        for (int i = 0; i < 4; i++) cr[i] = S->corr[tr + i];
        #pragma unroll
        for (int i = 0; i < 4; i++)
            #pragma unroll
            for (int j = 0; j < 4; j++) o[i][j] *= cr[i];
        #pragma unroll 8
        for (int jk = 0; jk < 64; jk++) {
            float a[4], b4[4];
            *(float4*)a  = *(const float4*)&S->Pst[jk][tr];
            *(float4*)b4 = *(const float4*)&S->Vs[jk][tc];
            #pragma unroll
            for (int i = 0; i < 4; i++)
                #pragma unroll
                for (int j = 0; j < 4; j++)
                    o[i][j] += a[i] * b4[j];
        }
        __syncthreads();
    }

    float li[4];
    #pragma unroll
    for (int i = 0; i < 4; i++) li[i] = 1.0f / S->l[tr + i];
    #pragma unroll
    for (int i = 0; i < 4; i++) {
        float4 r = make_float4(o[i][0]*li[i], o[i][1]*li[i],
                               o[i][2]*li[i], o[i][3]*li[i]);
        *(float4*)&ctx[((size_t)((bb*S_ + q0 + tr + i)*H_ + hh))*DH_ + tc] = r;
    }
}

// ---------------------------------------------------------------------------
// Launcher
// ---------------------------------------------------------------------------
extern "C" void kernel_launch(void* const* d_in, const int* in_sizes, int n_in,
                              void* d_out, int out_size)
{
    const float* x   = (const float*)d_in[0];
    const float* Wq  = (const float*)d_in[1];
    const float* bq  = (const float*)d_in[2];
    const float* Wk  = (const float*)d_in[3];
    const float* bk  = (const float*)d_in[4];
    const float* Wv  = (const float*)d_in[5];
    const float* bv  = (const float*)d_in[6];
    const float* Wo  = (const float*)d_in[7];
    const float* bo  = (const float*)d_in[8];
    const float* g1  = (const float*)d_in[9];
    const float* be1 = (const float*)d_in[10];
    const float* g2  = (const float*)d_in[11];
    const float* be2 = (const float*)d_in[12];
    const float* W1  = (const float*)d_in[13];
    const float* b1  = (const float*)d_in[14];
    const float* W2  = (const float*)d_in[15];
    const float* b2  = (const float*)d_in[16];
    float* out = (float*)d_out;

    float *h, *q, *k, *v, *ctx, *x2, *ln2, *act;
    cudaGetSymbolAddress((void**)&h,   g_h);
    cudaGetSymbolAddress((void**)&q,   g_q);
    cudaGetSymbolAddress((void**)&k,   g_k);
    cudaGetSymbolAddress((void**)&v,   g_v);
    cudaGetSymbolAddress((void**)&ctx, g_ctx);
    cudaGetSymbolAddress((void**)&x2,  g_x2);
    cudaGetSymbolAddress((void**)&ln2, g_ln2);
    cudaGetSymbolAddress((void**)&act, g_act);

    cudaFuncSetAttribute(attn_kernel,
                         cudaFuncAttributeMaxDynamicSharedMemorySize,
                         (int)sizeof(AttnSmem));

    // 1. pre-LN
    ln_kernel<<<NROWS, 256>>>(x, g1, be1, h);
    // 2. QKV (batched)
    dim3 gqkv(D_/128, NROWS/128, 3);
    sgemm_qkv_kernel<<<gqkv, 256>>>(h, Wq, Wk, Wv, bq, bk, bv, q, k, v);
    // 3. fused attention
    dim3 gat(S_/64, H_, B_);
    attn_kernel<<<gat, 256, (int)sizeof(AttnSmem)>>>(q, k, v, ctx);
    // 4. Wo projection + residual -> x2
    dim3 go(D_/128, NROWS/128);
    sgemm_kernel<EPI_ADD><<<go, 256>>>(ctx, Wo, bo, x, x2, NROWS, D_, D_);
    // 5. LN2
    ln_kernel<<<NROWS, 256>>>(x2, g2, be2, ln2);
    // 6. MLP up + exact GELU
    dim3 gup(F_/128, NROWS/128);
    sgemm_kernel<EPI_GELU><<<gup, 256>>>(ln2, W1, b1, nullptr, act, NROWS, F_, D_);
    // 7. MLP down + bias + residual -> out
    dim3 gdn(D_/128, NROWS/128);
    sgemm_kernel<EPI_ADD><<<gdn, 256>>>(act, W2, b2, x2, out, NROWS, D_, F_);
}

// round 3
// speedup vs baseline: 1.7399x; 1.7399x over previous
#include <cuda_runtime.h>
#include <math.h>

#define B_  8
#define S_  1024
#define D_  768
#define H_  12
#define DH_ 64
#define F_  3072
#define NROWS (B_*S_)   /* 8192 */

#define EPI_NONE 0
#define EPI_GELU 1
#define EPI_ADD  2

// ---------------------------------------------------------------------------
// Scratch (device globals — no allocation allowed)
// ---------------------------------------------------------------------------
__device__ float g_h  [NROWS*D_];
__device__ float g_q  [NROWS*D_];
__device__ float g_k  [NROWS*D_];
__device__ float g_v  [NROWS*D_];
__device__ float g_ctx[NROWS*D_];
__device__ float g_x2 [NROWS*D_];
__device__ float g_ln2[NROWS*D_];
__device__ float g_act[NROWS*F_];

// ---------------------------------------------------------------------------
// LayerNorm: one block per row, 256 threads, D=768 = 3 elems/thread
// ---------------------------------------------------------------------------
__global__ __launch_bounds__(256) void ln_kernel(
    const float* __restrict__ x, const float* __restrict__ gam,
    const float* __restrict__ bet, float* __restrict__ out)
{
    int row = blockIdx.x;
    int tid = threadIdx.x;
    const float* xr = x + (size_t)row * D_;
    float v0 = xr[tid], v1 = xr[tid + 256], v2 = xr[tid + 512];
    float s  = v0 + v1 + v2;
    float ss = v0*v0 + v1*v1 + v2*v2;
    #pragma unroll
    for (int o = 16; o > 0; o >>= 1) {
        s  += __shfl_xor_sync(0xffffffffu, s,  o);
        ss += __shfl_xor_sync(0xffffffffu, ss, o);
    }
    __shared__ float rs[8], rss[8];
    __shared__ float s_mu, s_inv;
    int w = tid >> 5, lane = tid & 31;
    if (lane == 0) { rs[w] = s; rss[w] = ss; }
    __syncthreads();
    if (tid == 0) {
        float ts = 0.f, tss = 0.f;
        #pragma unroll
        for (int i = 0; i < 8; i++) { ts += rs[i]; tss += rss[i]; }
        float mu  = ts * (1.0f / D_);
        float var = tss * (1.0f / D_) - mu * mu;
        s_mu = mu;
        s_inv = rsqrtf(var + 1e-6f);
    }
    __syncthreads();
    float mu = s_mu, inv = s_inv;
    float* orow = out + (size_t)row * D_;
    orow[tid]       = (v0 - mu) * inv * gam[tid]       + bet[tid];
    orow[tid + 256] = (v1 - mu) * inv * gam[tid + 256] + bet[tid + 256];
    orow[tid + 512] = (v2 - mu) * inv * gam[tid + 512] + bet[tid + 512];
}

// ---------------------------------------------------------------------------
// tf32 tensor-core GEMM: 128x128 block tile, BK=16, 256 threads (8 warps),
// warp tile 32x64 via mma.sync.m16n8k8 tf32. Double-buffered SMEM, fp32 data
// converted to tf32 once at smem-store time. Stride 136 => conflict-free
// fragment loads (bank = 8*tg + g, all lanes distinct).
// C[M,N] = A[M,K] @ B[K,N] + bias; EPI: none / gelu(erf) / +residual
// ---------------------------------------------------------------------------
__device__ __forceinline__ float gelu_f(float x) {
    return 0.5f * x * (1.0f + erff(x * 0.70710678118654752f));
}

__device__ __forceinline__ unsigned f2tf32(float x) {
    unsigned r;
    asm("cvt.rna.tf32.f32 %0, %1;" : "=r"(r) : "f"(x));
    return r;
}

#define LDA 136
#define LDB 136

__device__ __forceinline__ void mma_tf32(
    float c[4], const unsigned a[4], const unsigned b[2])
{
    asm volatile(
        "mma.sync.aligned.m16n8k8.row.col.f32.tf32.tf32.f32 "
        "{%0,%1,%2,%3}, {%4,%5,%6,%7}, {%8,%9}, {%0,%1,%2,%3};"
        : "+f"(c[0]), "+f"(c[1]), "+f"(c[2]), "+f"(c[3])
        : "r"(a[0]), "r"(a[1]), "r"(a[2]), "r"(a[3]),
          "r"(b[0]), "r"(b[1]));
}

template<int EPI>
__device__ __forceinline__ void mma_gemm_body(
    const float* __restrict__ A, const float* __restrict__ Bm,
    const float* __restrict__ bias, const float* __restrict__ res,
    float* __restrict__ C, int M, int N, int K)
{
    __shared__ unsigned As[2][16][LDA];   // K-major: As[k][m]
    __shared__ unsigned Bs[2][16][LDB];   // Bs[k][n]

    int tid  = threadIdx.x;
    int bm = blockIdx.y * 128, bn = blockIdx.x * 128;
    int lane = tid & 31, warp = tid >> 5;
    int warp_m = warp >> 1;            // 0..3  -> 32-row slab
    int warp_n = warp & 1;             // 0..1  -> 64-col slab
    int g  = lane >> 2;                // 0..7
    int tg = lane & 3;                 // 0..3

    // loader indices
    int ar = tid >> 2;                 // A row 0..63 (+64 second pass)
    int akq = tid & 3;                 // A k-quad
    const float* ApBase = A + (size_t)(bm + ar) * K + akq * 4;

    float acc[2][8][4];
    #pragma unroll
    for (int mt = 0; mt < 2; mt++)
        #pragma unroll
        for (int nt = 0; nt < 8; nt++)
            #pragma unroll
            for (int i = 0; i < 4; i++) acc[mt][nt][i] = 0.f;

    int nk = K >> 4;

    // ---- load tile 0 ----
    {
        #pragma unroll
        for (int p = 0; p < 2; p++) {
            float4 av = *(const float4*)(ApBase + (size_t)p * 64 * K);
            int r = ar + p * 64;
            As[0][akq*4+0][r] = f2tf32(av.x);
            As[0][akq*4+1][r] = f2tf32(av.y);
            As[0][akq*4+2][r] = f2tf32(av.z);
            As[0][akq*4+3][r] = f2tf32(av.w);
        }
        #pragma unroll
        for (int p = 0; p < 2; p++) {
            int idx = tid + p * 256;
            int kr = idx >> 5, nq = idx & 31;
            float4 bv = *(const float4*)(Bm + (size_t)kr * N + bn + nq * 4);
            uint4 u;
            u.x = f2tf32(bv.x); u.y = f2tf32(bv.y);
            u.z = f2tf32(bv.z); u.w = f2tf32(bv.w);
            *(uint4*)&Bs[0][kr][nq*4] = u;
        }
    }
    __syncthreads();

    float4 pa[2], pb[2];
    for (int kt = 0; kt < nk; kt++) {
        int cur = kt & 1;
        if (kt + 1 < nk) {
            int koff = (kt + 1) * 16;
            #pragma unroll
            for (int p = 0; p < 2; p++)
                pa[p] = *(const float4*)(ApBase + (size_t)p * 64 * K + koff);
            #pragma unroll
            for (int p = 0; p < 2; p++) {
                int idx = tid + p * 256;
                int kr = idx >> 5, nq = idx & 31;
                pb[p] = *(const float4*)(Bm + (size_t)(koff + kr) * N + bn + nq * 4);
            }
        }

        #pragma unroll
        for (int ks = 0; ks < 2; ks++) {
            int k0 = ks * 8;
            unsigned af[2][4], bf[8][2];
            #pragma unroll
            for (int mt = 0; mt < 2; mt++) {
                int mb = warp_m * 32 + mt * 16 + g;
                af[mt][0] = As[cur][k0 + tg    ][mb];
                af[mt][1] = As[cur][k0 + tg    ][mb + 8];
                af[mt][2] = As[cur][k0 + tg + 4][mb];
                af[mt][3] = As[cur][k0 + tg + 4][mb + 8];
            }
            #pragma unroll
            for (int nt = 0; nt < 8; nt++) {
                int nb = warp_n * 64 + nt * 8 + g;
                bf[nt][0] = Bs[cur][k0 + tg    ][nb];
                bf[nt][1] = Bs[cur][k0 + tg + 4][nb];
            }
            #pragma unroll
            for (int mt = 0; mt < 2; mt++)
                #pragma unroll
                for (int nt = 0; nt < 8; nt++)
                    mma_tf32(acc[mt][nt], af[mt], bf[nt]);
        }

        if (kt + 1 < nk) {
            int nxt = cur ^ 1;
            #pragma unroll
            for (int p = 0; p < 2; p++) {
                int r = ar + p * 64;
                As[nxt][akq*4+0][r] = f2tf32(pa[p].x);
                As[nxt][akq*4+1][r] = f2tf32(pa[p].y);
                As[nxt][akq*4+2][r] = f2tf32(pa[p].z);
                As[nxt][akq*4+3][r] = f2tf32(pa[p].w);
            }
            #pragma unroll
            for (int p = 0; p < 2; p++) {
                int idx = tid + p * 256;
                int kr = idx >> 5, nq = idx & 31;
                uint4 u;
                u.x = f2tf32(pb[p].x); u.y = f2tf32(pb[p].y);
                u.z = f2tf32(pb[p].z); u.w = f2tf32(pb[p].w);
                *(uint4*)&Bs[nxt][kr][nq*4] = u;
            }
            __syncthreads();
        }
    }

    // ---- epilogue ----
    #pragma unroll
    for (int mt = 0; mt < 2; mt++) {
        #pragma unroll
        for (int nt = 0; nt < 8; nt++) {
            int row0 = bm + warp_m * 32 + mt * 16 + g;
            int row1 = row0 + 8;
            int col  = bn + warp_n * 64 + nt * 8 + tg * 2;
            float2 bb = *(const float2*)&bias[col];
            float v0 = acc[mt][nt][0] + bb.x;
            float v1 = acc[mt][nt][1] + bb.y;
            float v2 = acc[mt][nt][2] + bb.x;
            float v3 = acc[mt][nt][3] + bb.y;
            if (EPI == EPI_GELU) {
                v0 = gelu_f(v0); v1 = gelu_f(v1);
                v2 = gelu_f(v2); v3 = gelu_f(v3);
            }
            if (EPI == EPI_ADD) {
                float2 r0 = *(const float2*)&res[(size_t)row0 * N + col];
                float2 r1 = *(const float2*)&res[(size_t)row1 * N + col];
                v0 += r0.x; v1 += r0.y; v2 += r1.x; v3 += r1.y;
            }
            *(float2*)&C[(size_t)row0 * N + col] = make_float2(v0, v1);
            *(float2*)&C[(size_t)row1 * N + col] = make_float2(v2, v3);
        }
    }
}

template<int EPI>
__global__ __launch_bounds__(256, 2) void mma_gemm_kernel(
    const float* __restrict__ A, const float* __restrict__ Bm,
    const float* __restrict__ bias, const float* __restrict__ res,
    float* __restrict__ C, int M, int N, int K)
{
    mma_gemm_body<EPI>(A, Bm, bias, res, C, M, N, K);
}

// QKV batched: blockIdx.z selects W/bias/output
__global__ __launch_bounds__(256, 2) void mma_qkv_kernel(
    const float* __restrict__ A,
    const float* __restrict__ Wq, const float* __restrict__ Wk, const float* __restrict__ Wv,
    const float* __restrict__ bq, const float* __restrict__ bk, const float* __restrict__ bv,
    float* __restrict__ Cq, float* __restrict__ Ck, float* __restrict__ Cv)
{
    const float* Bm  = (blockIdx.z == 0) ? Wq : (blockIdx.z == 1) ? Wk : Wv;
    const float* bia = (blockIdx.z == 0) ? bq : (blockIdx.z == 1) ? bk : bv;
    float*       C   = (blockIdx.z == 0) ? Cq : (blockIdx.z == 1) ? Ck : Cv;
    mma_gemm_body<EPI_NONE>(A, Bm, bia, nullptr, C, NROWS, D_, D_);
}

// ---------------------------------------------------------------------------
// Fused attention (flash-style): block = (b, h, 64 query rows), K-tiles of 64.
// ---------------------------------------------------------------------------
struct AttnSmem {
    float Qst[64][68];   // Q^T (d-major), pre-scaled by 1/sqrt(DH)
    float Kst[64][68];   // K^T (d-major)
    float Vs [64][68];   // V natural [key][d]
    float Pst[64][68];   // scores / probs, [key][q] (S^T)
    float m[64];
    float l[64];
    float corr[64];
    float red[4][64];
};

__global__ __launch_bounds__(256) void attn_kernel(
    const float* __restrict__ q, const float* __restrict__ k,
    const float* __restrict__ v, float* __restrict__ ctx)
{
    extern __shared__ char smem_raw[];
    AttnSmem* S = (AttnSmem*)smem_raw;
    int bb = blockIdx.z, hh = blockIdx.y;
    int q0 = blockIdx.x * 64;
    int tid = threadIdx.x;
    int lr = tid >> 2;              // load row (0..63)
    int ld = (tid & 3) * 16;        // load d base

    {
        const float* gq = q + ((size_t)((bb*S_ + q0 + lr)*H_ + hh))*DH_ + ld;
        #pragma unroll
        for (int c = 0; c < 4; c++) {
            float4 t = *(const float4*)(gq + c*4);
            int d = ld + c*4;
            S->Qst[d+0][lr] = t.x * 0.125f;
            S->Qst[d+1][lr] = t.y * 0.125f;
            S->Qst[d+2][lr] = t.z * 0.125f;
            S->Qst[d+3][lr] = t.w * 0.125f;
        }
    }
    if (tid < 64) { S->m[tid] = -1e30f; S->l[tid] = 0.f; }

    int tr = (tid >> 4) * 4;
    int tc = (tid & 15) * 4;
    int qq = tid & 63, part = tid >> 6;

    float o[4][4];
    #pragma unroll
    for (int i = 0; i < 4; i++)
        #pragma unroll
        for (int j = 0; j < 4; j++) o[i][j] = 0.f;

    __syncthreads();

    for (int kt = 0; kt < 16; kt++) {
        int k0 = kt * 64;
        {
            const float* gk = k + ((size_t)((bb*S_ + k0 + lr)*H_ + hh))*DH_ + ld;
            const float* gv = v + ((size_t)((bb*S_ + k0 + lr)*H_ + hh))*DH_ + ld;
            #pragma unroll
            for (int c = 0; c < 4; c++) {
                int d = ld + c*4;
                float4 t = *(const float4*)(gk + c*4);
                S->Kst[d+0][lr] = t.x;
                S->Kst[d+1][lr] = t.y;
                S->Kst[d+2][lr] = t.z;
                S->Kst[d+3][lr] = t.w;
                float4 tv = *(const float4*)(gv + c*4);
                *(float4*)&S->Vs[lr][d] = tv;
            }
        }
        __syncthreads();

        float acc[4][4];
        #pragma unroll
        for (int i = 0; i < 4; i++)
            #pragma unroll
            for (int j = 0; j < 4; j++) acc[i][j] = 0.f;
        #pragma unroll 8
        for (int d = 0; d < 64; d++) {
            float a[4], b4[4];
            *(float4*)a  = *(const float4*)&S->Kst[d][tr];
            *(float4*)b4 = *(const float4*)&S->Qst[d][tc];
            #pragma unroll
            for (int i = 0; i < 4; i++)
                #pragma unroll
                for (int j = 0; j < 4; j++)
                    acc[i][j] += a[i] * b4[j];
        }
        #pragma unroll
        for (int i = 0; i < 4; i++)
            *(float4*)&S->Pst[tr + i][tc] =
                make_float4(acc[i][0], acc[i][1], acc[i][2], acc[i][3]);
        __syncthreads();

        float lmax = -1e30f;
        #pragma unroll
        for (int j = 0; j < 16; j++)
            lmax = fmaxf(lmax, S->Pst[part*16 + j][qq]);
        S->red[part][qq] = lmax;
        __syncthreads();
        if (part == 0) {
            float mo = S->m[qq];
            float mn = fmaxf(fmaxf(S->red[0][qq], S->red[1][qq]),
                             fmaxf(S->red[2][qq], S->red[3][qq]));
            mn = fmaxf(mn, mo);
            S->corr[qq] = __expf(mo - mn);
            S->m[qq] = mn;
        }
        __syncthreads();
        float mn = S->m[qq];
        float ls = 0.f;
        #pragma unroll
        for (int j = 0; j < 16; j++) {
            float p = __expf(S->Pst[part*16 + j][qq] - mn);
            S->Pst[part*16 + j][qq] = p;
            ls += p;
        }
        S->red[part][qq] = ls;
        __syncthreads();
        if (part == 0)
            S->l[qq] = S->l[qq] * S->corr[qq]
                     + S->red[0][qq] + S->red[1][qq] + S->red[2][qq] + S->red[3][qq];

        float cr[4];
        #pragma unroll
        for (int i = 0; i < 4; i++) cr[i] = S->corr[tr + i];
        #pragma unroll
        for (int i = 0; i < 4; i++)
            #pragma unroll
            for (int j = 0; j < 4; j++) o[i][j] *= cr[i];
        #pragma unroll 8
        for (int jk = 0; jk < 64; jk++) {
            float a[4], b4[4];
            *(float4*)a  = *(const float4*)&S->Pst[jk][tr];
            *(float4*)b4 = *(const float4*)&S->Vs[jk][tc];
            #pragma unroll
            for (int i = 0; i < 4; i++)
                #pragma unroll
                for (int j = 0; j < 4; j++)
                    o[i][j] += a[i] * b4[j];
        }
        __syncthreads();
    }

    float li[4];
    #pragma unroll
    for (int i = 0; i < 4; i++) li[i] = 1.0f / S->l[tr + i];
    #pragma unroll
    for (int i = 0; i < 4; i++) {
        float4 r = make_float4(o[i][0]*li[i], o[i][1]*li[i],
                               o[i][2]*li[i], o[i][3]*li[i]);
        *(float4*)&ctx[((size_t)((bb*S_ + q0 + tr + i)*H_ + hh))*DH_ + tc] = r;
    }
}

// ---------------------------------------------------------------------------
// Launcher
// ---------------------------------------------------------------------------
extern "C" void kernel_launch(void* const* d_in, const int* in_sizes, int n_in,
                              void* d_out, int out_size)
{
    const float* x   = (const float*)d_in[0];
    const float* Wq  = (const float*)d_in[1];
    const float* bq  = (const float*)d_in[2];
    const float* Wk  = (const float*)d_in[3];
    const float* bk  = (const float*)d_in[4];
    const float* Wv  = (const float*)d_in[5];
    const float* bv  = (const float*)d_in[6];
    const float* Wo  = (const float*)d_in[7];
    const float* bo  = (const float*)d_in[8];
    const float* g1  = (const float*)d_in[9];
    const float* be1 = (const float*)d_in[10];
    const float* g2  = (const float*)d_in[11];
    const float* be2 = (const float*)d_in[12];
    const float* W1  = (const float*)d_in[13];
    const float* b1  = (const float*)d_in[14];
    const float* W2  = (const float*)d_in[15];
    const float* b2  = (const float*)d_in[16];
    float* out = (float*)d_out;

    float *h, *q, *k, *v, *ctx, *x2, *ln2, *act;
    cudaGetSymbolAddress((void**)&h,   g_h);
    cudaGetSymbolAddress((void**)&q,   g_q);
    cudaGetSymbolAddress((void**)&k,   g_k);
    cudaGetSymbolAddress((void**)&v,   g_v);
    cudaGetSymbolAddress((void**)&ctx, g_ctx);
    cudaGetSymbolAddress((void**)&x2,  g_x2);
    cudaGetSymbolAddress((void**)&ln2, g_ln2);
    cudaGetSymbolAddress((void**)&act, g_act);

    cudaFuncSetAttribute(attn_kernel,
                         cudaFuncAttributeMaxDynamicSharedMemorySize,
                         (int)sizeof(AttnSmem));

    // 1. pre-LN
    ln_kernel<<<NROWS, 256>>>(x, g1, be1, h);
    // 2. QKV (batched, tf32 tensor cores)
    dim3 gqkv(D_/128, NROWS/128, 3);
    mma_qkv_kernel<<<gqkv, 256>>>(h, Wq, Wk, Wv, bq, bk, bv, q, k, v);
    // 3. fused attention
    dim3 gat(S_/64, H_, B_);
    attn_kernel<<<gat, 256, (int)sizeof(AttnSmem)>>>(q, k, v, ctx);
    // 4. Wo projection + residual -> x2
    dim3 go(D_/128, NROWS/128);
    mma_gemm_kernel<EPI_ADD><<<go, 256>>>(ctx, Wo, bo, x, x2, NROWS, D_, D_);
    // 5. LN2
    ln_kernel<<<NROWS, 256>>>(x2, g2, be2, ln2);
    // 6. MLP up + exact GELU
    dim3 gup(F_/128, NROWS/128);
    mma_gemm_kernel<EPI_GELU><<<gup, 256>>>(ln2, W1, b1, nullptr, act, NROWS, F_, D_);
    // 7. MLP down + bias + residual -> out
    dim3 gdn(D_/128, NROWS/128);
    mma_gemm_kernel<EPI_ADD><<<gdn, 256>>>(act, W2, b2, x2, out, NROWS, D_, F_);
}

// round 4
// speedup vs baseline: 2.1738x; 1.2494x over previous
#include <cuda_runtime.h>
#include <math.h>

#define B_  8
#define S_  1024
#define D_  768
#define H_  12
#define DH_ 64
#define F_  3072
#define NROWS (B_*S_)   /* 8192 */

#define EPI_NONE 0
#define EPI_GELU 1
#define EPI_ADD  2

// ---------------------------------------------------------------------------
// Scratch (device globals — no allocation allowed)
// ---------------------------------------------------------------------------
__device__ float g_h  [NROWS*D_];
__device__ float g_q  [NROWS*D_];
__device__ float g_k  [NROWS*D_];
__device__ float g_v  [NROWS*D_];
__device__ float g_ctx[NROWS*D_];
__device__ float g_x2 [NROWS*D_];
__device__ float g_ln2[NROWS*D_];
__device__ float g_act[NROWS*F_];

// ---------------------------------------------------------------------------
// helpers
// ---------------------------------------------------------------------------
__device__ __forceinline__ float gelu_f(float x) {
    return 0.5f * x * (1.0f + erff(x * 0.70710678118654752f));
}

__device__ __forceinline__ unsigned f2tf32(float x) {
    unsigned r;
    asm("cvt.rna.tf32.f32 %0, %1;" : "=r"(r) : "f"(x));
    return r;
}

__device__ __forceinline__ void mma_tf32(
    float c[4], const unsigned a[4], const unsigned b[2])
{
    asm volatile(
        "mma.sync.aligned.m16n8k8.row.col.f32.tf32.tf32.f32 "
        "{%0,%1,%2,%3}, {%4,%5,%6,%7}, {%8,%9}, {%0,%1,%2,%3};"
        : "+f"(c[0]), "+f"(c[1]), "+f"(c[2]), "+f"(c[3])
        : "r"(a[0]), "r"(a[1]), "r"(a[2]), "r"(a[3]),
          "r"(b[0]), "r"(b[1]));
}

// ---------------------------------------------------------------------------
// LayerNorm: one block per row, 256 threads, D=768 = 3 elems/thread
// ---------------------------------------------------------------------------
__global__ __launch_bounds__(256) void ln_kernel(
    const float* __restrict__ x, const float* __restrict__ gam,
    const float* __restrict__ bet, float* __restrict__ out)
{
    int row = blockIdx.x;
    int tid = threadIdx.x;
    const float* xr = x + (size_t)row * D_;
    float v0 = xr[tid], v1 = xr[tid + 256], v2 = xr[tid + 512];
    float s  = v0 + v1 + v2;
    float ss = v0*v0 + v1*v1 + v2*v2;
    #pragma unroll
    for (int o = 16; o > 0; o >>= 1) {
        s  += __shfl_xor_sync(0xffffffffu, s,  o);
        ss += __shfl_xor_sync(0xffffffffu, ss, o);
    }
    __shared__ float rs[8], rss[8];
    __shared__ float s_mu, s_inv;
    int w = tid >> 5, lane = tid & 31;
    if (lane == 0) { rs[w] = s; rss[w] = ss; }
    __syncthreads();
    if (tid == 0) {
        float ts = 0.f, tss = 0.f;
        #pragma unroll
        for (int i = 0; i < 8; i++) { ts += rs[i]; tss += rss[i]; }
        float mu  = ts * (1.0f / D_);
        float var = tss * (1.0f / D_) - mu * mu;
        s_mu = mu;
        s_inv = rsqrtf(var + 1e-6f);
    }
    __syncthreads();
    float mu = s_mu, inv = s_inv;
    float* orow = out + (size_t)row * D_;
    orow[tid]       = (v0 - mu) * inv * gam[tid]       + bet[tid];
    orow[tid + 256] = (v1 - mu) * inv * gam[tid + 256] + bet[tid + 256];
    orow[tid + 512] = (v2 - mu) * inv * gam[tid + 512] + bet[tid + 512];
}

// ---------------------------------------------------------------------------
// tf32 tensor-core GEMM: 128x128 block tile, BK=16, 256 threads (8 warps),
// warp tile 32x64 via mma.sync.m16n8k8 tf32.  (validated R2)
// ---------------------------------------------------------------------------
#define LDA 136
#define LDB 136

template<int EPI>
__device__ __forceinline__ void mma_gemm_body(
    const float* __restrict__ A, const float* __restrict__ Bm,
    const float* __restrict__ bias, const float* __restrict__ res,
    float* __restrict__ C, int M, int N, int K)
{
    __shared__ unsigned As[2][16][LDA];   // K-major: As[k][m]
    __shared__ unsigned Bs[2][16][LDB];   // Bs[k][n]

    int tid  = threadIdx.x;
    int bm = blockIdx.y * 128, bn = blockIdx.x * 128;
    int lane = tid & 31, warp = tid >> 5;
    int warp_m = warp >> 1;
    int warp_n = warp & 1;
    int g  = lane >> 2;
    int tg = lane & 3;

    int ar = tid >> 2;
    int akq = tid & 3;
    const float* ApBase = A + (size_t)(bm + ar) * K + akq * 4;

    float acc[2][8][4];
    #pragma unroll
    for (int mt = 0; mt < 2; mt++)
        #pragma unroll
        for (int nt = 0; nt < 8; nt++)
            #pragma unroll
            for (int i = 0; i < 4; i++) acc[mt][nt][i] = 0.f;

    int nk = K >> 4;

    {
        #pragma unroll
        for (int p = 0; p < 2; p++) {
            float4 av = *(const float4*)(ApBase + (size_t)p * 64 * K);
            int r = ar + p * 64;
            As[0][akq*4+0][r] = f2tf32(av.x);
            As[0][akq*4+1][r] = f2tf32(av.y);
            As[0][akq*4+2][r] = f2tf32(av.z);
            As[0][akq*4+3][r] = f2tf32(av.w);
        }
        #pragma unroll
        for (int p = 0; p < 2; p++) {
            int idx = tid + p * 256;
            int kr = idx >> 5, nq = idx & 31;
            float4 bv = *(const float4*)(Bm + (size_t)kr * N + bn + nq * 4);
            uint4 u;
            u.x = f2tf32(bv.x); u.y = f2tf32(bv.y);
            u.z = f2tf32(bv.z); u.w = f2tf32(bv.w);
            *(uint4*)&Bs[0][kr][nq*4] = u;
        }
    }
    __syncthreads();

    float4 pa[2], pb[2];
    for (int kt = 0; kt < nk; kt++) {
        int cur = kt & 1;
        if (kt + 1 < nk) {
            int koff = (kt + 1) * 16;
            #pragma unroll
            for (int p = 0; p < 2; p++)
                pa[p] = *(const float4*)(ApBase + (size_t)p * 64 * K + koff);
            #pragma unroll
            for (int p = 0; p < 2; p++) {
                int idx = tid + p * 256;
                int kr = idx >> 5, nq = idx & 31;
                pb[p] = *(const float4*)(Bm + (size_t)(koff + kr) * N + bn + nq * 4);
            }
        }

        #pragma unroll
        for (int ks = 0; ks < 2; ks++) {
            int k0 = ks * 8;
            unsigned af[2][4], bf[8][2];
            #pragma unroll
            for (int mt = 0; mt < 2; mt++) {
                int mb = warp_m * 32 + mt * 16 + g;
                af[mt][0] = As[cur][k0 + tg    ][mb];
                af[mt][1] = As[cur][k0 + tg    ][mb + 8];
                af[mt][2] = As[cur][k0 + tg + 4][mb];
                af[mt][3] = As[cur][k0 + tg + 4][mb + 8];
            }
            #pragma unroll
            for (int nt = 0; nt < 8; nt++) {
                int nb = warp_n * 64 + nt * 8 + g;
                bf[nt][0] = Bs[cur][k0 + tg    ][nb];
                bf[nt][1] = Bs[cur][k0 + tg + 4][nb];
            }
            #pragma unroll
            for (int mt = 0; mt < 2; mt++)
                #pragma unroll
                for (int nt = 0; nt < 8; nt++)
                    mma_tf32(acc[mt][nt], af[mt], bf[nt]);
        }

        if (kt + 1 < nk) {
            int nxt = cur ^ 1;
            #pragma unroll
            for (int p = 0; p < 2; p++) {
                int r = ar + p * 64;
                As[nxt][akq*4+0][r] = f2tf32(pa[p].x);
                As[nxt][akq*4+1][r] = f2tf32(pa[p].y);
                As[nxt][akq*4+2][r] = f2tf32(pa[p].z);
                As[nxt][akq*4+3][r] = f2tf32(pa[p].w);
            }
            #pragma unroll
            for (int p = 0; p < 2; p++) {
                int idx = tid + p * 256;
                int kr = idx >> 5, nq = idx & 31;
                uint4 u;
                u.x = f2tf32(pb[p].x); u.y = f2tf32(pb[p].y);
                u.z = f2tf32(pb[p].z); u.w = f2tf32(pb[p].w);
                *(uint4*)&Bs[nxt][kr][nq*4] = u;
            }
            __syncthreads();
        }
    }

    #pragma unroll
    for (int mt = 0; mt < 2; mt++) {
        #pragma unroll
        for (int nt = 0; nt < 8; nt++) {
            int row0 = bm + warp_m * 32 + mt * 16 + g;
            int row1 = row0 + 8;
            int col  = bn + warp_n * 64 + nt * 8 + tg * 2;
            float2 bb = *(const float2*)&bias[col];
            float v0 = acc[mt][nt][0] + bb.x;
            float v1 = acc[mt][nt][1] + bb.y;
            float v2 = acc[mt][nt][2] + bb.x;
            float v3 = acc[mt][nt][3] + bb.y;
            if (EPI == EPI_GELU) {
                v0 = gelu_f(v0); v1 = gelu_f(v1);
                v2 = gelu_f(v2); v3 = gelu_f(v3);
            }
            if (EPI == EPI_ADD) {
                float2 r0 = *(const float2*)&res[(size_t)row0 * N + col];
                float2 r1 = *(const float2*)&res[(size_t)row1 * N + col];
                v0 += r0.x; v1 += r0.y; v2 += r1.x; v3 += r1.y;
            }
            *(float2*)&C[(size_t)row0 * N + col] = make_float2(v0, v1);
            *(float2*)&C[(size_t)row1 * N + col] = make_float2(v2, v3);
        }
    }
}

template<int EPI>
__global__ __launch_bounds__(256, 2) void mma_gemm_kernel(
    const float* __restrict__ A, const float* __restrict__ Bm,
    const float* __restrict__ bias, const float* __restrict__ res,
    float* __restrict__ C, int M, int N, int K)
{
    mma_gemm_body<EPI>(A, Bm, bias, res, C, M, N, K);
}

__global__ __launch_bounds__(256, 2) void mma_qkv_kernel(
    const float* __restrict__ A,
    const float* __restrict__ Wq, const float* __restrict__ Wk, const float* __restrict__ Wv,
    const float* __restrict__ bq, const float* __restrict__ bk, const float* __restrict__ bv,
    float* __restrict__ Cq, float* __restrict__ Ck, float* __restrict__ Cv)
{
    const float* Bm  = (blockIdx.z == 0) ? Wq : (blockIdx.z == 1) ? Wk : Wv;
    const float* bia = (blockIdx.z == 0) ? bq : (blockIdx.z == 1) ? bk : bv;
    float*       C   = (blockIdx.z == 0) ? Cq : (blockIdx.z == 1) ? Ck : Cv;
    mma_gemm_body<EPI_NONE>(A, Bm, bia, nullptr, C, NROWS, D_, D_);
}

// ---------------------------------------------------------------------------
// Fused attention, tensor-core edition.
// Block = (b, h, 64 query rows). 8 warps, each owns a 16x32 output slab.
// smem: Q[q][d], K[kk][d] (tf32 bits), Vt[d][kk] (tf32 bits),
//       P[q][kk] (fp32 scores -> tf32 probs in place).
// QK^T: A=Q (row-major), B=K ([n][k] col-major view).
// P*V : A=P (row-major), B=Vt ([n][k] col-major view).
// Fragment maps identical to the validated GEMM kernel.
// ---------------------------------------------------------------------------
struct AttnSmem {
    float Q [64][68];
    float K [64][68];
    float Vt[64][68];
    float P [64][68];
    float m[64];
    float l[64];
    float corr[64];
    float red[4][64];
};

__global__ __launch_bounds__(256) void attn_kernel(
    const float* __restrict__ q, const float* __restrict__ k,
    const float* __restrict__ v, float* __restrict__ ctx)
{
    extern __shared__ char smem_raw[];
    AttnSmem* S = (AttnSmem*)smem_raw;
    int bb = blockIdx.z, hh = blockIdx.y;
    int q0 = blockIdx.x * 64;
    int tid = threadIdx.x;
    int lane = tid & 31, wid = tid >> 5;
    int g = lane >> 2, tg = lane & 3;
    int warp_m = wid >> 1, warp_n = wid & 1;
    int m0 = warp_m * 16;

    int lr = tid >> 2;              // load row (0..63)
    int ld = (tid & 3) * 16;        // load d base

    // load Q (scaled by 1/sqrt(DH), tf32 bits)
    {
        const float* gq = q + ((size_t)((bb*S_ + q0 + lr)*H_ + hh))*DH_ + ld;
        #pragma unroll
        for (int c = 0; c < 4; c++) {
            float4 t = *(const float4*)(gq + c*4);
            uint4 u;
            u.x = f2tf32(t.x * 0.125f);
            u.y = f2tf32(t.y * 0.125f);
            u.z = f2tf32(t.z * 0.125f);
            u.w = f2tf32(t.w * 0.125f);
            *(uint4*)&S->Q[lr][ld + c*4] = u;
        }
    }
    if (tid < 64) { S->m[tid] = -1e30f; S->l[tid] = 0.f; }

    float o[4][4];
    #pragma unroll
    for (int nt = 0; nt < 4; nt++)
        #pragma unroll
        for (int i = 0; i < 4; i++) o[nt][i] = 0.f;

    int srow = tid >> 2, part = tid & 3;   // softmax mapping: 4 threads/row

    __syncthreads();

    for (int kt = 0; kt < 16; kt++) {
        int k0g = kt * 64;
        // ---- load K (natural, tf32) and Vt (transposed, tf32) ----
        {
            const float* gk = k + ((size_t)((bb*S_ + k0g + lr)*H_ + hh))*DH_ + ld;
            const float* gv = v + ((size_t)((bb*S_ + k0g + lr)*H_ + hh))*DH_ + ld;
            #pragma unroll
            for (int c = 0; c < 4; c++) {
                float4 t = *(const float4*)(gk + c*4);
                uint4 u;
                u.x = f2tf32(t.x); u.y = f2tf32(t.y);
                u.z = f2tf32(t.z); u.w = f2tf32(t.w);
                *(uint4*)&S->K[lr][ld + c*4] = u;
                float4 tv = *(const float4*)(gv + c*4);
                int d = ld + c*4;
                S->Vt[d+0][lr] = __uint_as_float(f2tf32(tv.x));
                S->Vt[d+1][lr] = __uint_as_float(f2tf32(tv.y));
                S->Vt[d+2][lr] = __uint_as_float(f2tf32(tv.z));
                S->Vt[d+3][lr] = __uint_as_float(f2tf32(tv.w));
            }
        }
        __syncthreads();

        // ---- QK^T -> P (fp32 scores) ----
        {
            float s[4][4];
            #pragma unroll
            for (int nt = 0; nt < 4; nt++)
                #pragma unroll
                for (int i = 0; i < 4; i++) s[nt][i] = 0.f;
            #pragma unroll
            for (int ks = 0; ks < 8; ks++) {
                int k0 = ks * 8;
                unsigned a[4];
                a[0] = __float_as_uint(S->Q[m0 + g    ][k0 + tg    ]);
                a[1] = __float_as_uint(S->Q[m0 + g + 8][k0 + tg    ]);
                a[2] = __float_as_uint(S->Q[m0 + g    ][k0 + tg + 4]);
                a[3] = __float_as_uint(S->Q[m0 + g + 8][k0 + tg + 4]);
                #pragma unroll
                for (int nt = 0; nt < 4; nt++) {
                    int n0 = warp_n * 32 + nt * 8;
                    unsigned b[2];
                    b[0] = __float_as_uint(S->K[n0 + g][k0 + tg    ]);
                    b[1] = __float_as_uint(S->K[n0 + g][k0 + tg + 4]);
                    mma_tf32(s[nt], a, b);
                }
            }
            #pragma unroll
            for (int nt = 0; nt < 4; nt++) {
                int n0 = warp_n * 32 + nt * 8;
                *(float2*)&S->P[m0 + g    ][n0 + tg*2] = make_float2(s[nt][0], s[nt][1]);
                *(float2*)&S->P[m0 + g + 8][n0 + tg*2] = make_float2(s[nt][2], s[nt][3]);
            }
        }
        __syncthreads();

        // ---- online softmax on P rows ----
        float lmax = -1e30f;
        #pragma unroll
        for (int j = 0; j < 16; j++)
            lmax = fmaxf(lmax, S->P[srow][part*16 + j]);
        S->red[part][srow] = lmax;
        __syncthreads();
        if (tid < 64) {
            float mo = S->m[tid];
            float mn = fmaxf(fmaxf(S->red[0][tid], S->red[1][tid]),
                             fmaxf(S->red[2][tid], S->red[3][tid]));
            mn = fmaxf(mn, mo);
            S->corr[tid] = __expf(mo - mn);
            S->m[tid] = mn;
        }
        __syncthreads();
        {
            float mn = S->m[srow];
            float ls = 0.f;
            #pragma unroll
            for (int j = 0; j < 16; j++) {
                float p = __expf(S->P[srow][part*16 + j] - mn);
                S->P[srow][part*16 + j] = __uint_as_float(f2tf32(p));
                ls += p;
            }
            S->red[part][srow] = ls;
        }
        __syncthreads();
        if (tid < 64)
            S->l[tid] = S->l[tid] * S->corr[tid]
                      + S->red[0][tid] + S->red[1][tid]
                      + S->red[2][tid] + S->red[3][tid];

        // ---- P*V accumulate with correction ----
        {
            float cr0 = S->corr[m0 + g], cr1 = S->corr[m0 + g + 8];
            #pragma unroll
            for (int nt = 0; nt < 4; nt++) {
                o[nt][0] *= cr0; o[nt][1] *= cr0;
                o[nt][2] *= cr1; o[nt][3] *= cr1;
            }
            #pragma unroll
            for (int ks = 0; ks < 8; ks++) {
                int k0 = ks * 8;
                unsigned a[4];
                a[0] = __float_as_uint(S->P[m0 + g    ][k0 + tg    ]);
                a[1] = __float_as_uint(S->P[m0 + g + 8][k0 + tg    ]);
                a[2] = __float_as_uint(S->P[m0 + g    ][k0 + tg + 4]);
                a[3] = __float_as_uint(S->P[m0 + g + 8][k0 + tg + 4]);
                #pragma unroll
                for (int nt = 0; nt < 4; nt++) {
                    int n0 = warp_n * 32 + nt * 8;
                    unsigned b[2];
                    b[0] = __float_as_uint(S->Vt[n0 + g][k0 + tg    ]);
                    b[1] = __float_as_uint(S->Vt[n0 + g][k0 + tg + 4]);
                    mma_tf32(o[nt], a, b);
                }
            }
        }
        __syncthreads();
    }

    // ---- finalize: divide by l, write ctx ----
    float inv0 = 1.0f / S->l[m0 + g];
    float inv1 = 1.0f / S->l[m0 + g + 8];
    int row0 = bb*S_ + q0 + m0 + g;
    int row1 = row0 + 8;
    #pragma unroll
    for (int nt = 0; nt < 4; nt++) {
        int d = warp_n * 32 + nt * 8 + tg * 2;
        *(float2*)&ctx[((size_t)(row0*H_ + hh))*DH_ + d] =
            make_float2(o[nt][0] * inv0, o[nt][1] * inv0);
        *(float2*)&ctx[((size_t)(row1*H_ + hh))*DH_ + d] =
            make_float2(o[nt][2] * inv1, o[nt][3] * inv1);
    }
}

// ---------------------------------------------------------------------------
// Launcher
// ---------------------------------------------------------------------------
extern "C" void kernel_launch(void* const* d_in, const int* in_sizes, int n_in,
                              void* d_out, int out_size)
{
    const float* x   = (const float*)d_in[0];
    const float* Wq  = (const float*)d_in[1];
    const float* bq  = (const float*)d_in[2];
    const float* Wk  = (const float*)d_in[3];
    const float* bk  = (const float*)d_in[4];
    const float* Wv  = (const float*)d_in[5];
    const float* bv  = (const float*)d_in[6];
    const float* Wo  = (const float*)d_in[7];
    const float* bo  = (const float*)d_in[8];
    const float* g1  = (const float*)d_in[9];
    const float* be1 = (const float*)d_in[10];
    const float* g2  = (const float*)d_in[11];
    const float* be2 = (const float*)d_in[12];
    const float* W1  = (const float*)d_in[13];
    const float* b1  = (const float*)d_in[14];
    const float* W2  = (const float*)d_in[15];
    const float* b2  = (const float*)d_in[16];
    float* out = (float*)d_out;

    float *h, *q, *k, *v, *ctx, *x2, *ln2, *act;
    cudaGetSymbolAddress((void**)&h,   g_h);
    cudaGetSymbolAddress((void**)&q,   g_q);
    cudaGetSymbolAddress((void**)&k,   g_k);
    cudaGetSymbolAddress((void**)&v,   g_v);
    cudaGetSymbolAddress((void**)&ctx, g_ctx);
    cudaGetSymbolAddress((void**)&x2,  g_x2);
    cudaGetSymbolAddress((void**)&ln2, g_ln2);
    cudaGetSymbolAddress((void**)&act, g_act);

    cudaFuncSetAttribute(attn_kernel,
                         cudaFuncAttributeMaxDynamicSharedMemorySize,
                         (int)sizeof(AttnSmem));

    // 1. pre-LN
    ln_kernel<<<NROWS, 256>>>(x, g1, be1, h);
    // 2. QKV (batched, tf32 tensor cores)
    dim3 gqkv(D_/128, NROWS/128, 3);
    mma_qkv_kernel<<<gqkv, 256>>>(h, Wq, Wk, Wv, bq, bk, bv, q, k, v);
    // 3. fused attention (tf32 tensor cores)
    dim3 gat(S_/64, H_, B_);
    attn_kernel<<<gat, 256, (int)sizeof(AttnSmem)>>>(q, k, v, ctx);
    // 4. Wo projection + residual -> x2
    dim3 go(D_/128, NROWS/128);
    mma_gemm_kernel<EPI_ADD><<<go, 256>>>(ctx, Wo, bo, x, x2, NROWS, D_, D_);
    // 5. LN2
    ln_kernel<<<NROWS, 256>>>(x2, g2, be2, ln2);
    // 6. MLP up + exact GELU
    dim3 gup(F_/128, NROWS/128);
    mma_gemm_kernel<EPI_GELU><<<gup, 256>>>(ln2, W1, b1, nullptr, act, NROWS, F_, D_);
    // 7. MLP down + bias + residual -> out
    dim3 gdn(D_/128, NROWS/128);
    mma_gemm_kernel<EPI_ADD><<<gdn, 256>>>(act, W2, b2, x2, out, NROWS, D_, F_);
}

// round 5
// speedup vs baseline: 2.4375x; 1.1213x over previous
#include <cuda_runtime.h>
#include <math.h>

#define B_  8
#define S_  1024
#define D_  768
#define H_  12
#define DH_ 64
#define F_  3072
#define NROWS (B_*S_)   /* 8192 */

#define EPI_NONE 0
#define EPI_GELU 1
#define EPI_ADD  2

// ---------------------------------------------------------------------------
// Scratch (device globals — no allocation allowed)
// ---------------------------------------------------------------------------
__device__ float g_h  [NROWS*D_];
__device__ float g_q  [NROWS*D_];
__device__ float g_k  [NROWS*D_];
__device__ float g_v  [NROWS*D_];
__device__ float g_ctx[NROWS*D_];
__device__ float g_x2 [NROWS*D_];
__device__ float g_ln2[NROWS*D_];
__device__ float g_act[NROWS*F_];

// ---------------------------------------------------------------------------
// helpers
// ---------------------------------------------------------------------------
__device__ __forceinline__ float gelu_f(float x) {
    return 0.5f * x * (1.0f + erff(x * 0.70710678118654752f));
}

__device__ __forceinline__ unsigned f2tf32(float x) {
    unsigned r;
    asm("cvt.rna.tf32.f32 %0, %1;" : "=r"(r) : "f"(x));
    return r;
}

__device__ __forceinline__ void mma_tf32(
    float c[4], const unsigned a[4], const unsigned b[2])
{
    asm volatile(
        "mma.sync.aligned.m16n8k8.row.col.f32.tf32.tf32.f32 "
        "{%0,%1,%2,%3}, {%4,%5,%6,%7}, {%8,%9}, {%0,%1,%2,%3};"
        : "+f"(c[0]), "+f"(c[1]), "+f"(c[2]), "+f"(c[3])
        : "r"(a[0]), "r"(a[1]), "r"(a[2]), "r"(a[3]),
          "r"(b[0]), "r"(b[1]));
}

__device__ __forceinline__ void cp_async16(unsigned smem_addr, const void* gptr) {
    asm volatile("cp.async.cg.shared.global [%0], [%1], 16;"
                 :: "r"(smem_addr), "l"(gptr));
}
__device__ __forceinline__ void cp_commit() {
    asm volatile("cp.async.commit_group;");
}
template<int N>
__device__ __forceinline__ void cp_wait() {
    asm volatile("cp.async.wait_group %0;" :: "n"(N));
}

// ---------------------------------------------------------------------------
// LayerNorm: one block per row, 256 threads, D=768 = 3 elems/thread
// ---------------------------------------------------------------------------
__global__ __launch_bounds__(256) void ln_kernel(
    const float* __restrict__ x, const float* __restrict__ gam,
    const float* __restrict__ bet, float* __restrict__ out)
{
    int row = blockIdx.x;
    int tid = threadIdx.x;
    const float* xr = x + (size_t)row * D_;
    float v0 = xr[tid], v1 = xr[tid + 256], v2 = xr[tid + 512];
    float s  = v0 + v1 + v2;
    float ss = v0*v0 + v1*v1 + v2*v2;
    #pragma unroll
    for (int o = 16; o > 0; o >>= 1) {
        s  += __shfl_xor_sync(0xffffffffu, s,  o);
        ss += __shfl_xor_sync(0xffffffffu, ss, o);
    }
    __shared__ float rs[8], rss[8];
    __shared__ float s_mu, s_inv;
    int w = tid >> 5, lane = tid & 31;
    if (lane == 0) { rs[w] = s; rss[w] = ss; }
    __syncthreads();
    if (tid == 0) {
        float ts = 0.f, tss = 0.f;
        #pragma unroll
        for (int i = 0; i < 8; i++) { ts += rs[i]; tss += rss[i]; }
        float mu  = ts * (1.0f / D_);
        float var = tss * (1.0f / D_) - mu * mu;
        s_mu = mu;
        s_inv = rsqrtf(var + 1e-6f);
    }
    __syncthreads();
    float mu = s_mu, inv = s_inv;
    float* orow = out + (size_t)row * D_;
    orow[tid]       = (v0 - mu) * inv * gam[tid]       + bet[tid];
    orow[tid + 256] = (v1 - mu) * inv * gam[tid + 256] + bet[tid + 256];
    orow[tid + 512] = (v2 - mu) * inv * gam[tid + 512] + bet[tid + 512];
}

// ---------------------------------------------------------------------------
// tf32 tensor-core GEMM, cp.async 3-stage pipeline.
// 128x128 block tile, BK=16, 256 threads (8 warps), warp tile 32x64,
// mma.sync.m16n8k8. A in smem natural [m][k] stride 20 (conflict-free frags,
// 16B-aligned rows); B [k][n] stride 136. fp32 bits fed to tf32 mma directly
// (hardware truncation; no cvt in the hot path).
// ---------------------------------------------------------------------------
#define LDA2 20
#define LDB2 136
#define A_STG (128*LDA2)          /* floats per A stage  = 2560 */
#define B_STG (16*LDB2)           /* floats per B stage  = 2176 */
#define SMEM_FLOATS (3*(A_STG + B_STG))   /* 14208 floats = 56832 B */

template<int EPI>
__device__ __forceinline__ void mma_gemm_body(
    const float* __restrict__ A, const float* __restrict__ Bm,
    const float* __restrict__ bias, const float* __restrict__ res,
    float* __restrict__ C, int M, int N, int K)
{
    extern __shared__ float smem[];
    float* As = smem;               // [3][128][LDA2]
    float* Bs = smem + 3*A_STG;     // [3][16][LDB2]
    unsigned As_u = (unsigned)__cvta_generic_to_shared(As);
    unsigned Bs_u = (unsigned)__cvta_generic_to_shared(Bs);

    int tid  = threadIdx.x;
    int bm = blockIdx.y * 128, bn = blockIdx.x * 128;
    int lane = tid & 31, warp = tid >> 5;
    int warp_m = warp >> 1;            // 0..3
    int warp_n = warp & 1;             // 0..1
    int g  = lane >> 2;                // 0..7
    int tg = lane & 3;                 // 0..3

    // loader indices (per 16B chunk)
    int a_row = tid >> 2, a_ko = (tid & 3) * 4;      // +64 rows on pass 2
    int b_kr  = tid >> 5, b_no = (tid & 31) * 4;     // +8 rows on pass 2

    const float* Ap0 = A + (size_t)(bm + a_row) * K + a_ko;
    const float* Ap1 = Ap0 + (size_t)64 * K;
    const float* Bp0 = Bm + (size_t)b_kr * N + bn + b_no;
    const float* Bp1 = Bp0 + (size_t)8 * N;

    unsigned a_dst0 = As_u + (a_row * LDA2 + a_ko) * 4;
    unsigned a_dst1 = As_u + ((a_row + 64) * LDA2 + a_ko) * 4;
    unsigned b_dst0 = Bs_u + (b_kr * LDB2 + b_no) * 4;
    unsigned b_dst1 = Bs_u + ((b_kr + 8) * LDB2 + b_no) * 4;

    float acc[2][8][4];
    #pragma unroll
    for (int mt = 0; mt < 2; mt++)
        #pragma unroll
        for (int nt = 0; nt < 8; nt++)
            #pragma unroll
            for (int i = 0; i < 4; i++) acc[mt][nt][i] = 0.f;

    int nk = K >> 4;

    // issue stage for k-tile kt into buffer st
    auto issue = [&](int st, int kt) {
        int kb = kt * 16;
        unsigned ao = st * A_STG * 4, bo = st * B_STG * 4;
        cp_async16(a_dst0 + ao, Ap0 + kb);
        cp_async16(a_dst1 + ao, Ap1 + kb);
        cp_async16(b_dst0 + bo, Bp0 + (size_t)kb * N);
        cp_async16(b_dst1 + bo, Bp1 + (size_t)kb * N);
        cp_commit();
    };

    issue(0, 0);
    issue(1, 1);

    for (int kt = 0; kt < nk; kt++) {
        if (kt + 2 < nk) cp_wait<1>(); else cp_wait<0>();
        __syncthreads();
        if (kt + 2 < nk) issue((kt + 2) % 3, kt + 2);

        const float* Ab = As + (kt % 3) * A_STG;
        const float* Bb = Bs + (kt % 3) * B_STG;

        #pragma unroll
        for (int ks = 0; ks < 2; ks++) {
            int k0 = ks * 8;
            unsigned af[2][4], bf[8][2];
            #pragma unroll
            for (int mt = 0; mt < 2; mt++) {
                int mb = warp_m * 32 + mt * 16 + g;
                af[mt][0] = __float_as_uint(Ab[(mb    ) * LDA2 + k0 + tg    ]);
                af[mt][1] = __float_as_uint(Ab[(mb + 8) * LDA2 + k0 + tg    ]);
                af[mt][2] = __float_as_uint(Ab[(mb    ) * LDA2 + k0 + tg + 4]);
                af[mt][3] = __float_as_uint(Ab[(mb + 8) * LDA2 + k0 + tg + 4]);
            }
            #pragma unroll
            for (int nt = 0; nt < 8; nt++) {
                int nb = warp_n * 64 + nt * 8 + g;
                bf[nt][0] = __float_as_uint(Bb[(k0 + tg    ) * LDB2 + nb]);
                bf[nt][1] = __float_as_uint(Bb[(k0 + tg + 4) * LDB2 + nb]);
            }
            #pragma unroll
            for (int mt = 0; mt < 2; mt++)
                #pragma unroll
                for (int nt = 0; nt < 8; nt++)
                    mma_tf32(acc[mt][nt], af[mt], bf[nt]);
        }
        __syncthreads();
    }

    // ---- epilogue ----
    #pragma unroll
    for (int mt = 0; mt < 2; mt++) {
        #pragma unroll
        for (int nt = 0; nt < 8; nt++) {
            int row0 = bm + warp_m * 32 + mt * 16 + g;
            int row1 = row0 + 8;
            int col  = bn + warp_n * 64 + nt * 8 + tg * 2;
            float2 bb = *(const float2*)&bias[col];
            float v0 = acc[mt][nt][0] + bb.x;
            float v1 = acc[mt][nt][1] + bb.y;
            float v2 = acc[mt][nt][2] + bb.x;
            float v3 = acc[mt][nt][3] + bb.y;
            if (EPI == EPI_GELU) {
                v0 = gelu_f(v0); v1 = gelu_f(v1);
                v2 = gelu_f(v2); v3 = gelu_f(v3);
            }
            if (EPI == EPI_ADD) {
                float2 r0 = *(const float2*)&res[(size_t)row0 * N + col];
                float2 r1 = *(const float2*)&res[(size_t)row1 * N + col];
                v0 += r0.x; v1 += r0.y; v2 += r1.x; v3 += r1.y;
            }
            *(float2*)&C[(size_t)row0 * N + col] = make_float2(v0, v1);
            *(float2*)&C[(size_t)row1 * N + col] = make_float2(v2, v3);
        }
    }
}

template<int EPI>
__global__ __launch_bounds__(256, 2) void mma_gemm_kernel(
    const float* __restrict__ A, const float* __restrict__ Bm,
    const float* __restrict__ bias, const float* __restrict__ res,
    float* __restrict__ C, int M, int N, int K)
{
    mma_gemm_body<EPI>(A, Bm, bias, res, C, M, N, K);
}

__global__ __launch_bounds__(256, 2) void mma_qkv_kernel(
    const float* __restrict__ A,
    const float* __restrict__ Wq, const float* __restrict__ Wk, const float* __restrict__ Wv,
    const float* __restrict__ bq, const float* __restrict__ bk, const float* __restrict__ bv,
    float* __restrict__ Cq, float* __restrict__ Ck, float* __restrict__ Cv)
{
    const float* Bm  = (blockIdx.z == 0) ? Wq : (blockIdx.z == 1) ? Wk : Wv;
    const float* bia = (blockIdx.z == 0) ? bq : (blockIdx.z == 1) ? bk : bv;
    float*       C   = (blockIdx.z == 0) ? Cq : (blockIdx.z == 1) ? Ck : Cv;
    mma_gemm_body<EPI_NONE>(A, Bm, bia, nullptr, C, NROWS, D_, D_);
}

// ---------------------------------------------------------------------------
// Fused attention, tensor-core edition (validated R3).
// ---------------------------------------------------------------------------
struct AttnSmem {
    float Q [64][68];
    float K [64][68];
    float Vt[64][68];
    float P [64][68];
    float m[64];
    float l[64];
    float corr[64];
    float red[4][64];
};

__global__ __launch_bounds__(256) void attn_kernel(
    const float* __restrict__ q, const float* __restrict__ k,
    const float* __restrict__ v, float* __restrict__ ctx)
{
    extern __shared__ char smem_raw[];
    AttnSmem* S = (AttnSmem*)smem_raw;
    int bb = blockIdx.z, hh = blockIdx.y;
    int q0 = blockIdx.x * 64;
    int tid = threadIdx.x;
    int lane = tid & 31, wid = tid >> 5;
    int g = lane >> 2, tg = lane & 3;
    int warp_m = wid >> 1, warp_n = wid & 1;
    int m0 = warp_m * 16;

    int lr = tid >> 2;
    int ld = (tid & 3) * 16;

    {
        const float* gq = q + ((size_t)((bb*S_ + q0 + lr)*H_ + hh))*DH_ + ld;
        #pragma unroll
        for (int c = 0; c < 4; c++) {
            float4 t = *(const float4*)(gq + c*4);
            uint4 u;
            u.x = f2tf32(t.x * 0.125f);
            u.y = f2tf32(t.y * 0.125f);
            u.z = f2tf32(t.z * 0.125f);
            u.w = f2tf32(t.w * 0.125f);
            *(uint4*)&S->Q[lr][ld + c*4] = u;
        }
    }
    if (tid < 64) { S->m[tid] = -1e30f; S->l[tid] = 0.f; }

    float o[4][4];
    #pragma unroll
    for (int nt = 0; nt < 4; nt++)
        #pragma unroll
        for (int i = 0; i < 4; i++) o[nt][i] = 0.f;

    int srow = tid >> 2, part = tid & 3;

    __syncthreads();

    for (int kt = 0; kt < 16; kt++) {
        int k0g = kt * 64;
        {
            const float* gk = k + ((size_t)((bb*S_ + k0g + lr)*H_ + hh))*DH_ + ld;
            const float* gv = v + ((size_t)((bb*S_ + k0g + lr)*H_ + hh))*DH_ + ld;
            #pragma unroll
            for (int c = 0; c < 4; c++) {
                float4 t = *(const float4*)(gk + c*4);
                uint4 u;
                u.x = f2tf32(t.x); u.y = f2tf32(t.y);
                u.z = f2tf32(t.z); u.w = f2tf32(t.w);
                *(uint4*)&S->K[lr][ld + c*4] = u;
                float4 tv = *(const float4*)(gv + c*4);
                int d = ld + c*4;
                S->Vt[d+0][lr] = __uint_as_float(f2tf32(tv.x));
                S->Vt[d+1][lr] = __uint_as_float(f2tf32(tv.y));
                S->Vt[d+2][lr] = __uint_as_float(f2tf32(tv.z));
                S->Vt[d+3][lr] = __uint_as_float(f2tf32(tv.w));
            }
        }
        __syncthreads();

        {
            float s[4][4];
            #pragma unroll
            for (int nt = 0; nt < 4; nt++)
                #pragma unroll
                for (int i = 0; i < 4; i++) s[nt][i] = 0.f;
            #pragma unroll
            for (int ks = 0; ks < 8; ks++) {
                int k0 = ks * 8;
                unsigned a[4];
                a[0] = __float_as_uint(S->Q[m0 + g    ][k0 + tg    ]);
                a[1] = __float_as_uint(S->Q[m0 + g + 8][k0 + tg    ]);
                a[2] = __float_as_uint(S->Q[m0 + g    ][k0 + tg + 4]);
                a[3] = __float_as_uint(S->Q[m0 + g + 8][k0 + tg + 4]);
                #pragma unroll
                for (int nt = 0; nt < 4; nt++) {
                    int n0 = warp_n * 32 + nt * 8;
                    unsigned b[2];
                    b[0] = __float_as_uint(S->K[n0 + g][k0 + tg    ]);
                    b[1] = __float_as_uint(S->K[n0 + g][k0 + tg + 4]);
                    mma_tf32(s[nt], a, b);
                }
            }
            #pragma unroll
            for (int nt = 0; nt < 4; nt++) {
                int n0 = warp_n * 32 + nt * 8;
                *(float2*)&S->P[m0 + g    ][n0 + tg*2] = make_float2(s[nt][0], s[nt][1]);
                *(float2*)&S->P[m0 + g + 8][n0 + tg*2] = make_float2(s[nt][2], s[nt][3]);
            }
        }
        __syncthreads();

        float lmax = -1e30f;
        #pragma unroll
        for (int j = 0; j < 16; j++)
            lmax = fmaxf(lmax, S->P[srow][part*16 + j]);
        S->red[part][srow] = lmax;
        __syncthreads();
        if (tid < 64) {
            float mo = S->m[tid];
            float mn = fmaxf(fmaxf(S->red[0][tid], S->red[1][tid]),
                             fmaxf(S->red[2][tid], S->red[3][tid]));
            mn = fmaxf(mn, mo);
            S->corr[tid] = __expf(mo - mn);
            S->m[tid] = mn;
        }
        __syncthreads();
        {
            float mn = S->m[srow];
            float ls = 0.f;
            #pragma unroll
            for (int j = 0; j < 16; j++) {
                float p = __expf(S->P[srow][part*16 + j] - mn);
                S->P[srow][part*16 + j] = __uint_as_float(f2tf32(p));
                ls += p;
            }
            S->red[part][srow] = ls;
        }
        __syncthreads();
        if (tid < 64)
            S->l[tid] = S->l[tid] * S->corr[tid]
                      + S->red[0][tid] + S->red[1][tid]
                      + S->red[2][tid] + S->red[3][tid];

        {
            float cr0 = S->corr[m0 + g], cr1 = S->corr[m0 + g + 8];
            #pragma unroll
            for (int nt = 0; nt < 4; nt++) {
                o[nt][0] *= cr0; o[nt][1] *= cr0;
                o[nt][2] *= cr1; o[nt][3] *= cr1;
            }
            #pragma unroll
            for (int ks = 0; ks < 8; ks++) {
                int k0 = ks * 8;
                unsigned a[4];
                a[0] = __float_as_uint(S->P[m0 + g    ][k0 + tg    ]);
                a[1] = __float_as_uint(S->P[m0 + g + 8][k0 + tg    ]);
                a[2] = __float_as_uint(S->P[m0 + g    ][k0 + tg + 4]);
                a[3] = __float_as_uint(S->P[m0 + g + 8][k0 + tg + 4]);
                #pragma unroll
                for (int nt = 0; nt < 4; nt++) {
                    int n0 = warp_n * 32 + nt * 8;
                    unsigned b[2];
                    b[0] = __float_as_uint(S->Vt[n0 + g][k0 + tg    ]);
                    b[1] = __float_as_uint(S->Vt[n0 + g][k0 + tg + 4]);
                    mma_tf32(o[nt], a, b);
                }
            }
        }
        __syncthreads();
    }

    float inv0 = 1.0f / S->l[m0 + g];
    float inv1 = 1.0f / S->l[m0 + g + 8];
    int row0 = bb*S_ + q0 + m0 + g;
    int row1 = row0 + 8;
    #pragma unroll
    for (int nt = 0; nt < 4; nt++) {
        int d = warp_n * 32 + nt * 8 + tg * 2;
        *(float2*)&ctx[((size_t)(row0*H_ + hh))*DH_ + d] =
            make_float2(o[nt][0] * inv0, o[nt][1] * inv0);
        *(float2*)&ctx[((size_t)(row1*H_ + hh))*DH_ + d] =
            make_float2(o[nt][2] * inv1, o[nt][3] * inv1);
    }
}

// ---------------------------------------------------------------------------
// Launcher
// ---------------------------------------------------------------------------
extern "C" void kernel_launch(void* const* d_in, const int* in_sizes, int n_in,
                              void* d_out, int out_size)
{
    const float* x   = (const float*)d_in[0];
    const float* Wq  = (const float*)d_in[1];
    const float* bq  = (const float*)d_in[2];
    const float* Wk  = (const float*)d_in[3];
    const float* bk  = (const float*)d_in[4];
    const float* Wv  = (const float*)d_in[5];
    const float* bv  = (const float*)d_in[6];
    const float* Wo  = (const float*)d_in[7];
    const float* bo  = (const float*)d_in[8];
    const float* g1  = (const float*)d_in[9];
    const float* be1 = (const float*)d_in[10];
    const float* g2  = (const float*)d_in[11];
    const float* be2 = (const float*)d_in[12];
    const float* W1  = (const float*)d_in[13];
    const float* b1  = (const float*)d_in[14];
    const float* W2  = (const float*)d_in[15];
    const float* b2  = (const float*)d_in[16];
    float* out = (float*)d_out;

    float *h, *q, *k, *v, *ctx, *x2, *ln2, *act;
    cudaGetSymbolAddress((void**)&h,   g_h);
    cudaGetSymbolAddress((void**)&q,   g_q);
    cudaGetSymbolAddress((void**)&k,   g_k);
    cudaGetSymbolAddress((void**)&v,   g_v);
    cudaGetSymbolAddress((void**)&ctx, g_ctx);
    cudaGetSymbolAddress((void**)&x2,  g_x2);
    cudaGetSymbolAddress((void**)&ln2, g_ln2);
    cudaGetSymbolAddress((void**)&act, g_act);

    const int gemm_smem = SMEM_FLOATS * 4;   // 56832 B
    cudaFuncSetAttribute(mma_gemm_kernel<EPI_ADD>,
                         cudaFuncAttributeMaxDynamicSharedMemorySize, gemm_smem);
    cudaFuncSetAttribute(mma_gemm_kernel<EPI_GELU>,
                         cudaFuncAttributeMaxDynamicSharedMemorySize, gemm_smem);
    cudaFuncSetAttribute(mma_qkv_kernel,
                         cudaFuncAttributeMaxDynamicSharedMemorySize, gemm_smem);
    cudaFuncSetAttribute(attn_kernel,
                         cudaFuncAttributeMaxDynamicSharedMemorySize,
                         (int)sizeof(AttnSmem));

    // 1. pre-LN
    ln_kernel<<<NROWS, 256>>>(x, g1, be1, h);
    // 2. QKV (batched, tf32 tensor cores, cp.async)
    dim3 gqkv(D_/128, NROWS/128, 3);
    mma_qkv_kernel<<<gqkv, 256, gemm_smem>>>(h, Wq, Wk, Wv, bq, bk, bv, q, k, v);
    // 3. fused attention (tf32 tensor cores)
    dim3 gat(S_/64, H_, B_);
    attn_kernel<<<gat, 256, (int)sizeof(AttnSmem)>>>(q, k, v, ctx);
    // 4. Wo projection + residual -> x2
    dim3 go(D_/128, NROWS/128);
    mma_gemm_kernel<EPI_ADD><<<go, 256, gemm_smem>>>(ctx, Wo, bo, x, x2, NROWS, D_, D_);
    // 5. LN2
    ln_kernel<<<NROWS, 256>>>(x2, g2, be2, ln2);
    // 6. MLP up + exact GELU
    dim3 gup(F_/128, NROWS/128);
    mma_gemm_kernel<EPI_GELU><<<gup, 256, gemm_smem>>>(ln2, W1, b1, nullptr, act, NROWS, F_, D_);
    // 7. MLP down + bias + residual -> out
    dim3 gdn(D_/128, NROWS/128);
    mma_gemm_kernel<EPI_ADD><<<gdn, 256, gemm_smem>>>(act, W2, b2, x2, out, NROWS, D_, F_);
}

// round 7
// speedup vs baseline: 3.3314x; 1.3667x over previous
#include <cuda_runtime.h>
#include <cuda_fp16.h>
#include <math.h>
#include <stdint.h>

#define B_  8
#define S_  1024
#define D_  768
#define H_  12
#define DH_ 64
#define F_  3072
#define NROWS (B_*S_)   /* 8192 */

#define EPI_NONE 0
#define EPI_GELU 1
#define EPI_ADD  2

// ---------------------------------------------------------------------------
// Scratch (device globals — no allocation allowed)
// ---------------------------------------------------------------------------
__device__ __half g_h  [NROWS*D_];
__device__ __half g_q  [NROWS*D_];
__device__ __half g_k  [NROWS*D_];
__device__ __half g_v  [NROWS*D_];
__device__ __half g_ctx[NROWS*D_];
__device__ float  g_x2 [NROWS*D_];
__device__ __half g_ln2[NROWS*D_];
__device__ __half g_act[NROWS*F_];
// transposed fp16 weights: Wq^T,Wk^T,Wv^T,Wo^T (768x768), W1^T (3072x768), W2^T (768x3072)
#define WT_Q  0
#define WT_K  (768*768)
#define WT_V  (2*768*768)
#define WT_O  (3*768*768)
#define WT_W1 (4*768*768)
#define WT_W2 (4*768*768 + 3072*768)
__device__ __half g_wt [4*768*768 + 2*3072*768];

// ---------------------------------------------------------------------------
// helpers
// ---------------------------------------------------------------------------
__device__ __forceinline__ float gelu_f(float x) {
    return 0.5f * x * (1.0f + erff(x * 0.70710678118654752f));
}

__device__ __forceinline__ unsigned f2tf32(float x) {
    unsigned r;
    asm("cvt.rna.tf32.f32 %0, %1;" : "=r"(r) : "f"(x));
    return r;
}

__device__ __forceinline__ void mma_tf32(
    float c[4], const unsigned a[4], const unsigned b[2])
{
    asm volatile(
        "mma.sync.aligned.m16n8k8.row.col.f32.tf32.tf32.f32 "
        "{%0,%1,%2,%3}, {%4,%5,%6,%7}, {%8,%9}, {%0,%1,%2,%3};"
        : "+f"(c[0]), "+f"(c[1]), "+f"(c[2]), "+f"(c[3])
        : "r"(a[0]), "r"(a[1]), "r"(a[2]), "r"(a[3]),
          "r"(b[0]), "r"(b[1]));
}

__device__ __forceinline__ void mma_f16(
    float c[4], const unsigned a[4], const unsigned b[2])
{
    asm volatile(
        "mma.sync.aligned.m16n8k16.row.col.f32.f16.f16.f32 "
        "{%0,%1,%2,%3}, {%4,%5,%6,%7}, {%8,%9}, {%0,%1,%2,%3};"
        : "+f"(c[0]), "+f"(c[1]), "+f"(c[2]), "+f"(c[3])
        : "r"(a[0]), "r"(a[1]), "r"(a[2]), "r"(a[3]),
          "r"(b[0]), "r"(b[1]));
}

__device__ __forceinline__ void cp_async16(unsigned smem_addr, const void* gptr) {
    asm volatile("cp.async.cg.shared.global [%0], [%1], 16;"
                 :: "r"(smem_addr), "l"(gptr));
}
__device__ __forceinline__ void cp_commit() {
    asm volatile("cp.async.commit_group;");
}
template<int N>
__device__ __forceinline__ void cp_wait() {
    asm volatile("cp.async.wait_group %0;" :: "n"(N));
}

// ---------------------------------------------------------------------------
// LayerNorm: fp32 in, fp16 out. One block per row, 256 threads.
// ---------------------------------------------------------------------------
__global__ __launch_bounds__(256) void ln_kernel(
    const float* __restrict__ x, const float* __restrict__ gam,
    const float* __restrict__ bet, __half* __restrict__ out)
{
    int row = blockIdx.x;
    int tid = threadIdx.x;
    const float* xr = x + (size_t)row * D_;
    float v0 = xr[tid], v1 = xr[tid + 256], v2 = xr[tid + 512];
    float s  = v0 + v1 + v2;
    float ss = v0*v0 + v1*v1 + v2*v2;
    #pragma unroll
    for (int o = 16; o > 0; o >>= 1) {
        s  += __shfl_xor_sync(0xffffffffu, s,  o);
        ss += __shfl_xor_sync(0xffffffffu, ss, o);
    }
    __shared__ float rs[8], rss[8];
    __shared__ float s_mu, s_inv;
    int w = tid >> 5, lane = tid & 31;
    if (lane == 0) { rs[w] = s; rss[w] = ss; }
    __syncthreads();
    if (tid == 0) {
        float ts = 0.f, tss = 0.f;
        #pragma unroll
        for (int i = 0; i < 8; i++) { ts += rs[i]; tss += rss[i]; }
        float mu  = ts * (1.0f / D_);
        float var = tss * (1.0f / D_) - mu * mu;
        s_mu = mu;
        s_inv = rsqrtf(var + 1e-6f);
    }
    __syncthreads();
    float mu = s_mu, inv = s_inv;
    __half* orow = out + (size_t)row * D_;
    orow[tid]       = __float2half_rn((v0 - mu) * inv * gam[tid]       + bet[tid]);
    orow[tid + 256] = __float2half_rn((v1 - mu) * inv * gam[tid + 256] + bet[tid + 256]);
    orow[tid + 512] = __float2half_rn((v2 - mu) * inv * gam[tid + 512] + bet[tid + 512]);
}

// ---------------------------------------------------------------------------
// Weight transpose + fp16 convert: out[c][r] = half(in[r][c]).
// ---------------------------------------------------------------------------
__global__ __launch_bounds__(256) void transpose_kernel(
    const float* __restrict__ in, __half* __restrict__ out, int R, int Ccols)
{
    __shared__ float t[32][33];
    int c0 = blockIdx.x * 32, r0 = blockIdx.y * 32;
    int x = threadIdx.x, y = threadIdx.y;
    #pragma unroll
    for (int i = 0; i < 32; i += 8)
        t[y + i][x] = in[(size_t)(r0 + y + i) * Ccols + c0 + x];
    __syncthreads();
    #pragma unroll
    for (int i = 0; i < 32; i += 8)
        out[(size_t)(c0 + y + i) * R + r0 + x] = __float2half_rn(t[x][y + i]);
}

// ---------------------------------------------------------------------------
// fp16 tensor-core GEMM, cp.async 3-stage pipeline.
// 128x128 block tile, BK=32 halves, 256 threads (8 warps), warp tile 32x64,
// mma.sync.m16n8k16.f16, fp32 accumulate. A [M][K], Bt [N][K], both fp16
// row-major; smem tiles [row][k], row stride 40 halves (conflict-free frags).
// ---------------------------------------------------------------------------
#define BK 32
#define LDAH 40
#define STG_H (128*LDAH)
#define NSTG 3
#define GEMM_SMEM_BYTES (NSTG*2*STG_H*2)   /* 61440 B */

template<int EPI>
__device__ __forceinline__ void h_gemm_body(
    const __half* __restrict__ A, const __half* __restrict__ Bt,
    const float* __restrict__ bias, const float* __restrict__ res,
    void* __restrict__ Cout, int M, int N, int K)
{
    extern __shared__ __half hsm[];
    __half* As = hsm;
    __half* Bs = hsm + NSTG * STG_H;

    int tid  = threadIdx.x;
    int bm = blockIdx.y * 128, bn = blockIdx.x * 128;
    int lane = tid & 31, warp = tid >> 5;
    int warp_m = warp >> 1;
    int warp_n = warp & 1;
    int g  = lane >> 2;
    int tg = lane & 3;

    unsigned a_su[NSTG], b_su[NSTG];
    #pragma unroll
    for (int s = 0; s < NSTG; s++) {
        a_su[s] = (unsigned)__cvta_generic_to_shared(As + s * STG_H);
        b_su[s] = (unsigned)__cvta_generic_to_shared(Bs + s * STG_H);
    }

    float acc[2][8][4];
    #pragma unroll
    for (int mt = 0; mt < 2; mt++)
        #pragma unroll
        for (int nt = 0; nt < 8; nt++)
            #pragma unroll
            for (int i = 0; i < 4; i++) acc[mt][nt][i] = 0.f;

    int nck = K / BK;

    auto issue = [&](int st, int ck) {
        int kb = ck * BK;
        #pragma unroll
        for (int p = 0; p < 2; p++) {
            int cid = tid + p * 256;
            int row = cid >> 2, c = cid & 3;
            unsigned off = (unsigned)((row * LDAH + c * 8) * 2);
            cp_async16(a_su[st] + off, A  + (size_t)(bm + row) * K + kb + c * 8);
            cp_async16(b_su[st] + off, Bt + (size_t)(bn + row) * K + kb + c * 8);
        }
        cp_commit();
    };

    issue(0, 0);
    issue(1, 1);

    for (int ck = 0; ck < nck; ck++) {
        int st = ck % 3;
        if (ck + 2 < nck) cp_wait<1>(); else cp_wait<0>();
        __syncthreads();
        if (ck + 2 < nck) issue((ck + 2) % 3, ck + 2);

        const __half* Ab = As + st * STG_H;
        const __half* Bb = Bs + st * STG_H;

        #pragma unroll
        for (int ks = 0; ks < 2; ks++) {
            int k0 = ks * 16;
            unsigned af[2][4], bf[8][2];
            #pragma unroll
            for (int mt = 0; mt < 2; mt++) {
                int mb = warp_m * 32 + mt * 16;
                af[mt][0] = *(const unsigned*)&Ab[(mb + g    ) * LDAH + k0 + 2*tg    ];
                af[mt][1] = *(const unsigned*)&Ab[(mb + g + 8) * LDAH + k0 + 2*tg    ];
                af[mt][2] = *(const unsigned*)&Ab[(mb + g    ) * LDAH + k0 + 2*tg + 8];
                af[mt][3] = *(const unsigned*)&Ab[(mb + g + 8) * LDAH + k0 + 2*tg + 8];
            }
            #pragma unroll
            for (int nt = 0; nt < 8; nt++) {
                int nb = warp_n * 64 + nt * 8;
                bf[nt][0] = *(const unsigned*)&Bb[(nb + g) * LDAH + k0 + 2*tg    ];
                bf[nt][1] = *(const unsigned*)&Bb[(nb + g) * LDAH + k0 + 2*tg + 8];
            }
            #pragma unroll
            for (int mt = 0; mt < 2; mt++)
                #pragma unroll
                for (int nt = 0; nt < 8; nt++)
                    mma_f16(acc[mt][nt], af[mt], bf[nt]);
        }
        __syncthreads();
    }

    #pragma unroll
    for (int mt = 0; mt < 2; mt++) {
        #pragma unroll
        for (int nt = 0; nt < 8; nt++) {
            int row0 = bm + warp_m * 32 + mt * 16 + g;
            int row1 = row0 + 8;
            int col  = bn + warp_n * 64 + nt * 8 + tg * 2;
            float2 bb = *(const float2*)&bias[col];
            float v0 = acc[mt][nt][0] + bb.x;
            float v1 = acc[mt][nt][1] + bb.y;
            float v2 = acc[mt][nt][2] + bb.x;
            float v3 = acc[mt][nt][3] + bb.y;
            if (EPI == EPI_GELU) {
                v0 = gelu_f(v0); v1 = gelu_f(v1);
                v2 = gelu_f(v2); v3 = gelu_f(v3);
            }
            if (EPI == EPI_ADD) {
                float* C = (float*)Cout;
                float2 r0 = *(const float2*)&res[(size_t)row0 * N + col];
                float2 r1 = *(const float2*)&res[(size_t)row1 * N + col];
                v0 += r0.x; v1 += r0.y; v2 += r1.x; v3 += r1.y;
                *(float2*)&C[(size_t)row0 * N + col] = make_float2(v0, v1);
                *(float2*)&C[(size_t)row1 * N + col] = make_float2(v2, v3);
            } else {
                __half* C = (__half*)Cout;
                *(__half2*)&C[(size_t)row0 * N + col] = __floats2half2_rn(v0, v1);
                *(__half2*)&C[(size_t)row1 * N + col] = __floats2half2_rn(v2, v3);
            }
        }
    }
}

template<int EPI>
__global__ __launch_bounds__(256, 2) void h_gemm_kernel(
    const __half* __restrict__ A, const __half* __restrict__ Bt,
    const float* __restrict__ bias, const float* __restrict__ res,
    void* __restrict__ Cout, int M, int N, int K)
{
    h_gemm_body<EPI>(A, Bt, bias, res, Cout, M, N, K);
}

__global__ __launch_bounds__(256, 2) void h_qkv_kernel(
    const __half* __restrict__ A, const __half* __restrict__ wt,
    const float* __restrict__ bq, const float* __restrict__ bk, const float* __restrict__ bv,
    __half* __restrict__ Cq, __half* __restrict__ Ck, __half* __restrict__ Cv)
{
    const __half* Bt  = wt + (size_t)blockIdx.z * (768 * 768);
    const float*  bia = (blockIdx.z == 0) ? bq : (blockIdx.z == 1) ? bk : bv;
    __half*       C   = (blockIdx.z == 0) ? Cq : (blockIdx.z == 1) ? Ck : Cv;
    h_gemm_body<EPI_NONE>(A, Bt, bia, nullptr, (void*)C, NROWS, D_, D_);
}

// ---------------------------------------------------------------------------
// Fused attention: fp16 inputs (exact in tf32), tf32 mma.sync; fp16 ctx out.
// ---------------------------------------------------------------------------
struct AttnSmem {
    float Q [64][68];
    float K [64][68];
    float Vt[64][68];
    float P [64][68];
    float m[64];
    float l[64];
    float corr[64];
    float red[4][64];
};

__global__ __launch_bounds__(256) void attn_kernel(
    const __half* __restrict__ q, const __half* __restrict__ k,
    const __half* __restrict__ v, __half* __restrict__ ctx)
{
    extern __shared__ char smem_raw[];
    AttnSmem* S = (AttnSmem*)smem_raw;
    int bb = blockIdx.z, hh = blockIdx.y;
    int q0 = blockIdx.x * 64;
    int tid = threadIdx.x;
    int lane = tid & 31, wid = tid >> 5;
    int g = lane >> 2, tg = lane & 3;
    int warp_m = wid >> 1, warp_n = wid & 1;
    int m0 = warp_m * 16;

    int lr = tid >> 2;
    int ld = (tid & 3) * 16;

    {
        const __half* gq = q + ((size_t)((bb*S_ + q0 + lr)*H_ + hh))*DH_ + ld;
        #pragma unroll
        for (int c = 0; c < 8; c++) {
            float2 f = __half22float2(*(const __half2*)(gq + 2*c));
            S->Q[lr][ld + 2*c    ] = f.x * 0.125f;
            S->Q[lr][ld + 2*c + 1] = f.y * 0.125f;
        }
    }
    if (tid < 64) { S->m[tid] = -1e30f; S->l[tid] = 0.f; }

    float o[4][4];
    #pragma unroll
    for (int nt = 0; nt < 4; nt++)
        #pragma unroll
        for (int i = 0; i < 4; i++) o[nt][i] = 0.f;

    int srow = tid >> 2, part = tid & 3;

    __syncthreads();

    for (int kt = 0; kt < 16; kt++) {
        int k0g = kt * 64;
        {
            const __half* gk = k + ((size_t)((bb*S_ + k0g + lr)*H_ + hh))*DH_ + ld;
            const __half* gv = v + ((size_t)((bb*S_ + k0g + lr)*H_ + hh))*DH_ + ld;
            #pragma unroll
            for (int c = 0; c < 8; c++) {
                float2 fk = __half22float2(*(const __half2*)(gk + 2*c));
                S->K[lr][ld + 2*c    ] = fk.x;
                S->K[lr][ld + 2*c + 1] = fk.y;
                float2 fv = __half22float2(*(const __half2*)(gv + 2*c));
                int d = ld + 2*c;
                S->Vt[d    ][lr] = fv.x;
                S->Vt[d + 1][lr] = fv.y;
            }
        }
        __syncthreads();

        {
            float s[4][4];
            #pragma unroll
            for (int nt = 0; nt < 4; nt++)
                #pragma unroll
                for (int i = 0; i < 4; i++) s[nt][i] = 0.f;
            #pragma unroll
            for (int ks = 0; ks < 8; ks++) {
                int k0 = ks * 8;
                unsigned a[4];
                a[0] = __float_as_uint(S->Q[m0 + g    ][k0 + tg    ]);
                a[1] = __float_as_uint(S->Q[m0 + g + 8][k0 + tg    ]);
                a[2] = __float_as_uint(S->Q[m0 + g    ][k0 + tg + 4]);
                a[3] = __float_as_uint(S->Q[m0 + g + 8][k0 + tg + 4]);
                #pragma unroll
                for (int nt = 0; nt < 4; nt++) {
                    int n0 = warp_n * 32 + nt * 8;
                    unsigned b[2];
                    b[0] = __float_as_uint(S->K[n0 + g][k0 + tg    ]);
                    b[1] = __float_as_uint(S->K[n0 + g][k0 + tg + 4]);
                    mma_tf32(s[nt], a, b);
                }
            }
            #pragma unroll
            for (int nt = 0; nt < 4; nt++) {
                int n0 = warp_n * 32 + nt * 8;
                *(float2*)&S->P[m0 + g    ][n0 + tg*2] = make_float2(s[nt][0], s[nt][1]);
                *(float2*)&S->P[m0 + g + 8][n0 + tg*2] = make_float2(s[nt][2], s[nt][3]);
            }
        }
        __syncthreads();

        float lmax = -1e30f;
        #pragma unroll
        for (int j = 0; j < 16; j++)
            lmax = fmaxf(lmax, S->P[srow][part*16 + j]);
        S->red[part][srow] = lmax;
        __syncthreads();
        if (tid < 64) {
            float mo = S->m[tid];
            float mn = fmaxf(fmaxf(S->red[0][tid], S->red[1][tid]),
                             fmaxf(S->red[2][tid], S->red[3][tid]));
            mn = fmaxf(mn, mo);
            S->corr[tid] = __expf(mo - mn);
            S->m[tid] = mn;
        }
        __syncthreads();
        {
            float mn = S->m[srow];
            float ls = 0.f;
            #pragma unroll
            for (int j = 0; j < 16; j++) {
                float p = __expf(S->P[srow][part*16 + j] - mn);
                S->P[srow][part*16 + j] = __uint_as_float(f2tf32(p));
                ls += p;
            }
            S->red[part][srow] = ls;
        }
        __syncthreads();
        if (tid < 64)
            S->l[tid] = S->l[tid] * S->corr[tid]
                      + S->red[0][tid] + S->red[1][tid]
                      + S->red[2][tid] + S->red[3][tid];

        {
            float cr0 = S->corr[m0 + g], cr1 = S->corr[m0 + g + 8];
            #pragma unroll
            for (int nt = 0; nt < 4; nt++) {
                o[nt][0] *= cr0; o[nt][1] *= cr0;
                o[nt][2] *= cr1; o[nt][3] *= cr1;
            }
            #pragma unroll
            for (int ks = 0; ks < 8; ks++) {
                int k0 = ks * 8;
                unsigned a[4];
                a[0] = __float_as_uint(S->P[m0 + g    ][k0 + tg    ]);
                a[1] = __float_as_uint(S->P[m0 + g + 8][k0 + tg    ]);
                a[2] = __float_as_uint(S->P[m0 + g    ][k0 + tg + 4]);
                a[3] = __float_as_uint(S->P[m0 + g + 8][k0 + tg + 4]);
                #pragma unroll
                for (int nt = 0; nt < 4; nt++) {
                    int n0 = warp_n * 32 + nt * 8;
                    unsigned b[2];
                    b[0] = __float_as_uint(S->Vt[n0 + g][k0 + tg    ]);
                    b[1] = __float_as_uint(S->Vt[n0 + g][k0 + tg + 4]);
                    mma_tf32(o[nt], a, b);
                }
            }
        }
        __syncthreads();
    }

    float inv0 = 1.0f / S->l[m0 + g];
    float inv1 = 1.0f / S->l[m0 + g + 8];
    int row0 = bb*S_ + q0 + m0 + g;
    int row1 = row0 + 8;
    #pragma unroll
    for (int nt = 0; nt < 4; nt++) {
        int d = warp_n * 32 + nt * 8 + tg * 2;
        *(__half2*)&ctx[((size_t)(row0*H_ + hh))*DH_ + d] =
            __floats2half2_rn(o[nt][0] * inv0, o[nt][1] * inv0);
        *(__half2*)&ctx[((size_t)(row1*H_ + hh))*DH_ + d] =
            __floats2half2_rn(o[nt][2] * inv1, o[nt][3] * inv1);
    }
}

// ---------------------------------------------------------------------------
// Launcher
// ---------------------------------------------------------------------------
extern "C" void kernel_launch(void* const* d_in, const int* in_sizes, int n_in,
                              void* d_out, int out_size)
{
    const float* x   = (const float*)d_in[0];
    const float* Wq  = (const float*)d_in[1];
    const float* bq  = (const float*)d_in[2];
    const float* Wk  = (const float*)d_in[3];
    const float* bk  = (const float*)d_in[4];
    const float* Wv  = (const float*)d_in[5];
    const float* bv  = (const float*)d_in[6];
    const float* Wo  = (const float*)d_in[7];
    const float* bo  = (const float*)d_in[8];
    const float* g1  = (const float*)d_in[9];
    const float* be1 = (const float*)d_in[10];
    const float* g2  = (const float*)d_in[11];
    const float* be2 = (const float*)d_in[12];
    const float* W1  = (const float*)d_in[13];
    const float* b1  = (const float*)d_in[14];
    const float* W2  = (const float*)d_in[15];
    const float* b2  = (const float*)d_in[16];
    float* out = (float*)d_out;

    __half *h, *q, *k, *v, *ctx, *ln2, *act, *wt;
    float *x2;
    cudaGetSymbolAddress((void**)&h,   g_h);
    cudaGetSymbolAddress((void**)&q,   g_q);
    cudaGetSymbolAddress((void**)&k,   g_k);
    cudaGetSymbolAddress((void**)&v,   g_v);
    cudaGetSymbolAddress((void**)&ctx, g_ctx);
    cudaGetSymbolAddress((void**)&x2,  g_x2);
    cudaGetSymbolAddress((void**)&ln2, g_ln2);
    cudaGetSymbolAddress((void**)&act, g_act);
    cudaGetSymbolAddress((void**)&wt,  g_wt);

    cudaFuncSetAttribute(h_gemm_kernel<EPI_ADD>,
                         cudaFuncAttributeMaxDynamicSharedMemorySize, GEMM_SMEM_BYTES);
    cudaFuncSetAttribute(h_gemm_kernel<EPI_GELU>,
                         cudaFuncAttributeMaxDynamicSharedMemorySize, GEMM_SMEM_BYTES);
    cudaFuncSetAttribute(h_qkv_kernel,
                         cudaFuncAttributeMaxDynamicSharedMemorySize, GEMM_SMEM_BYTES);
    cudaFuncSetAttribute(attn_kernel,
                         cudaFuncAttributeMaxDynamicSharedMemorySize,
                         (int)sizeof(AttnSmem));

    dim3 tb(32, 8);
    // 0. weight transpose + fp16 convert
    transpose_kernel<<<dim3(24, 24), tb>>>(Wq, wt + WT_Q,  768, 768);
    transpose_kernel<<<dim3(24, 24), tb>>>(Wk, wt + WT_K,  768, 768);
    transpose_kernel<<<dim3(24, 24), tb>>>(Wv, wt + WT_V,  768, 768);
    transpose_kernel<<<dim3(24, 24), tb>>>(Wo, wt + WT_O,  768, 768);
    transpose_kernel<<<dim3(96, 24), tb>>>(W1, wt + WT_W1, 768, 3072);
    transpose_kernel<<<dim3(24, 96), tb>>>(W2, wt + WT_W2, 3072, 768);

    // 1. pre-LN -> fp16 h
    ln_kernel<<<NROWS, 256>>>(x, g1, be1, h);
    // 2. QKV (fp16 mma, batched) -> fp16 q,k,v
    dim3 gqkv(D_/128, NROWS/128, 3);
    h_qkv_kernel<<<gqkv, 256, GEMM_SMEM_BYTES>>>(h, wt, bq, bk, bv, q, k, v);
    // 3. fused attention -> fp16 ctx
    dim3 gat(S_/64, H_, B_);
    attn_kernel<<<gat, 256, (int)sizeof(AttnSmem)>>>(q, k, v, ctx);
    // 4. Wo projection + residual -> fp32 x2
    dim3 go(D_/128, NROWS/128);
    h_gemm_kernel<EPI_ADD><<<go, 256, GEMM_SMEM_BYTES>>>(ctx, wt + WT_O, bo, x, (void*)x2, NROWS, D_, D_);
    // 5. LN2 -> fp16 ln2
    ln_kernel<<<NROWS, 256>>>(x2, g2, be2, ln2);
    // 6. MLP up + exact GELU -> fp16 act
    dim3 gup(F_/128, NROWS/128);
    h_gemm_kernel<EPI_GELU><<<gup, 256, GEMM_SMEM_BYTES>>>(ln2, wt + WT_W1, b1, nullptr, (void*)act, NROWS, F_, D_);
    // 7. MLP down + bias + residual -> fp32 out
    dim3 gdn(D_/128, NROWS/128);
    h_gemm_kernel<EPI_ADD><<<gdn, 256, GEMM_SMEM_BYTES>>>(act, wt + WT_W2, b2, x2, (void*)out, NROWS, D_, F_);
}

// round 8
// speedup vs baseline: 3.9048x; 1.1721x over previous
#include <cuda_runtime.h>
#include <cuda_fp16.h>
#include <math.h>
#include <stdint.h>

#define B_  8
#define S_  1024
#define D_  768
#define H_  12
#define DH_ 64
#define F_  3072
#define NROWS (B_*S_)   /* 8192 */

#define EPI_NONE 0
#define EPI_GELU 1
#define EPI_ADD  2

// ---------------------------------------------------------------------------
// Scratch (device globals — no allocation allowed)
// ---------------------------------------------------------------------------
__device__ __half g_h  [NROWS*D_];
__device__ __half g_q  [NROWS*D_];
__device__ __half g_k  [NROWS*D_];
__device__ __half g_v  [NROWS*D_];
__device__ __half g_ctx[NROWS*D_];
__device__ float  g_x2 [NROWS*D_];
__device__ __half g_ln2[NROWS*D_];
__device__ __half g_act[NROWS*F_];
// transposed fp16 weights
#define WT_Q  0
#define WT_K  (768*768)
#define WT_V  (2*768*768)
#define WT_O  (3*768*768)
#define WT_W1 (4*768*768)
#define WT_W2 (4*768*768 + 3072*768)
__device__ __half g_wt [4*768*768 + 2*3072*768];

// ---------------------------------------------------------------------------
// helpers
// ---------------------------------------------------------------------------
__device__ __forceinline__ float gelu_f(float x) {
    return 0.5f * x * (1.0f + erff(x * 0.70710678118654752f));
}

__device__ __forceinline__ void mma_f16(
    float c[4], const unsigned a[4], const unsigned b[2])
{
    asm volatile(
        "mma.sync.aligned.m16n8k16.row.col.f32.f16.f16.f32 "
        "{%0,%1,%2,%3}, {%4,%5,%6,%7}, {%8,%9}, {%0,%1,%2,%3};"
        : "+f"(c[0]), "+f"(c[1]), "+f"(c[2]), "+f"(c[3])
        : "r"(a[0]), "r"(a[1]), "r"(a[2]), "r"(a[3]),
          "r"(b[0]), "r"(b[1]));
}

__device__ __forceinline__ void cp_async16(unsigned smem_addr, const void* gptr) {
    asm volatile("cp.async.cg.shared.global [%0], [%1], 16;"
                 :: "r"(smem_addr), "l"(gptr));
}
__device__ __forceinline__ void cp_commit() {
    asm volatile("cp.async.commit_group;");
}
template<int N>
__device__ __forceinline__ void cp_wait() {
    asm volatile("cp.async.wait_group %0;" :: "n"(N));
}

// ---------------------------------------------------------------------------
// LayerNorm: fp32 in, fp16 out. One block per row, 256 threads.
// ---------------------------------------------------------------------------
__global__ __launch_bounds__(256) void ln_kernel(
    const float* __restrict__ x, const float* __restrict__ gam,
    const float* __restrict__ bet, __half* __restrict__ out)
{
    int row = blockIdx.x;
    int tid = threadIdx.x;
    const float* xr = x + (size_t)row * D_;
    float v0 = xr[tid], v1 = xr[tid + 256], v2 = xr[tid + 512];
    float s  = v0 + v1 + v2;
    float ss = v0*v0 + v1*v1 + v2*v2;
    #pragma unroll
    for (int o = 16; o > 0; o >>= 1) {
        s  += __shfl_xor_sync(0xffffffffu, s,  o);
        ss += __shfl_xor_sync(0xffffffffu, ss, o);
    }
    __shared__ float rs[8], rss[8];
    __shared__ float s_mu, s_inv;
    int w = tid >> 5, lane = tid & 31;
    if (lane == 0) { rs[w] = s; rss[w] = ss; }
    __syncthreads();
    if (tid == 0) {
        float ts = 0.f, tss = 0.f;
        #pragma unroll
        for (int i = 0; i < 8; i++) { ts += rs[i]; tss += rss[i]; }
        float mu  = ts * (1.0f / D_);
        float var = tss * (1.0f / D_) - mu * mu;
        s_mu = mu;
        s_inv = rsqrtf(var + 1e-6f);
    }
    __syncthreads();
    float mu = s_mu, inv = s_inv;
    __half* orow = out + (size_t)row * D_;
    orow[tid]       = __float2half_rn((v0 - mu) * inv * gam[tid]       + bet[tid]);
    orow[tid + 256] = __float2half_rn((v1 - mu) * inv * gam[tid + 256] + bet[tid + 256]);
    orow[tid + 512] = __float2half_rn((v2 - mu) * inv * gam[tid + 512] + bet[tid + 512]);
}

// ---------------------------------------------------------------------------
// Weight transpose + fp16 convert: out[c][r] = half(in[r][c]).
// ---------------------------------------------------------------------------
__global__ __launch_bounds__(256) void transpose_kernel(
    const float* __restrict__ in, __half* __restrict__ out, int R, int Ccols)
{
    __shared__ float t[32][33];
    int c0 = blockIdx.x * 32, r0 = blockIdx.y * 32;
    int x = threadIdx.x, y = threadIdx.y;
    #pragma unroll
    for (int i = 0; i < 32; i += 8)
        t[y + i][x] = in[(size_t)(r0 + y + i) * Ccols + c0 + x];
    __syncthreads();
    #pragma unroll
    for (int i = 0; i < 32; i += 8)
        out[(size_t)(c0 + y + i) * R + r0 + x] = __float2half_rn(t[x][y + i]);
}

// ---------------------------------------------------------------------------
// fp16 tensor-core GEMM, cp.async 3-stage pipeline (validated R6).
// ---------------------------------------------------------------------------
#define BK 32
#define LDAH 40
#define STG_H (128*LDAH)
#define NSTG 3
#define GEMM_SMEM_BYTES (NSTG*2*STG_H*2)   /* 61440 B */

template<int EPI>
__device__ __forceinline__ void h_gemm_body(
    const __half* __restrict__ A, const __half* __restrict__ Bt,
    const float* __restrict__ bias, const float* __restrict__ res,
    void* __restrict__ Cout, int M, int N, int K)
{
    extern __shared__ __half hsm[];
    __half* As = hsm;
    __half* Bs = hsm + NSTG * STG_H;

    int tid  = threadIdx.x;
    int bm = blockIdx.y * 128, bn = blockIdx.x * 128;
    int lane = tid & 31, warp = tid >> 5;
    int warp_m = warp >> 1;
    int warp_n = warp & 1;
    int g  = lane >> 2;
    int tg = lane & 3;

    unsigned a_su[NSTG], b_su[NSTG];
    #pragma unroll
    for (int s = 0; s < NSTG; s++) {
        a_su[s] = (unsigned)__cvta_generic_to_shared(As + s * STG_H);
        b_su[s] = (unsigned)__cvta_generic_to_shared(Bs + s * STG_H);
    }

    float acc[2][8][4];
    #pragma unroll
    for (int mt = 0; mt < 2; mt++)
        #pragma unroll
        for (int nt = 0; nt < 8; nt++)
            #pragma unroll
            for (int i = 0; i < 4; i++) acc[mt][nt][i] = 0.f;

    int nck = K / BK;

    auto issue = [&](int st, int ck) {
        int kb = ck * BK;
        #pragma unroll
        for (int p = 0; p < 2; p++) {
            int cid = tid + p * 256;
            int row = cid >> 2, c = cid & 3;
            unsigned off = (unsigned)((row * LDAH + c * 8) * 2);
            cp_async16(a_su[st] + off, A  + (size_t)(bm + row) * K + kb + c * 8);
            cp_async16(b_su[st] + off, Bt + (size_t)(bn + row) * K + kb + c * 8);
        }
        cp_commit();
    };

    issue(0, 0);
    issue(1, 1);

    for (int ck = 0; ck < nck; ck++) {
        int st = ck % 3;
        if (ck + 2 < nck) cp_wait<1>(); else cp_wait<0>();
        __syncthreads();
        if (ck + 2 < nck) issue((ck + 2) % 3, ck + 2);

        const __half* Ab = As + st * STG_H;
        const __half* Bb = Bs + st * STG_H;

        #pragma unroll
        for (int ks = 0; ks < 2; ks++) {
            int k0 = ks * 16;
            unsigned af[2][4], bf[8][2];
            #pragma unroll
            for (int mt = 0; mt < 2; mt++) {
                int mb = warp_m * 32 + mt * 16;
                af[mt][0] = *(const unsigned*)&Ab[(mb + g    ) * LDAH + k0 + 2*tg    ];
                af[mt][1] = *(const unsigned*)&Ab[(mb + g + 8) * LDAH + k0 + 2*tg    ];
                af[mt][2] = *(const unsigned*)&Ab[(mb + g    ) * LDAH + k0 + 2*tg + 8];
                af[mt][3] = *(const unsigned*)&Ab[(mb + g + 8) * LDAH + k0 + 2*tg + 8];
            }
            #pragma unroll
            for (int nt = 0; nt < 8; nt++) {
                int nb = warp_n * 64 + nt * 8;
                bf[nt][0] = *(const unsigned*)&Bb[(nb + g) * LDAH + k0 + 2*tg    ];
                bf[nt][1] = *(const unsigned*)&Bb[(nb + g) * LDAH + k0 + 2*tg + 8];
            }
            #pragma unroll
            for (int mt = 0; mt < 2; mt++)
                #pragma unroll
                for (int nt = 0; nt < 8; nt++)
                    mma_f16(acc[mt][nt], af[mt], bf[nt]);
        }
        __syncthreads();
    }

    #pragma unroll
    for (int mt = 0; mt < 2; mt++) {
        #pragma unroll
        for (int nt = 0; nt < 8; nt++) {
            int row0 = bm + warp_m * 32 + mt * 16 + g;
            int row1 = row0 + 8;
            int col  = bn + warp_n * 64 + nt * 8 + tg * 2;
            float2 bb = *(const float2*)&bias[col];
            float v0 = acc[mt][nt][0] + bb.x;
            float v1 = acc[mt][nt][1] + bb.y;
            float v2 = acc[mt][nt][2] + bb.x;
            float v3 = acc[mt][nt][3] + bb.y;
            if (EPI == EPI_GELU) {
                v0 = gelu_f(v0); v1 = gelu_f(v1);
                v2 = gelu_f(v2); v3 = gelu_f(v3);
            }
            if (EPI == EPI_ADD) {
                float* C = (float*)Cout;
                float2 r0 = *(const float2*)&res[(size_t)row0 * N + col];
                float2 r1 = *(const float2*)&res[(size_t)row1 * N + col];
                v0 += r0.x; v1 += r0.y; v2 += r1.x; v3 += r1.y;
                *(float2*)&C[(size_t)row0 * N + col] = make_float2(v0, v1);
                *(float2*)&C[(size_t)row1 * N + col] = make_float2(v2, v3);
            } else {
                __half* C = (__half*)Cout;
                *(__half2*)&C[(size_t)row0 * N + col] = __floats2half2_rn(v0, v1);
                *(__half2*)&C[(size_t)row1 * N + col] = __floats2half2_rn(v2, v3);
            }
        }
    }
}

template<int EPI>
__global__ __launch_bounds__(256, 2) void h_gemm_kernel(
    const __half* __restrict__ A, const __half* __restrict__ Bt,
    const float* __restrict__ bias, const float* __restrict__ res,
    void* __restrict__ Cout, int M, int N, int K)
{
    h_gemm_body<EPI>(A, Bt, bias, res, Cout, M, N, K);
}

__global__ __launch_bounds__(256, 2) void h_qkv_kernel(
    const __half* __restrict__ A, const __half* __restrict__ wt,
    const float* __restrict__ bq, const float* __restrict__ bk, const float* __restrict__ bv,
    __half* __restrict__ Cq, __half* __restrict__ Ck, __half* __restrict__ Cv)
{
    const __half* Bt  = wt + (size_t)blockIdx.z * (768 * 768);
    const float*  bia = (blockIdx.z == 0) ? bq : (blockIdx.z == 1) ? bk : bv;
    __half*       C   = (blockIdx.z == 0) ? Cq : (blockIdx.z == 1) ? Ck : Cv;
    h_gemm_body<EPI_NONE>(A, Bt, bia, nullptr, (void*)C, NROWS, D_, D_);
}

// ---------------------------------------------------------------------------
// Fused attention, fp16 m16n8k16 edition.
// Block = (b, h, 64 query rows). 8 warps: warp tile 16x32 (warp_m 0..3 x warp_n 0..1).
// smem: Qh[q][d] (pre-scaled), Kh[key][d], Vt[d][key] all fp16 stride 72;
//       P fp32 [q][key] for softmax; P16 fp16 [q][key] for P*V.
// Fragment maps identical to the validated fp16 GEMM.
// ---------------------------------------------------------------------------
#define LATT 72
struct AttnSmem {
    __half Qh [64][LATT];
    __half Kh [64][LATT];
    __half Vt [64][LATT];
    __half P16[64][LATT];
    float  P  [64][68];
    float m[64];
    float l[64];
    float corr[64];
    float red[4][64];
};

__global__ __launch_bounds__(256) void attn_kernel(
    const __half* __restrict__ q, const __half* __restrict__ k,
    const __half* __restrict__ v, __half* __restrict__ ctx)
{
    extern __shared__ char smem_raw[];
    AttnSmem* S = (AttnSmem*)smem_raw;
    int bb = blockIdx.z, hh = blockIdx.y;
    int q0 = blockIdx.x * 64;
    int tid = threadIdx.x;
    int lane = tid & 31, wid = tid >> 5;
    int g = lane >> 2, tg = lane & 3;
    int warp_m = wid >> 1, warp_n = wid & 1;
    int m0 = warp_m * 16;

    int lr = tid >> 2;              // load row (0..63)
    int ld = (tid & 3) * 16;        // load d base

    // load Q, pre-scale by 1/8 (exponent shift — fp16 exact)
    {
        const __half* gq = q + ((size_t)((bb*S_ + q0 + lr)*H_ + hh))*DH_ + ld;
        const __half2 sc = __half2half2(__float2half(0.125f));
        #pragma unroll
        for (int c = 0; c < 8; c++) {
            __half2 t = *(const __half2*)(gq + 2*c);
            *(__half2*)&S->Qh[lr][ld + 2*c] = __hmul2(t, sc);
        }
    }
    if (tid < 64) { S->m[tid] = -1e30f; S->l[tid] = 0.f; }

    float o[4][4];
    #pragma unroll
    for (int nt = 0; nt < 4; nt++)
        #pragma unroll
        for (int i = 0; i < 4; i++) o[nt][i] = 0.f;

    int srow = tid >> 2, part = tid & 3;   // softmax: 4 threads per row

    __syncthreads();

    for (int kt = 0; kt < 16; kt++) {
        int k0g = kt * 64;
        // ---- load K (natural, uint4) and Vt (transposed, scalar) ----
        {
            const __half* gk = k + ((size_t)((bb*S_ + k0g + lr)*H_ + hh))*DH_ + ld;
            const __half* gv = v + ((size_t)((bb*S_ + k0g + lr)*H_ + hh))*DH_ + ld;
            *(uint4*)&S->Kh[lr][ld]     = *(const uint4*)gk;
            *(uint4*)&S->Kh[lr][ld + 8] = *(const uint4*)(gk + 8);
            #pragma unroll
            for (int c = 0; c < 8; c++) {
                __half2 fv = *(const __half2*)(gv + 2*c);
                int d = ld + 2*c;
                S->Vt[d    ][lr] = __low2half(fv);
                S->Vt[d + 1][lr] = __high2half(fv);
            }
        }
        __syncthreads();

        // ---- QK^T -> P (fp32), 4 fp16 mma k-steps ----
        {
            float s[4][4];
            #pragma unroll
            for (int nt = 0; nt < 4; nt++)
                #pragma unroll
                for (int i = 0; i < 4; i++) s[nt][i] = 0.f;
            #pragma unroll
            for (int ks = 0; ks < 4; ks++) {
                int k0 = ks * 16;
                unsigned a[4];
                a[0] = *(const unsigned*)&S->Qh[m0 + g    ][k0 + 2*tg    ];
                a[1] = *(const unsigned*)&S->Qh[m0 + g + 8][k0 + 2*tg    ];
                a[2] = *(const unsigned*)&S->Qh[m0 + g    ][k0 + 2*tg + 8];
                a[3] = *(const unsigned*)&S->Qh[m0 + g + 8][k0 + 2*tg + 8];
                #pragma unroll
                for (int nt = 0; nt < 4; nt++) {
                    int n0 = warp_n * 32 + nt * 8;
                    unsigned b[2];
                    b[0] = *(const unsigned*)&S->Kh[n0 + g][k0 + 2*tg    ];
                    b[1] = *(const unsigned*)&S->Kh[n0 + g][k0 + 2*tg + 8];
                    mma_f16(s[nt], a, b);
                }
            }
            #pragma unroll
            for (int nt = 0; nt < 4; nt++) {
                int n0 = warp_n * 32 + nt * 8;
                *(float2*)&S->P[m0 + g    ][n0 + tg*2] = make_float2(s[nt][0], s[nt][1]);
                *(float2*)&S->P[m0 + g + 8][n0 + tg*2] = make_float2(s[nt][2], s[nt][3]);
            }
        }
        __syncthreads();

        // ---- online softmax on P rows; emit fp16 probs into P16 ----
        float lmax = -1e30f;
        #pragma unroll
        for (int j = 0; j < 16; j++)
            lmax = fmaxf(lmax, S->P[srow][part*16 + j]);
        S->red[part][srow] = lmax;
        __syncthreads();
        if (tid < 64) {
            float mo = S->m[tid];
            float mn = fmaxf(fmaxf(S->red[0][tid], S->red[1][tid]),
                             fmaxf(S->red[2][tid], S->red[3][tid]));
            mn = fmaxf(mn, mo);
            S->corr[tid] = __expf(mo - mn);
            S->m[tid] = mn;
        }
        __syncthreads();
        {
            float mn = S->m[srow];
            float ls = 0.f;
            #pragma unroll
            for (int j = 0; j < 16; j++) {
                float p = __expf(S->P[srow][part*16 + j] - mn);
                S->P16[srow][part*16 + j] = __float2half_rn(p);
                ls += p;
            }
            S->red[part][srow] = ls;
        }
        __syncthreads();
        if (tid < 64)
            S->l[tid] = S->l[tid] * S->corr[tid]
                      + S->red[0][tid] + S->red[1][tid]
                      + S->red[2][tid] + S->red[3][tid];

        // ---- P*V accumulate with correction, 4 fp16 mma k-steps ----
        {
            float cr0 = S->corr[m0 + g], cr1 = S->corr[m0 + g + 8];
            #pragma unroll
            for (int nt = 0; nt < 4; nt++) {
                o[nt][0] *= cr0; o[nt][1] *= cr0;
                o[nt][2] *= cr1; o[nt][3] *= cr1;
            }
            #pragma unroll
            for (int ks = 0; ks < 4; ks++) {
                int k0 = ks * 16;
                unsigned a[4];
                a[0] = *(const unsigned*)&S->P16[m0 + g    ][k0 + 2*tg    ];
                a[1] = *(const unsigned*)&S->P16[m0 + g + 8][k0 + 2*tg    ];
                a[2] = *(const unsigned*)&S->P16[m0 + g    ][k0 + 2*tg + 8];
                a[3] = *(const unsigned*)&S->P16[m0 + g + 8][k0 + 2*tg + 8];
                #pragma unroll
                for (int nt = 0; nt < 4; nt++) {
                    int n0 = warp_n * 32 + nt * 8;
                    unsigned b[2];
                    b[0] = *(const unsigned*)&S->Vt[n0 + g][k0 + 2*tg    ];
                    b[1] = *(const unsigned*)&S->Vt[n0 + g][k0 + 2*tg + 8];
                    mma_f16(o[nt], a, b);
                }
            }
        }
        __syncthreads();
    }

    // ---- finalize: divide by l, write fp16 ctx ----
    float inv0 = 1.0f / S->l[m0 + g];
    float inv1 = 1.0f / S->l[m0 + g + 8];
    int row0 = bb*S_ + q0 + m0 + g;
    int row1 = row0 + 8;
    #pragma unroll
    for (int nt = 0; nt < 4; nt++) {
        int d = warp_n * 32 + nt * 8 + tg * 2;
        *(__half2*)&ctx[((size_t)(row0*H_ + hh))*DH_ + d] =
            __floats2half2_rn(o[nt][0] * inv0, o[nt][1] * inv0);
        *(__half2*)&ctx[((size_t)(row1*H_ + hh))*DH_ + d] =
            __floats2half2_rn(o[nt][2] * inv1, o[nt][3] * inv1);
    }
}

// ---------------------------------------------------------------------------
// Launcher
// ---------------------------------------------------------------------------
extern "C" void kernel_launch(void* const* d_in, const int* in_sizes, int n_in,
                              void* d_out, int out_size)
{
    const float* x   = (const float*)d_in[0];
    const float* Wq  = (const float*)d_in[1];
    const float* bq  = (const float*)d_in[2];
    const float* Wk  = (const float*)d_in[3];
    const float* bk  = (const float*)d_in[4];
    const float* Wv  = (const float*)d_in[5];
    const float* bv  = (const float*)d_in[6];
    const float* Wo  = (const float*)d_in[7];
    const float* bo  = (const float*)d_in[8];
    const float* g1  = (const float*)d_in[9];
    const float* be1 = (const float*)d_in[10];
    const float* g2  = (const float*)d_in[11];
    const float* be2 = (const float*)d_in[12];
    const float* W1  = (const float*)d_in[13];
    const float* b1  = (const float*)d_in[14];
    const float* W2  = (const float*)d_in[15];
    const float* b2  = (const float*)d_in[16];
    float* out = (float*)d_out;

    __half *h, *q, *k, *v, *ctx, *ln2, *act, *wt;
    float *x2;
    cudaGetSymbolAddress((void**)&h,   g_h);
    cudaGetSymbolAddress((void**)&q,   g_q);
    cudaGetSymbolAddress((void**)&k,   g_k);
    cudaGetSymbolAddress((void**)&v,   g_v);
    cudaGetSymbolAddress((void**)&ctx, g_ctx);
    cudaGetSymbolAddress((void**)&x2,  g_x2);
    cudaGetSymbolAddress((void**)&ln2, g_ln2);
    cudaGetSymbolAddress((void**)&act, g_act);
    cudaGetSymbolAddress((void**)&wt,  g_wt);

    cudaFuncSetAttribute(h_gemm_kernel<EPI_ADD>,
                         cudaFuncAttributeMaxDynamicSharedMemorySize, GEMM_SMEM_BYTES);
    cudaFuncSetAttribute(h_gemm_kernel<EPI_GELU>,
                         cudaFuncAttributeMaxDynamicSharedMemorySize, GEMM_SMEM_BYTES);
    cudaFuncSetAttribute(h_qkv_kernel,
                         cudaFuncAttributeMaxDynamicSharedMemorySize, GEMM_SMEM_BYTES);
    cudaFuncSetAttribute(attn_kernel,
                         cudaFuncAttributeMaxDynamicSharedMemorySize,
                         (int)sizeof(AttnSmem));

    dim3 tb(32, 8);
    // 0. weight transpose + fp16 convert
    transpose_kernel<<<dim3(24, 24), tb>>>(Wq, wt + WT_Q,  768, 768);
    transpose_kernel<<<dim3(24, 24), tb>>>(Wk, wt + WT_K,  768, 768);
    transpose_kernel<<<dim3(24, 24), tb>>>(Wv, wt + WT_V,  768, 768);
    transpose_kernel<<<dim3(24, 24), tb>>>(Wo, wt + WT_O,  768, 768);
    transpose_kernel<<<dim3(96, 24), tb>>>(W1, wt + WT_W1, 768, 3072);
    transpose_kernel<<<dim3(24, 96), tb>>>(W2, wt + WT_W2, 3072, 768);

    // 1. pre-LN -> fp16 h
    ln_kernel<<<NROWS, 256>>>(x, g1, be1, h);
    // 2. QKV (fp16 mma, batched) -> fp16 q,k,v
    dim3 gqkv(D_/128, NROWS/128, 3);
    h_qkv_kernel<<<gqkv, 256, GEMM_SMEM_BYTES>>>(h, wt, bq, bk, bv, q, k, v);
    // 3. fused attention (fp16 mma) -> fp16 ctx
    dim3 gat(S_/64, H_, B_);
    attn_kernel<<<gat, 256, (int)sizeof(AttnSmem)>>>(q, k, v, ctx);
    // 4. Wo projection + residual -> fp32 x2
    dim3 go(D_/128, NROWS/128);
    h_gemm_kernel<EPI_ADD><<<go, 256, GEMM_SMEM_BYTES>>>(ctx, wt + WT_O, bo, x, (void*)x2, NROWS, D_, D_);
    // 5. LN2 -> fp16 ln2
    ln_kernel<<<NROWS, 256>>>(x2, g2, be2, ln2);
    // 6. MLP up + exact GELU -> fp16 act
    dim3 gup(F_/128, NROWS/128);
    h_gemm_kernel<EPI_GELU><<<gup, 256, GEMM_SMEM_BYTES>>>(ln2, wt + WT_W1, b1, nullptr, (void*)act, NROWS, F_, D_);
    // 7. MLP down + bias + residual -> fp32 out
    dim3 gdn(D_/128, NROWS/128);
    h_gemm_kernel<EPI_ADD><<<gdn, 256, GEMM_SMEM_BYTES>>>(act, wt + WT_W2, b2, x2, (void*)out, NROWS, D_, F_);
}

// round 9
// speedup vs baseline: 4.0075x; 1.0263x over previous
#include <cuda_runtime.h>
#include <cuda_fp16.h>
#include <math.h>
#include <stdint.h>

#define B_  8
#define S_  1024
#define D_  768
#define H_  12
#define DH_ 64
#define F_  3072
#define NROWS (B_*S_)   /* 8192 */

#define EPI_NONE 0
#define EPI_GELU 1
#define EPI_ADD  2

// ---------------------------------------------------------------------------
// Scratch (device globals — no allocation allowed)
// ---------------------------------------------------------------------------
__device__ __half g_h  [NROWS*D_];
__device__ __half g_q  [NROWS*D_];
__device__ __half g_k  [NROWS*D_];
__device__ __half g_v  [NROWS*D_];
__device__ __half g_ctx[NROWS*D_];
__device__ float  g_x2 [NROWS*D_];
__device__ __half g_ln2[NROWS*D_];
__device__ __half g_act[NROWS*F_];
// transposed fp16 weights
#define WT_Q  0
#define WT_K  (768*768)
#define WT_V  (2*768*768)
#define WT_O  (3*768*768)
#define WT_W1 (4*768*768)
#define WT_W2 (4*768*768 + 3072*768)
__device__ __half g_wt [4*768*768 + 2*3072*768];

// ---------------------------------------------------------------------------
// helpers
// ---------------------------------------------------------------------------
__device__ __forceinline__ float gelu_f(float x) {
    return 0.5f * x * (1.0f + erff(x * 0.70710678118654752f));
}

__device__ __forceinline__ void mma_f16(
    float c[4], const unsigned a[4], const unsigned b[2])
{
    asm volatile(
        "mma.sync.aligned.m16n8k16.row.col.f32.f16.f16.f32 "
        "{%0,%1,%2,%3}, {%4,%5,%6,%7}, {%8,%9}, {%0,%1,%2,%3};"
        : "+f"(c[0]), "+f"(c[1]), "+f"(c[2]), "+f"(c[3])
        : "r"(a[0]), "r"(a[1]), "r"(a[2]), "r"(a[3]),
          "r"(b[0]), "r"(b[1]));
}

__device__ __forceinline__ void ldsm_x4(
    unsigned& r0, unsigned& r1, unsigned& r2, unsigned& r3, unsigned addr)
{
    asm volatile("ldmatrix.sync.aligned.m8n8.x4.shared.b16 {%0,%1,%2,%3}, [%4];"
                 : "=r"(r0), "=r"(r1), "=r"(r2), "=r"(r3) : "r"(addr));
}

__device__ __forceinline__ void cp_async16(unsigned smem_addr, const void* gptr) {
    asm volatile("cp.async.cg.shared.global [%0], [%1], 16;"
                 :: "r"(smem_addr), "l"(gptr));
}
__device__ __forceinline__ void cp_commit() {
    asm volatile("cp.async.commit_group;");
}
template<int N>
__device__ __forceinline__ void cp_wait() {
    asm volatile("cp.async.wait_group %0;" :: "n"(N));
}

// ---------------------------------------------------------------------------
// LayerNorm: fp32 in, fp16 out. One block per row, 256 threads.
// ---------------------------------------------------------------------------
__global__ __launch_bounds__(256) void ln_kernel(
    const float* __restrict__ x, const float* __restrict__ gam,
    const float* __restrict__ bet, __half* __restrict__ out)
{
    int row = blockIdx.x;
    int tid = threadIdx.x;
    const float* xr = x + (size_t)row * D_;
    float v0 = xr[tid], v1 = xr[tid + 256], v2 = xr[tid + 512];
    float s  = v0 + v1 + v2;
    float ss = v0*v0 + v1*v1 + v2*v2;
    #pragma unroll
    for (int o = 16; o > 0; o >>= 1) {
        s  += __shfl_xor_sync(0xffffffffu, s,  o);
        ss += __shfl_xor_sync(0xffffffffu, ss, o);
    }
    __shared__ float rs[8], rss[8];
    __shared__ float s_mu, s_inv;
    int w = tid >> 5, lane = tid & 31;
    if (lane == 0) { rs[w] = s; rss[w] = ss; }
    __syncthreads();
    if (tid == 0) {
        float ts = 0.f, tss = 0.f;
        #pragma unroll
        for (int i = 0; i < 8; i++) { ts += rs[i]; tss += rss[i]; }
        float mu  = ts * (1.0f / D_);
        float var = tss * (1.0f / D_) - mu * mu;
        s_mu = mu;
        s_inv = rsqrtf(var + 1e-6f);
    }
    __syncthreads();
    float mu = s_mu, inv = s_inv;
    __half* orow = out + (size_t)row * D_;
    orow[tid]       = __float2half_rn((v0 - mu) * inv * gam[tid]       + bet[tid]);
    orow[tid + 256] = __float2half_rn((v1 - mu) * inv * gam[tid + 256] + bet[tid + 256]);
    orow[tid + 512] = __float2half_rn((v2 - mu) * inv * gam[tid + 512] + bet[tid + 512]);
}

// ---------------------------------------------------------------------------
// Weight transpose + fp16 convert: out[c][r] = half(in[r][c]).
// ---------------------------------------------------------------------------
__global__ __launch_bounds__(256) void transpose_kernel(
    const float* __restrict__ in, __half* __restrict__ out, int R, int Ccols)
{
    __shared__ float t[32][33];
    int c0 = blockIdx.x * 32, r0 = blockIdx.y * 32;
    int x = threadIdx.x, y = threadIdx.y;
    #pragma unroll
    for (int i = 0; i < 32; i += 8)
        t[y + i][x] = in[(size_t)(r0 + y + i) * Ccols + c0 + x];
    __syncthreads();
    #pragma unroll
    for (int i = 0; i < 32; i += 8)
        out[(size_t)(c0 + y + i) * R + r0 + x] = __float2half_rn(t[x][y + i]);
}

// ---------------------------------------------------------------------------
// fp16 tensor-core GEMM: 128x128 tile, BK=32, 256 threads, warp tile 32x64,
// mma.sync.m16n8k16 + ldmatrix.x4 fragment loads, 4-stage cp.async pipeline.
// ---------------------------------------------------------------------------
#define BK 32
#define LDAH 40
#define STG_H (128*LDAH)
#define NSTG 4
#define GEMM_SMEM_BYTES (NSTG*2*STG_H*2)   /* 81920 B */

template<int EPI>
__device__ __forceinline__ void h_gemm_body(
    const __half* __restrict__ A, const __half* __restrict__ Bt,
    const float* __restrict__ bias, const float* __restrict__ res,
    void* __restrict__ Cout, int M, int N, int K)
{
    extern __shared__ __half hsm[];
    __half* As = hsm;
    __half* Bs = hsm + NSTG * STG_H;

    int tid  = threadIdx.x;
    int bm = blockIdx.y * 128, bn = blockIdx.x * 128;
    int lane = tid & 31, warp = tid >> 5;
    int warp_m = warp >> 1;
    int warp_n = warp & 1;
    int g  = lane >> 2;
    int tg = lane & 3;

    unsigned a_su[NSTG], b_su[NSTG];
    #pragma unroll
    for (int s = 0; s < NSTG; s++) {
        a_su[s] = (unsigned)__cvta_generic_to_shared(As + s * STG_H);
        b_su[s] = (unsigned)__cvta_generic_to_shared(Bs + s * STG_H);
    }

    // ldmatrix lane->address maps (halves)
    int arow_off = (lane & 7) + ((lane >> 3) & 1) * 8;
    int ak_off   = ((lane >> 4) & 1) * 8;
    int brow_off = (lane & 7) + ((lane >> 4) & 1) * 8;
    int bk_off   = ((lane >> 3) & 1) * 8;

    unsigned a_lm[2], b_lm[4];
    #pragma unroll
    for (int mt = 0; mt < 2; mt++)
        a_lm[mt] = (unsigned)(((warp_m * 32 + mt * 16 + arow_off) * LDAH + ak_off) * 2);
    #pragma unroll
    for (int p = 0; p < 4; p++)
        b_lm[p] = (unsigned)(((warp_n * 64 + p * 16 + brow_off) * LDAH + bk_off) * 2);

    float acc[2][8][4];
    #pragma unroll
    for (int mt = 0; mt < 2; mt++)
        #pragma unroll
        for (int nt = 0; nt < 8; nt++)
            #pragma unroll
            for (int i = 0; i < 4; i++) acc[mt][nt][i] = 0.f;

    int nck = K / BK;

    auto issue = [&](int st, int ck) {
        int kb = ck * BK;
        #pragma unroll
        for (int p = 0; p < 2; p++) {
            int cid = tid + p * 256;
            int row = cid >> 2, c = cid & 3;
            unsigned off = (unsigned)((row * LDAH + c * 8) * 2);
            cp_async16(a_su[st] + off, A  + (size_t)(bm + row) * K + kb + c * 8);
            cp_async16(b_su[st] + off, Bt + (size_t)(bn + row) * K + kb + c * 8);
        }
        cp_commit();
    };

    issue(0, 0);
    if (nck > 1) issue(1, 1);
    if (nck > 2) issue(2, 2);

    for (int ck = 0; ck < nck; ck++) {
        int st = ck & 3;
        int ahead = nck - 1 - ck;
        if (ahead >= 2)      cp_wait<2>();
        else if (ahead == 1) cp_wait<1>();
        else                 cp_wait<0>();
        __syncthreads();
        if (ck + 3 < nck) issue((ck + 3) & 3, ck + 3);

        unsigned abase = a_su[st], bbase = b_su[st];

        #pragma unroll
        for (int ks = 0; ks < 2; ks++) {
            unsigned kadd = (unsigned)(ks * 16 * 2);
            unsigned af[2][4], bf[8][2];
            #pragma unroll
            for (int mt = 0; mt < 2; mt++)
                ldsm_x4(af[mt][0], af[mt][1], af[mt][2], af[mt][3],
                        abase + a_lm[mt] + kadd);
            #pragma unroll
            for (int p = 0; p < 4; p++)
                ldsm_x4(bf[2*p][0], bf[2*p][1], bf[2*p+1][0], bf[2*p+1][1],
                        bbase + b_lm[p] + kadd);
            #pragma unroll
            for (int mt = 0; mt < 2; mt++)
                #pragma unroll
                for (int nt = 0; nt < 8; nt++)
                    mma_f16(acc[mt][nt], af[mt], bf[nt]);
        }
    }
    __syncthreads();

    #pragma unroll
    for (int mt = 0; mt < 2; mt++) {
        #pragma unroll
        for (int nt = 0; nt < 8; nt++) {
            int row0 = bm + warp_m * 32 + mt * 16 + g;
            int row1 = row0 + 8;
            int col  = bn + warp_n * 64 + nt * 8 + tg * 2;
            float2 bb = *(const float2*)&bias[col];
            float v0 = acc[mt][nt][0] + bb.x;
            float v1 = acc[mt][nt][1] + bb.y;
            float v2 = acc[mt][nt][2] + bb.x;
            float v3 = acc[mt][nt][3] + bb.y;
            if (EPI == EPI_GELU) {
                v0 = gelu_f(v0); v1 = gelu_f(v1);
                v2 = gelu_f(v2); v3 = gelu_f(v3);
            }
            if (EPI == EPI_ADD) {
                float* C = (float*)Cout;
                float2 r0 = *(const float2*)&res[(size_t)row0 * N + col];
                float2 r1 = *(const float2*)&res[(size_t)row1 * N + col];
                v0 += r0.x; v1 += r0.y; v2 += r1.x; v3 += r1.y;
                *(float2*)&C[(size_t)row0 * N + col] = make_float2(v0, v1);
                *(float2*)&C[(size_t)row1 * N + col] = make_float2(v2, v3);
            } else {
                __half* C = (__half*)Cout;
                *(__half2*)&C[(size_t)row0 * N + col] = __floats2half2_rn(v0, v1);
                *(__half2*)&C[(size_t)row1 * N + col] = __floats2half2_rn(v2, v3);
            }
        }
    }
}

template<int EPI>
__global__ __launch_bounds__(256, 2) void h_gemm_kernel(
    const __half* __restrict__ A, const __half* __restrict__ Bt,
    const float* __restrict__ bias, const float* __restrict__ res,
    void* __restrict__ Cout, int M, int N, int K)
{
    h_gemm_body<EPI>(A, Bt, bias, res, Cout, M, N, K);
}

__global__ __launch_bounds__(256, 2) void h_qkv_kernel(
    const __half* __restrict__ A, const __half* __restrict__ wt,
    const float* __restrict__ bq, const float* __restrict__ bk, const float* __restrict__ bv,
    __half* __restrict__ Cq, __half* __restrict__ Ck, __half* __restrict__ Cv)
{
    const __half* Bt  = wt + (size_t)blockIdx.z * (768 * 768);
    const float*  bia = (blockIdx.z == 0) ? bq : (blockIdx.z == 1) ? bk : bv;
    __half*       C   = (blockIdx.z == 0) ? Cq : (blockIdx.z == 1) ? Ck : Cv;
    h_gemm_body<EPI_NONE>(A, Bt, bia, nullptr, (void*)C, NROWS, D_, D_);
}

// ---------------------------------------------------------------------------
// Fused attention, fp16 m16n8k16 (validated R7).
// ---------------------------------------------------------------------------
#define LATT 72
struct AttnSmem {
    __half Qh [64][LATT];
    __half Kh [64][LATT];
    __half Vt [64][LATT];
    __half P16[64][LATT];
    float  P  [64][68];
    float m[64];
    float l[64];
    float corr[64];
    float red[4][64];
};

__global__ __launch_bounds__(256) void attn_kernel(
    const __half* __restrict__ q, const __half* __restrict__ k,
    const __half* __restrict__ v, __half* __restrict__ ctx)
{
    extern __shared__ char smem_raw[];
    AttnSmem* S = (AttnSmem*)smem_raw;
    int bb = blockIdx.z, hh = blockIdx.y;
    int q0 = blockIdx.x * 64;
    int tid = threadIdx.x;
    int lane = tid & 31, wid = tid >> 5;
    int g = lane >> 2, tg = lane & 3;
    int warp_m = wid >> 1, warp_n = wid & 1;
    int m0 = warp_m * 16;

    int lr = tid >> 2;
    int ld = (tid & 3) * 16;

    {
        const __half* gq = q + ((size_t)((bb*S_ + q0 + lr)*H_ + hh))*DH_ + ld;
        const __half2 sc = __half2half2(__float2half(0.125f));
        #pragma unroll
        for (int c = 0; c < 8; c++) {
            __half2 t = *(const __half2*)(gq + 2*c);
            *(__half2*)&S->Qh[lr][ld + 2*c] = __hmul2(t, sc);
        }
    }
    if (tid < 64) { S->m[tid] = -1e30f; S->l[tid] = 0.f; }

    float o[4][4];
    #pragma unroll
    for (int nt = 0; nt < 4; nt++)
        #pragma unroll
        for (int i = 0; i < 4; i++) o[nt][i] = 0.f;

    int srow = tid >> 2, part = tid & 3;

    __syncthreads();

    for (int kt = 0; kt < 16; kt++) {
        int k0g = kt * 64;
        {
            const __half* gk = k + ((size_t)((bb*S_ + k0g + lr)*H_ + hh))*DH_ + ld;
            const __half* gv = v + ((size_t)((bb*S_ + k0g + lr)*H_ + hh))*DH_ + ld;
            *(uint4*)&S->Kh[lr][ld]     = *(const uint4*)gk;
            *(uint4*)&S->Kh[lr][ld + 8] = *(const uint4*)(gk + 8);
            #pragma unroll
            for (int c = 0; c < 8; c++) {
                __half2 fv = *(const __half2*)(gv + 2*c);
                int d = ld + 2*c;
                S->Vt[d    ][lr] = __low2half(fv);
                S->Vt[d + 1][lr] = __high2half(fv);
            }
        }
        __syncthreads();

        {
            float s[4][4];
            #pragma unroll
            for (int nt = 0; nt < 4; nt++)
                #pragma unroll
                for (int i = 0; i < 4; i++) s[nt][i] = 0.f;
            #pragma unroll
            for (int ks = 0; ks < 4; ks++) {
                int k0 = ks * 16;
                unsigned a[4];
                a[0] = *(const unsigned*)&S->Qh[m0 + g    ][k0 + 2*tg    ];
                a[1] = *(const unsigned*)&S->Qh[m0 + g + 8][k0 + 2*tg    ];
                a[2] = *(const unsigned*)&S->Qh[m0 + g    ][k0 + 2*tg + 8];
                a[3] = *(const unsigned*)&S->Qh[m0 + g + 8][k0 + 2*tg + 8];
                #pragma unroll
                for (int nt = 0; nt < 4; nt++) {
                    int n0 = warp_n * 32 + nt * 8;
                    unsigned b[2];
                    b[0] = *(const unsigned*)&S->Kh[n0 + g][k0 + 2*tg    ];
                    b[1] = *(const unsigned*)&S->Kh[n0 + g][k0 + 2*tg + 8];
                    mma_f16(s[nt], a, b);
                }
            }
            #pragma unroll
            for (int nt = 0; nt < 4; nt++) {
                int n0 = warp_n * 32 + nt * 8;
                *(float2*)&S->P[m0 + g    ][n0 + tg*2] = make_float2(s[nt][0], s[nt][1]);
                *(float2*)&S->P[m0 + g + 8][n0 + tg*2] = make_float2(s[nt][2], s[nt][3]);
            }
        }
        __syncthreads();

        float lmax = -1e30f;
        #pragma unroll
        for (int j = 0; j < 16; j++)
            lmax = fmaxf(lmax, S->P[srow][part*16 + j]);
        S->red[part][srow] = lmax;
        __syncthreads();
        if (tid < 64) {
            float mo = S->m[tid];
            float mn = fmaxf(fmaxf(S->red[0][tid], S->red[1][tid]),
                             fmaxf(S->red[2][tid], S->red[3][tid]));
            mn = fmaxf(mn, mo);
            S->corr[tid] = __expf(mo - mn);
            S->m[tid] = mn;
        }
        __syncthreads();
        {
            float mn = S->m[srow];
            float ls = 0.f;
            #pragma unroll
            for (int j = 0; j < 16; j++) {
                float p = __expf(S->P[srow][part*16 + j] - mn);
                S->P16[srow][part*16 + j] = __float2half_rn(p);
                ls += p;
            }
            S->red[part][srow] = ls;
        }
        __syncthreads();
        if (tid < 64)
            S->l[tid] = S->l[tid] * S->corr[tid]
                      + S->red[0][tid] + S->red[1][tid]
                      + S->red[2][tid] + S->red[3][tid];

        {
            float cr0 = S->corr[m0 + g], cr1 = S->corr[m0 + g + 8];
            #pragma unroll
            for (int nt = 0; nt < 4; nt++) {
                o[nt][0] *= cr0; o[nt][1] *= cr0;
                o[nt][2] *= cr1; o[nt][3] *= cr1;
            }
            #pragma unroll
            for (int ks = 0; ks < 4; ks++) {
                int k0 = ks * 16;
                unsigned a[4];
                a[0] = *(const unsigned*)&S->P16[m0 + g    ][k0 + 2*tg    ];
                a[1] = *(const unsigned*)&S->P16[m0 + g + 8][k0 + 2*tg    ];
                a[2] = *(const unsigned*)&S->P16[m0 + g    ][k0 + 2*tg + 8];
                a[3] = *(const unsigned*)&S->P16[m0 + g + 8][k0 + 2*tg + 8];
                #pragma unroll
                for (int nt = 0; nt < 4; nt++) {
                    int n0 = warp_n * 32 + nt * 8;
                    unsigned b[2];
                    b[0] = *(const unsigned*)&S->Vt[n0 + g][k0 + 2*tg    ];
                    b[1] = *(const unsigned*)&S->Vt[n0 + g][k0 + 2*tg + 8];
                    mma_f16(o[nt], a, b);
                }
            }
        }
        __syncthreads();
    }

    float inv0 = 1.0f / S->l[m0 + g];
    float inv1 = 1.0f / S->l[m0 + g + 8];
    int row0 = bb*S_ + q0 + m0 + g;
    int row1 = row0 + 8;
    #pragma unroll
    for (int nt = 0; nt < 4; nt++) {
        int d = warp_n * 32 + nt * 8 + tg * 2;
        *(__half2*)&ctx[((size_t)(row0*H_ + hh))*DH_ + d] =
            __floats2half2_rn(o[nt][0] * inv0, o[nt][1] * inv0);
        *(__half2*)&ctx[((size_t)(row1*H_ + hh))*DH_ + d] =
            __floats2half2_rn(o[nt][2] * inv1, o[nt][3] * inv1);
    }
}

// ---------------------------------------------------------------------------
// Launcher
// ---------------------------------------------------------------------------
extern "C" void kernel_launch(void* const* d_in, const int* in_sizes, int n_in,
                              void* d_out, int out_size)
{
    const float* x   = (const float*)d_in[0];
    const float* Wq  = (const float*)d_in[1];
    const float* bq  = (const float*)d_in[2];
    const float* Wk  = (const float*)d_in[3];
    const float* bk  = (const float*)d_in[4];
    const float* Wv  = (const float*)d_in[5];
    const float* bv  = (const float*)d_in[6];
    const float* Wo  = (const float*)d_in[7];
    const float* bo  = (const float*)d_in[8];
    const float* g1  = (const float*)d_in[9];
    const float* be1 = (const float*)d_in[10];
    const float* g2  = (const float*)d_in[11];
    const float* be2 = (const float*)d_in[12];
    const float* W1  = (const float*)d_in[13];
    const float* b1  = (const float*)d_in[14];
    const float* W2  = (const float*)d_in[15];
    const float* b2  = (const float*)d_in[16];
    float* out = (float*)d_out;

    __half *h, *q, *k, *v, *ctx, *ln2, *act, *wt;
    float *x2;
    cudaGetSymbolAddress((void**)&h,   g_h);
    cudaGetSymbolAddress((void**)&q,   g_q);
    cudaGetSymbolAddress((void**)&k,   g_k);
    cudaGetSymbolAddress((void**)&v,   g_v);
    cudaGetSymbolAddress((void**)&ctx, g_ctx);
    cudaGetSymbolAddress((void**)&x2,  g_x2);
    cudaGetSymbolAddress((void**)&ln2, g_ln2);
    cudaGetSymbolAddress((void**)&act, g_act);
    cudaGetSymbolAddress((void**)&wt,  g_wt);

    cudaFuncSetAttribute(h_gemm_kernel<EPI_ADD>,
                         cudaFuncAttributeMaxDynamicSharedMemorySize, GEMM_SMEM_BYTES);
    cudaFuncSetAttribute(h_gemm_kernel<EPI_GELU>,
                         cudaFuncAttributeMaxDynamicSharedMemorySize, GEMM_SMEM_BYTES);
    cudaFuncSetAttribute(h_qkv_kernel,
                         cudaFuncAttributeMaxDynamicSharedMemorySize, GEMM_SMEM_BYTES);
    cudaFuncSetAttribute(attn_kernel,
                         cudaFuncAttributeMaxDynamicSharedMemorySize,
                         (int)sizeof(AttnSmem));

    dim3 tb(32, 8);
    // 0. weight transpose + fp16 convert
    transpose_kernel<<<dim3(24, 24), tb>>>(Wq, wt + WT_Q,  768, 768);
    transpose_kernel<<<dim3(24, 24), tb>>>(Wk, wt + WT_K,  768, 768);
    transpose_kernel<<<dim3(24, 24), tb>>>(Wv, wt + WT_V,  768, 768);
    transpose_kernel<<<dim3(24, 24), tb>>>(Wo, wt + WT_O,  768, 768);
    transpose_kernel<<<dim3(96, 24), tb>>>(W1, wt + WT_W1, 768, 3072);
    transpose_kernel<<<dim3(24, 96), tb>>>(W2, wt + WT_W2, 3072, 768);

    // 1. pre-LN -> fp16 h
    ln_kernel<<<NROWS, 256>>>(x, g1, be1, h);
    // 2. QKV (fp16 mma + ldmatrix, batched) -> fp16 q,k,v
    dim3 gqkv(D_/128, NROWS/128, 3);
    h_qkv_kernel<<<gqkv, 256, GEMM_SMEM_BYTES>>>(h, wt, bq, bk, bv, q, k, v);
    // 3. fused attention (fp16 mma) -> fp16 ctx
    dim3 gat(S_/64, H_, B_);
    attn_kernel<<<gat, 256, (int)sizeof(AttnSmem)>>>(q, k, v, ctx);
    // 4. Wo projection + residual -> fp32 x2
    dim3 go(D_/128, NROWS/128);
    h_gemm_kernel<EPI_ADD><<<go, 256, GEMM_SMEM_BYTES>>>(ctx, wt + WT_O, bo, x, (void*)x2, NROWS, D_, D_);
    // 5. LN2 -> fp16 ln2
    ln_kernel<<<NROWS, 256>>>(x2, g2, be2, ln2);
    // 6. MLP up + exact GELU -> fp16 act
    dim3 gup(F_/128, NROWS/128);
    h_gemm_kernel<EPI_GELU><<<gup, 256, GEMM_SMEM_BYTES>>>(ln2, wt + WT_W1, b1, nullptr, (void*)act, NROWS, F_, D_);
    // 7. MLP down + bias + residual -> fp32 out
    dim3 gdn(D_/128, NROWS/128);
    h_gemm_kernel<EPI_ADD><<<gdn, 256, GEMM_SMEM_BYTES>>>(act, wt + WT_W2, b2, x2, (void*)out, NROWS, D_, F_);
}

// round 10
// speedup vs baseline: 5.6729x; 1.4156x over previous
#include <cuda_runtime.h>
#include <cuda_fp16.h>
#include <math.h>
#include <stdint.h>

#define B_  8
#define S_  1024
#define D_  768
#define H_  12
#define DH_ 64
#define F_  3072
#define NROWS (B_*S_)   /* 8192 */

#define EPI_NONE 0
#define EPI_GELU 1
#define EPI_ADD  2

// ---------------------------------------------------------------------------
// Scratch (device globals — no allocation allowed)
// ---------------------------------------------------------------------------
__device__ __half g_h  [NROWS*D_];
__device__ __half g_q  [NROWS*D_];
__device__ __half g_k  [NROWS*D_];
__device__ __half g_v  [NROWS*D_];
__device__ __half g_ctx[NROWS*D_];
__device__ float  g_x2 [NROWS*D_];
__device__ __half g_ln2[NROWS*D_];
__device__ __half g_act[NROWS*F_];
// transposed fp16 weights
#define WT_Q  0
#define WT_K  (768*768)
#define WT_V  (2*768*768)
#define WT_O  (3*768*768)
#define WT_W1 (4*768*768)
#define WT_W2 (4*768*768 + 3072*768)
__device__ __half g_wt [4*768*768 + 2*3072*768];

// ---------------------------------------------------------------------------
// helpers
// ---------------------------------------------------------------------------
__device__ __forceinline__ float gelu_f(float x) {
    return 0.5f * x * (1.0f + erff(x * 0.70710678118654752f));
}

__device__ __forceinline__ void mma_f16(
    float c[4], const unsigned a[4], const unsigned b[2])
{
    asm volatile(
        "mma.sync.aligned.m16n8k16.row.col.f32.f16.f16.f32 "
        "{%0,%1,%2,%3}, {%4,%5,%6,%7}, {%8,%9}, {%0,%1,%2,%3};"
        : "+f"(c[0]), "+f"(c[1]), "+f"(c[2]), "+f"(c[3])
        : "r"(a[0]), "r"(a[1]), "r"(a[2]), "r"(a[3]),
          "r"(b[0]), "r"(b[1]));
}

__device__ __forceinline__ void ldsm_x4(
    unsigned& r0, unsigned& r1, unsigned& r2, unsigned& r3, unsigned addr)
{
    asm volatile("ldmatrix.sync.aligned.m8n8.x4.shared.b16 {%0,%1,%2,%3}, [%4];"
                 : "=r"(r0), "=r"(r1), "=r"(r2), "=r"(r3) : "r"(addr));
}

__device__ __forceinline__ void ldsm_x4_trans(
    unsigned& r0, unsigned& r1, unsigned& r2, unsigned& r3, unsigned addr)
{
    asm volatile("ldmatrix.sync.aligned.m8n8.x4.trans.shared.b16 {%0,%1,%2,%3}, [%4];"
                 : "=r"(r0), "=r"(r1), "=r"(r2), "=r"(r3) : "r"(addr));
}

__device__ __forceinline__ unsigned pack_h2(float a, float b) {
    __half2 t = __floats2half2_rn(a, b);
    return *(unsigned*)&t;
}

__device__ __forceinline__ void cp_async16(unsigned smem_addr, const void* gptr) {
    asm volatile("cp.async.cg.shared.global [%0], [%1], 16;"
                 :: "r"(smem_addr), "l"(gptr));
}
__device__ __forceinline__ void cp_commit() {
    asm volatile("cp.async.commit_group;");
}
template<int N>
__device__ __forceinline__ void cp_wait() {
    asm volatile("cp.async.wait_group %0;" :: "n"(N));
}

// ---------------------------------------------------------------------------
// LayerNorm: fp32 in, fp16 out. One block per row, 256 threads.
// ---------------------------------------------------------------------------
__global__ __launch_bounds__(256) void ln_kernel(
    const float* __restrict__ x, const float* __restrict__ gam,
    const float* __restrict__ bet, __half* __restrict__ out)
{
    int row = blockIdx.x;
    int tid = threadIdx.x;
    const float* xr = x + (size_t)row * D_;
    float v0 = xr[tid], v1 = xr[tid + 256], v2 = xr[tid + 512];
    float s  = v0 + v1 + v2;
    float ss = v0*v0 + v1*v1 + v2*v2;
    #pragma unroll
    for (int o = 16; o > 0; o >>= 1) {
        s  += __shfl_xor_sync(0xffffffffu, s,  o);
        ss += __shfl_xor_sync(0xffffffffu, ss, o);
    }
    __shared__ float rs[8], rss[8];
    __shared__ float s_mu, s_inv;
    int w = tid >> 5, lane = tid & 31;
    if (lane == 0) { rs[w] = s; rss[w] = ss; }
    __syncthreads();
    if (tid == 0) {
        float ts = 0.f, tss = 0.f;
        #pragma unroll
        for (int i = 0; i < 8; i++) { ts += rs[i]; tss += rss[i]; }
        float mu  = ts * (1.0f / D_);
        float var = tss * (1.0f / D_) - mu * mu;
        s_mu = mu;
        s_inv = rsqrtf(var + 1e-6f);
    }
    __syncthreads();
    float mu = s_mu, inv = s_inv;
    __half* orow = out + (size_t)row * D_;
    orow[tid]       = __float2half_rn((v0 - mu) * inv * gam[tid]       + bet[tid]);
    orow[tid + 256] = __float2half_rn((v1 - mu) * inv * gam[tid + 256] + bet[tid + 256]);
    orow[tid + 512] = __float2half_rn((v2 - mu) * inv * gam[tid + 512] + bet[tid + 512]);
}

// ---------------------------------------------------------------------------
// Weight transpose + fp16 convert: out[c][r] = half(in[r][c]).
// ---------------------------------------------------------------------------
__global__ __launch_bounds__(256) void transpose_kernel(
    const float* __restrict__ in, __half* __restrict__ out, int R, int Ccols)
{
    __shared__ float t[32][33];
    int c0 = blockIdx.x * 32, r0 = blockIdx.y * 32;
    int x = threadIdx.x, y = threadIdx.y;
    #pragma unroll
    for (int i = 0; i < 32; i += 8)
        t[y + i][x] = in[(size_t)(r0 + y + i) * Ccols + c0 + x];
    __syncthreads();
    #pragma unroll
    for (int i = 0; i < 32; i += 8)
        out[(size_t)(c0 + y + i) * R + r0 + x] = __float2half_rn(t[x][y + i]);
}

// ---------------------------------------------------------------------------
// fp16 tensor-core GEMM: 128x128 tile, BK=64, 256 threads, warp tile 32x64,
// mma.sync.m16n8k16 + ldmatrix.x4, 3-stage cp.async pipeline.
// Row stride 72 halves: ldmatrix conflict-free, rows 16B-aligned.
// ---------------------------------------------------------------------------
#define BK 64
#define LDAH 72
#define STG_H (128*LDAH)          /* 9216 halves = 18KB per matrix per stage */
#define NSTG 3
#define GEMM_SMEM_BYTES (NSTG*2*STG_H*2)   /* 110592 B */

template<int EPI>
__device__ __forceinline__ void h_gemm_body(
    const __half* __restrict__ A, const __half* __restrict__ Bt,
    const float* __restrict__ bias, const float* __restrict__ res,
    void* __restrict__ Cout, int M, int N, int K)
{
    extern __shared__ __half hsm[];
    __half* As = hsm;
    __half* Bs = hsm + NSTG * STG_H;

    int tid  = threadIdx.x;
    int bm = blockIdx.y * 128, bn = blockIdx.x * 128;
    int lane = tid & 31, warp = tid >> 5;
    int warp_m = warp >> 1;
    int warp_n = warp & 1;
    int g  = lane >> 2;
    int tg = lane & 3;

    unsigned a_su[NSTG], b_su[NSTG];
    #pragma unroll
    for (int s = 0; s < NSTG; s++) {
        a_su[s] = (unsigned)__cvta_generic_to_shared(As + s * STG_H);
        b_su[s] = (unsigned)__cvta_generic_to_shared(Bs + s * STG_H);
    }

    // ldmatrix lane->address maps (halves)
    int arow_off = (lane & 7) + ((lane >> 3) & 1) * 8;
    int ak_off   = ((lane >> 4) & 1) * 8;
    int brow_off = (lane & 7) + ((lane >> 4) & 1) * 8;
    int bk_off   = ((lane >> 3) & 1) * 8;

    unsigned a_lm[2], b_lm[4];
    #pragma unroll
    for (int mt = 0; mt < 2; mt++)
        a_lm[mt] = (unsigned)(((warp_m * 32 + mt * 16 + arow_off) * LDAH + ak_off) * 2);
    #pragma unroll
    for (int p = 0; p < 4; p++)
        b_lm[p] = (unsigned)(((warp_n * 64 + p * 16 + brow_off) * LDAH + bk_off) * 2);

    float acc[2][8][4];
    #pragma unroll
    for (int mt = 0; mt < 2; mt++)
        #pragma unroll
        for (int nt = 0; nt < 8; nt++)
            #pragma unroll
            for (int i = 0; i < 4; i++) acc[mt][nt][i] = 0.f;

    int nck = K / BK;

    auto issue = [&](int st, int ck) {
        int kb = ck * BK;
        #pragma unroll
        for (int p = 0; p < 4; p++) {
            int cid = tid + p * 256;          // 0..1023 16B chunks per matrix
            int row = cid >> 3, c = cid & 7;
            unsigned off = (unsigned)((row * LDAH + c * 8) * 2);
            cp_async16(a_su[st] + off, A  + (size_t)(bm + row) * K + kb + c * 8);
            cp_async16(b_su[st] + off, Bt + (size_t)(bn + row) * K + kb + c * 8);
        }
        cp_commit();
    };

    issue(0, 0);
    if (nck > 1) issue(1, 1);

    for (int ck = 0; ck < nck; ck++) {
        int st = ck % 3;
        if (ck + 1 < nck) cp_wait<1>(); else cp_wait<0>();
        __syncthreads();
        if (ck + 2 < nck) issue((ck + 2) % 3, ck + 2);

        unsigned abase = a_su[st], bbase = b_su[st];

        #pragma unroll
        for (int ks = 0; ks < 4; ks++) {
            unsigned kadd = (unsigned)(ks * 16 * 2);
            unsigned af[2][4], bf[8][2];
            #pragma unroll
            for (int mt = 0; mt < 2; mt++)
                ldsm_x4(af[mt][0], af[mt][1], af[mt][2], af[mt][3],
                        abase + a_lm[mt] + kadd);
            #pragma unroll
            for (int p = 0; p < 4; p++)
                ldsm_x4(bf[2*p][0], bf[2*p][1], bf[2*p+1][0], bf[2*p+1][1],
                        bbase + b_lm[p] + kadd);
            #pragma unroll
            for (int mt = 0; mt < 2; mt++)
                #pragma unroll
                for (int nt = 0; nt < 8; nt++)
                    mma_f16(acc[mt][nt], af[mt], bf[nt]);
        }
    }
    __syncthreads();

    #pragma unroll
    for (int mt = 0; mt < 2; mt++) {
        #pragma unroll
        for (int nt = 0; nt < 8; nt++) {
            int row0 = bm + warp_m * 32 + mt * 16 + g;
            int row1 = row0 + 8;
            int col  = bn + warp_n * 64 + nt * 8 + tg * 2;
            float2 bb = *(const float2*)&bias[col];
            float v0 = acc[mt][nt][0] + bb.x;
            float v1 = acc[mt][nt][1] + bb.y;
            float v2 = acc[mt][nt][2] + bb.x;
            float v3 = acc[mt][nt][3] + bb.y;
            if (EPI == EPI_GELU) {
                v0 = gelu_f(v0); v1 = gelu_f(v1);
                v2 = gelu_f(v2); v3 = gelu_f(v3);
            }
            if (EPI == EPI_ADD) {
                float* C = (float*)Cout;
                float2 r0 = *(const float2*)&res[(size_t)row0 * N + col];
                float2 r1 = *(const float2*)&res[(size_t)row1 * N + col];
                v0 += r0.x; v1 += r0.y; v2 += r1.x; v3 += r1.y;
                *(float2*)&C[(size_t)row0 * N + col] = make_float2(v0, v1);
                *(float2*)&C[(size_t)row1 * N + col] = make_float2(v2, v3);
            } else {
                __half* C = (__half*)Cout;
                *(__half2*)&C[(size_t)row0 * N + col] = __floats2half2_rn(v0, v1);
                *(__half2*)&C[(size_t)row1 * N + col] = __floats2half2_rn(v2, v3);
            }
        }
    }
}

template<int EPI>
__global__ __launch_bounds__(256, 2) void h_gemm_kernel(
    const __half* __restrict__ A, const __half* __restrict__ Bt,
    const float* __restrict__ bias, const float* __restrict__ res,
    void* __restrict__ Cout, int M, int N, int K)
{
    h_gemm_body<EPI>(A, Bt, bias, res, Cout, M, N, K);
}

__global__ __launch_bounds__(256, 2) void h_qkv_kernel(
    const __half* __restrict__ A, const __half* __restrict__ wt,
    const float* __restrict__ bq, const float* __restrict__ bk, const float* __restrict__ bv,
    __half* __restrict__ Cq, __half* __restrict__ Ck, __half* __restrict__ Cv)
{
    const __half* Bt  = wt + (size_t)blockIdx.z * (768 * 768);
    const float*  bia = (blockIdx.z == 0) ? bq : (blockIdx.z == 1) ? bk : bv;
    __half*       C   = (blockIdx.z == 0) ? Cq : (blockIdx.z == 1) ? Ck : Cv;
    h_gemm_body<EPI_NONE>(A, Bt, bia, nullptr, (void*)C, NROWS, D_, D_);
}

// ---------------------------------------------------------------------------
// Fused attention, register-resident flash style.
// Block = (b, h, 128 query rows); 8 warps, each owns 16 FULL rows (all 64 keys)
// -> softmax is warp-local (shuffles only). K-tiles of 64.
// smem: Qh[128][72], Kh[64][72], Vh[64][72] (all fp16, natural layout).
// QK^T: A=Q ldmatrix, B=K ldmatrix. Scores stay in registers; softmax in regs;
// probs repack directly into P*V A-fragments. V via ldmatrix.x4.trans.
// ---------------------------------------------------------------------------
#define LQ 72
struct AttnSmem {
    __half Qh[128][LQ];
    __half Kh[64][LQ];
    __half Vh[64][LQ];
};

__global__ __launch_bounds__(256) void attn_kernel(
    const __half* __restrict__ q, const __half* __restrict__ k,
    const __half* __restrict__ v, __half* __restrict__ ctx)
{
    __shared__ AttnSmem S;
    int bb = blockIdx.z, hh = blockIdx.y;
    int q0 = blockIdx.x * 128;
    int tid = threadIdx.x;
    int lane = tid & 31, wid = tid >> 5;
    int g = lane >> 2, tg = lane & 3;
    int m0 = wid * 16;

    // ---- load Q (scaled by 1/8; exponent shift, fp16-exact) ----
    {
        const __half2 sc = __half2half2(__float2half(0.125f));
        #pragma unroll
        for (int i = 0; i < 4; i++) {
            int cid = tid + i * 256;        // 0..1023
            int row = cid >> 3, c = cid & 7;
            const __half* gq = q + ((size_t)((bb*S_ + q0 + row)*H_ + hh))*DH_ + c*8;
            uint4 t = *(const uint4*)gq;
            __half2* hp = (__half2*)&t;
            #pragma unroll
            for (int j = 0; j < 4; j++) hp[j] = __hmul2(hp[j], sc);
            *(uint4*)&S.Qh[row][c*8] = t;
        }
    }

    // ldmatrix lane->address maps
    int arow = (lane & 7) + ((lane >> 3) & 1) * 8;  // A / V-trans row pattern
    int acol = ((lane >> 4) & 1) * 8;
    int brow = (lane & 7) + ((lane >> 4) & 1) * 8;  // B (K) row pattern
    int bcol = ((lane >> 3) & 1) * 8;

    unsigned q_lm = (unsigned)__cvta_generic_to_shared(&S.Qh[m0 + arow][acol]);
    unsigned k_lm[4], v_lm[4][4];
    #pragma unroll
    for (int p = 0; p < 4; p++)
        k_lm[p] = (unsigned)__cvta_generic_to_shared(&S.Kh[p*16 + brow][bcol]);
    #pragma unroll
    for (int ks = 0; ks < 4; ks++)
        #pragma unroll
        for (int dp = 0; dp < 4; dp++)
            v_lm[ks][dp] = (unsigned)__cvta_generic_to_shared(
                &S.Vh[ks*16 + arow][dp*16 + acol]);

    float m_r[2] = {-1e30f, -1e30f};
    float l_r[2] = {0.f, 0.f};
    float o[8][4];
    #pragma unroll
    for (int nt = 0; nt < 8; nt++)
        #pragma unroll
        for (int i = 0; i < 4; i++) o[nt][i] = 0.f;

    __syncthreads();

    // preload Q fragments (constant across key tiles)
    unsigned aq[4][4];
    #pragma unroll
    for (int ks = 0; ks < 4; ks++)
        ldsm_x4(aq[ks][0], aq[ks][1], aq[ks][2], aq[ks][3], q_lm + ks*32);

    for (int kt = 0; kt < S_/64; kt++) {
        int k0g = kt * 64;
        // ---- load K and V tiles (natural layout, uint4) ----
        #pragma unroll
        for (int i = 0; i < 2; i++) {
            int cid = tid + i * 256;        // 0..511
            int row = cid >> 3, c = cid & 7;
            size_t base = ((size_t)((bb*S_ + k0g + row)*H_ + hh))*DH_ + c*8;
            *(uint4*)&S.Kh[row][c*8] = *(const uint4*)(k + base);
            *(uint4*)&S.Vh[row][c*8] = *(const uint4*)(v + base);
        }
        __syncthreads();

        // ---- QK^T -> s (fp32 regs), 16 rows x 64 keys per warp ----
        float s[8][4];
        #pragma unroll
        for (int nt = 0; nt < 8; nt++)
            #pragma unroll
            for (int i = 0; i < 4; i++) s[nt][i] = 0.f;
        #pragma unroll
        for (int ks = 0; ks < 4; ks++) {
            unsigned bf[8][2];
            #pragma unroll
            for (int p = 0; p < 4; p++)
                ldsm_x4(bf[2*p][0], bf[2*p][1], bf[2*p+1][0], bf[2*p+1][1],
                        k_lm[p] + ks*32);
            #pragma unroll
            for (int nt = 0; nt < 8; nt++)
                mma_f16(s[nt], aq[ks], bf[nt]);
        }

        // ---- warp-local online softmax (rows g and g+8) ----
        #pragma unroll
        for (int r = 0; r < 2; r++) {
            float mx = -1e30f;
            #pragma unroll
            for (int nt = 0; nt < 8; nt++)
                mx = fmaxf(mx, fmaxf(s[nt][2*r], s[nt][2*r+1]));
            mx = fmaxf(mx, __shfl_xor_sync(0xffffffffu, mx, 1));
            mx = fmaxf(mx, __shfl_xor_sync(0xffffffffu, mx, 2));
            float mn = fmaxf(m_r[r], mx);
            float cr = __expf(m_r[r] - mn);
            m_r[r] = mn;
            float ls = 0.f;
            #pragma unroll
            for (int nt = 0; nt < 8; nt++) {
                float p0 = __expf(s[nt][2*r    ] - mn);
                float p1 = __expf(s[nt][2*r + 1] - mn);
                s[nt][2*r] = p0; s[nt][2*r+1] = p1;
                ls += p0 + p1;
            }
            ls += __shfl_xor_sync(0xffffffffu, ls, 1);
            ls += __shfl_xor_sync(0xffffffffu, ls, 2);
            l_r[r] = l_r[r] * cr + ls;
            #pragma unroll
            for (int nt = 0; nt < 8; nt++) {
                o[nt][2*r] *= cr; o[nt][2*r+1] *= cr;
            }
        }

        // ---- repack probs into P*V A-fragments ----
        unsigned pa[4][4];
        #pragma unroll
        for (int ks = 0; ks < 4; ks++) {
            pa[ks][0] = pack_h2(s[2*ks  ][0], s[2*ks  ][1]);
            pa[ks][1] = pack_h2(s[2*ks  ][2], s[2*ks  ][3]);
            pa[ks][2] = pack_h2(s[2*ks+1][0], s[2*ks+1][1]);
            pa[ks][3] = pack_h2(s[2*ks+1][2], s[2*ks+1][3]);
        }

        // ---- P*V accumulate: B = V via ldmatrix.trans ----
        #pragma unroll
        for (int ks = 0; ks < 4; ks++) {
            unsigned vf[8][2];
            #pragma unroll
            for (int dp = 0; dp < 4; dp++)
                ldsm_x4_trans(vf[2*dp][0], vf[2*dp][1], vf[2*dp+1][0], vf[2*dp+1][1],
                              v_lm[ks][dp]);
            #pragma unroll
            for (int nt = 0; nt < 8; nt++)
                mma_f16(o[nt], pa[ks], vf[nt]);
        }
        __syncthreads();
    }

    // ---- finalize ----
    float inv0 = 1.0f / l_r[0];
    float inv1 = 1.0f / l_r[1];
    int row0 = bb*S_ + q0 + m0 + g;
    int row1 = row0 + 8;
    #pragma unroll
    for (int nt = 0; nt < 8; nt++) {
        int d = nt * 8 + tg * 2;
        *(__half2*)&ctx[((size_t)(row0*H_ + hh))*DH_ + d] =
            __floats2half2_rn(o[nt][0] * inv0, o[nt][1] * inv0);
        *(__half2*)&ctx[((size_t)(row1*H_ + hh))*DH_ + d] =
            __floats2half2_rn(o[nt][2] * inv1, o[nt][3] * inv1);
    }
}

// ---------------------------------------------------------------------------
// Launcher
// ---------------------------------------------------------------------------
extern "C" void kernel_launch(void* const* d_in, const int* in_sizes, int n_in,
                              void* d_out, int out_size)
{
    const float* x   = (const float*)d_in[0];
    const float* Wq  = (const float*)d_in[1];
    const float* bq  = (const float*)d_in[2];
    const float* Wk  = (const float*)d_in[3];
    const float* bk  = (const float*)d_in[4];
    const float* Wv  = (const float*)d_in[5];
    const float* bv  = (const float*)d_in[6];
    const float* Wo  = (const float*)d_in[7];
    const float* bo  = (const float*)d_in[8];
    const float* g1  = (const float*)d_in[9];
    const float* be1 = (const float*)d_in[10];
    const float* g2  = (const float*)d_in[11];
    const float* be2 = (const float*)d_in[12];
    const float* W1  = (const float*)d_in[13];
    const float* b1  = (const float*)d_in[14];
    const float* W2  = (const float*)d_in[15];
    const float* b2  = (const float*)d_in[16];
    float* out = (float*)d_out;

    __half *h, *q, *k, *v, *ctx, *ln2, *act, *wt;
    float *x2;
    cudaGetSymbolAddress((void**)&h,   g_h);
    cudaGetSymbolAddress((void**)&q,   g_q);
    cudaGetSymbolAddress((void**)&k,   g_k);
    cudaGetSymbolAddress((void**)&v,   g_v);
    cudaGetSymbolAddress((void**)&ctx, g_ctx);
    cudaGetSymbolAddress((void**)&x2,  g_x2);
    cudaGetSymbolAddress((void**)&ln2, g_ln2);
    cudaGetSymbolAddress((void**)&act, g_act);
    cudaGetSymbolAddress((void**)&wt,  g_wt);

    cudaFuncSetAttribute(h_gemm_kernel<EPI_ADD>,
                         cudaFuncAttributeMaxDynamicSharedMemorySize, GEMM_SMEM_BYTES);
    cudaFuncSetAttribute(h_gemm_kernel<EPI_GELU>,
                         cudaFuncAttributeMaxDynamicSharedMemorySize, GEMM_SMEM_BYTES);
    cudaFuncSetAttribute(h_qkv_kernel,
                         cudaFuncAttributeMaxDynamicSharedMemorySize, GEMM_SMEM_BYTES);

    dim3 tb(32, 8);
    // 0. weight transpose + fp16 convert
    transpose_kernel<<<dim3(24, 24), tb>>>(Wq, wt + WT_Q,  768, 768);
    transpose_kernel<<<dim3(24, 24), tb>>>(Wk, wt + WT_K,  768, 768);
    transpose_kernel<<<dim3(24, 24), tb>>>(Wv, wt + WT_V,  768, 768);
    transpose_kernel<<<dim3(24, 24), tb>>>(Wo, wt + WT_O,  768, 768);
    transpose_kernel<<<dim3(96, 24), tb>>>(W1, wt + WT_W1, 768, 3072);
    transpose_kernel<<<dim3(24, 96), tb>>>(W2, wt + WT_W2, 3072, 768);

    // 1. pre-LN -> fp16 h
    ln_kernel<<<NROWS, 256>>>(x, g1, be1, h);
    // 2. QKV (fp16 mma, batched) -> fp16 q,k,v
    dim3 gqkv(D_/128, NROWS/128, 3);
    h_qkv_kernel<<<gqkv, 256, GEMM_SMEM_BYTES>>>(h, wt, bq, bk, bv, q, k, v);
    // 3. fused attention (register flash, fp16 mma) -> fp16 ctx
    dim3 gat(S_/128, H_, B_);
    attn_kernel<<<gat, 256>>>(q, k, v, ctx);
    // 4. Wo projection + residual -> fp32 x2
    dim3 go(D_/128, NROWS/128);
    h_gemm_kernel<EPI_ADD><<<go, 256, GEMM_SMEM_BYTES>>>(ctx, wt + WT_O, bo, x, (void*)x2, NROWS, D_, D_);
    // 5. LN2 -> fp16 ln2
    ln_kernel<<<NROWS, 256>>>(x2, g2, be2, ln2);
    // 6. MLP up + exact GELU -> fp16 act
    dim3 gup(F_/128, NROWS/128);
    h_gemm_kernel<EPI_GELU><<<gup, 256, GEMM_SMEM_BYTES>>>(ln2, wt + WT_W1, b1, nullptr, (void*)act, NROWS, F_, D_);
    // 7. MLP down + bias + residual -> fp32 out
    dim3 gdn(D_/128, NROWS/128);
    h_gemm_kernel<EPI_ADD><<<gdn, 256, GEMM_SMEM_BYTES>>>(act, wt + WT_W2, b2, x2, (void*)out, NROWS, D_, F_);
}

// round 11
// speedup vs baseline: 5.7834x; 1.0195x over previous
#include <cuda_runtime.h>
#include <cuda_fp16.h>
#include <math.h>
#include <stdint.h>

#define B_  8
#define S_  1024
#define D_  768
#define H_  12
#define DH_ 64
#define F_  3072
#define NROWS (B_*S_)   /* 8192 */

#define EPI_NONE 0
#define EPI_GELU 1
#define EPI_ADD  2

// ---------------------------------------------------------------------------
// Scratch (device globals — no allocation allowed)
// ---------------------------------------------------------------------------
__device__ __half g_h  [NROWS*D_];
__device__ __half g_q  [NROWS*D_];
__device__ __half g_k  [NROWS*D_];
__device__ __half g_v  [NROWS*D_];
__device__ __half g_ctx[NROWS*D_];
__device__ float  g_x2 [NROWS*D_];
__device__ __half g_ln2[NROWS*D_];
__device__ __half g_act[NROWS*F_];
// fp16 weights, NATURAL layout [K][N]
#define WT_Q  0
#define WT_K  (768*768)
#define WT_V  (2*768*768)
#define WT_O  (3*768*768)
#define WT_W1 (4*768*768)
#define WT_W2 (4*768*768 + 768*3072)
__device__ __half g_wt [4*768*768 + 2*768*3072];

// ---------------------------------------------------------------------------
// helpers
// ---------------------------------------------------------------------------
__device__ __forceinline__ float gelu_f(float x) {
    return 0.5f * x * (1.0f + erff(x * 0.70710678118654752f));
}

__device__ __forceinline__ void mma_f16(
    float c[4], const unsigned a[4], const unsigned b[2])
{
    asm volatile(
        "mma.sync.aligned.m16n8k16.row.col.f32.f16.f16.f32 "
        "{%0,%1,%2,%3}, {%4,%5,%6,%7}, {%8,%9}, {%0,%1,%2,%3};"
        : "+f"(c[0]), "+f"(c[1]), "+f"(c[2]), "+f"(c[3])
        : "r"(a[0]), "r"(a[1]), "r"(a[2]), "r"(a[3]),
          "r"(b[0]), "r"(b[1]));
}

__device__ __forceinline__ void ldsm_x4(
    unsigned& r0, unsigned& r1, unsigned& r2, unsigned& r3, unsigned addr)
{
    asm volatile("ldmatrix.sync.aligned.m8n8.x4.shared.b16 {%0,%1,%2,%3}, [%4];"
                 : "=r"(r0), "=r"(r1), "=r"(r2), "=r"(r3) : "r"(addr));
}

__device__ __forceinline__ void ldsm_x4_trans(
    unsigned& r0, unsigned& r1, unsigned& r2, unsigned& r3, unsigned addr)
{
    asm volatile("ldmatrix.sync.aligned.m8n8.x4.trans.shared.b16 {%0,%1,%2,%3}, [%4];"
                 : "=r"(r0), "=r"(r1), "=r"(r2), "=r"(r3) : "r"(addr));
}

__device__ __forceinline__ unsigned pack_h2(float a, float b) {
    __half2 t = __floats2half2_rn(a, b);
    return *(unsigned*)&t;
}

__device__ __forceinline__ void cp_async16(unsigned smem_addr, const void* gptr) {
    asm volatile("cp.async.cg.shared.global [%0], [%1], 16;"
                 :: "r"(smem_addr), "l"(gptr));
}
__device__ __forceinline__ void cp_commit() {
    asm volatile("cp.async.commit_group;");
}
template<int N>
__device__ __forceinline__ void cp_wait() {
    asm volatile("cp.async.wait_group %0;" :: "n"(N));
}

// ---------------------------------------------------------------------------
// Weight convert (fp32 -> fp16, natural layout). One launch for all 6.
// ---------------------------------------------------------------------------
__global__ __launch_bounds__(256) void convert_w_kernel(
    const float* __restrict__ Wq, const float* __restrict__ Wk,
    const float* __restrict__ Wv, const float* __restrict__ Wo,
    const float* __restrict__ W1, const float* __restrict__ W2,
    __half* __restrict__ out)
{
    const int n1 = 768*768/2;        // half2 units per square weight
    const int n2 = 768*3072/2;
    const int total = 4*n1 + 2*n2;
    for (int i = blockIdx.x*blockDim.x + threadIdx.x; i < total;
         i += gridDim.x*blockDim.x) {
        const float2* src; int off;
        if (i < 4*n1) {
            int w = i / n1; off = i - w*n1;
            src = (const float2*)((w==0)?Wq:(w==1)?Wk:(w==2)?Wv:Wo);
        } else if (i < 4*n1 + n2) {
            src = (const float2*)W1; off = i - 4*n1;
        } else {
            src = (const float2*)W2; off = i - 4*n1 - n2;
        }
        float2 f = src[off];
        ((__half2*)out)[i] = __floats2half2_rn(f.x, f.y);
    }
}

// ---------------------------------------------------------------------------
// LayerNorm: warp-per-row, 8 rows/block, shuffle-only reduction.
// ---------------------------------------------------------------------------
__global__ __launch_bounds__(256) void ln_kernel(
    const float* __restrict__ x, const float* __restrict__ gam,
    const float* __restrict__ bet, __half* __restrict__ out)
{
    int warp = threadIdx.x >> 5, lane = threadIdx.x & 31;
    int row = blockIdx.x * 8 + warp;
    const float4* xr = (const float4*)(x + (size_t)row * D_);

    float4 vv[6];
    float s = 0.f, ss = 0.f;
    #pragma unroll
    for (int c = 0; c < 6; c++) {
        float4 t = xr[c*32 + lane];
        vv[c] = t;
        s  += t.x + t.y + t.z + t.w;
        ss += t.x*t.x + t.y*t.y + t.z*t.z + t.w*t.w;
    }
    #pragma unroll
    for (int o = 16; o > 0; o >>= 1) {
        s  += __shfl_xor_sync(0xffffffffu, s,  o);
        ss += __shfl_xor_sync(0xffffffffu, ss, o);
    }
    float mu  = s * (1.0f / D_);
    float var = ss * (1.0f / D_) - mu * mu;
    float inv = rsqrtf(var + 1e-6f);

    uint2* orow = (uint2*)(out + (size_t)row * D_);
    const float4* gg4 = (const float4*)gam;
    const float4* bb4 = (const float4*)bet;
    #pragma unroll
    for (int c = 0; c < 6; c++) {
        int idx = c*32 + lane;
        float4 gg = gg4[idx], bb = bb4[idx];
        float4 t = vv[c];
        float v0 = (t.x - mu) * inv * gg.x + bb.x;
        float v1 = (t.y - mu) * inv * gg.y + bb.y;
        float v2 = (t.z - mu) * inv * gg.z + bb.z;
        float v3 = (t.w - mu) * inv * gg.w + bb.w;
        uint2 o2;
        o2.x = pack_h2(v0, v1);
        o2.y = pack_h2(v2, v3);
        orow[idx] = o2;
    }
}

// ---------------------------------------------------------------------------
// fp16 tensor-core GEMM: 128x128 tile, BK=64, 256 threads, warp tile 32x64.
// A: [M][K] fp16, smem [m][k] stride 72, ldmatrix.x4 (row-major frags).
// B: NATURAL W [K][N] fp16, smem [k][n] stride 136, ldmatrix.x4.trans
//    (col-major frags) — same pattern as attention's V path (validated R9).
// 3-stage cp.async pipeline.
// ---------------------------------------------------------------------------
#define BK 64
#define LDAH 72
#define LDBH 136
#define A_STG_H (128*LDAH)        /* 9216 halves */
#define B_STG_H (64*LDBH)         /* 8704 halves */
#define NSTG 3
#define GEMM_SMEM_BYTES (NSTG*(A_STG_H + B_STG_H)*2)   /* 107520 B */

template<int EPI>
__device__ __forceinline__ void h_gemm_body(
    const __half* __restrict__ A, const __half* __restrict__ W,
    const float* __restrict__ bias, const float* __restrict__ res,
    void* __restrict__ Cout, int M, int N, int K)
{
    extern __shared__ __half hsm[];
    __half* As = hsm;
    __half* Bs = hsm + NSTG * A_STG_H;

    int tid  = threadIdx.x;
    int bm = blockIdx.y * 128, bn = blockIdx.x * 128;
    int lane = tid & 31, warp = tid >> 5;
    int warp_m = warp >> 1;
    int warp_n = warp & 1;
    int g  = lane >> 2;
    int tg = lane & 3;

    unsigned a_su[NSTG], b_su[NSTG];
    #pragma unroll
    for (int s = 0; s < NSTG; s++) {
        a_su[s] = (unsigned)__cvta_generic_to_shared(As + s * A_STG_H);
        b_su[s] = (unsigned)__cvta_generic_to_shared(Bs + s * B_STG_H);
    }

    // A ldmatrix lane map (row-major fragments)
    int arow_off = (lane & 7) + ((lane >> 3) & 1) * 8;
    int ak_off   = ((lane >> 4) & 1) * 8;
    unsigned a_lm[2];
    #pragma unroll
    for (int mt = 0; mt < 2; mt++)
        a_lm[mt] = (unsigned)(((warp_m * 32 + mt * 16 + arow_off) * LDAH + ak_off) * 2);

    // B trans-ldmatrix lane map (mirrors attention V path)
    int trow = (lane & 7) + ((lane >> 3) & 1) * 8;   // k-row within 16
    int tcol = ((lane >> 4) & 1) * 8;                // n-col within 16
    unsigned b_lm[4];
    #pragma unroll
    for (int dp = 0; dp < 4; dp++)
        b_lm[dp] = (unsigned)((trow * LDBH + warp_n * 64 + dp * 16 + tcol) * 2);

    float acc[2][8][4];
    #pragma unroll
    for (int mt = 0; mt < 2; mt++)
        #pragma unroll
        for (int nt = 0; nt < 8; nt++)
            #pragma unroll
            for (int i = 0; i < 4; i++) acc[mt][nt][i] = 0.f;

    int nck = K / BK;

    auto issue = [&](int st, int ck) {
        int kb = ck * BK;
        // A: 128 rows x 64 halves = 1024 16B chunks
        #pragma unroll
        for (int p = 0; p < 4; p++) {
            int cid = tid + p * 256;
            int row = cid >> 3, c = cid & 7;
            unsigned off = (unsigned)((row * LDAH + c * 8) * 2);
            cp_async16(a_su[st] + off, A + (size_t)(bm + row) * K + kb + c * 8);
        }
        // B: 64 k-rows x 128 n-cols = 1024 16B chunks (16 per row)
        #pragma unroll
        for (int p = 0; p < 4; p++) {
            int cid = tid + p * 256;
            int row = cid >> 4, c = cid & 15;
            unsigned off = (unsigned)((row * LDBH + c * 8) * 2);
            cp_async16(b_su[st] + off, W + (size_t)(kb + row) * N + bn + c * 8);
        }
        cp_commit();
    };

    issue(0, 0);
    if (nck > 1) issue(1, 1);

    for (int ck = 0; ck < nck; ck++) {
        int st = ck % 3;
        if (ck + 1 < nck) cp_wait<1>(); else cp_wait<0>();
        __syncthreads();
        if (ck + 2 < nck) issue((ck + 2) % 3, ck + 2);

        unsigned abase = a_su[st], bbase = b_su[st];

        #pragma unroll
        for (int ks = 0; ks < 4; ks++) {
            unsigned kadd_a = (unsigned)(ks * 16 * 2);          // along row
            unsigned kadd_b = (unsigned)(ks * 16 * LDBH * 2);   // along k-rows
            unsigned af[2][4], bf[8][2];
            #pragma unroll
            for (int mt = 0; mt < 2; mt++)
                ldsm_x4(af[mt][0], af[mt][1], af[mt][2], af[mt][3],
                        abase + a_lm[mt] + kadd_a);
            #pragma unroll
            for (int dp = 0; dp < 4; dp++)
                ldsm_x4_trans(bf[2*dp][0], bf[2*dp][1], bf[2*dp+1][0], bf[2*dp+1][1],
                              bbase + b_lm[dp] + kadd_b);
            #pragma unroll
            for (int mt = 0; mt < 2; mt++)
                #pragma unroll
                for (int nt = 0; nt < 8; nt++)
                    mma_f16(acc[mt][nt], af[mt], bf[nt]);
        }
    }
    __syncthreads();

    #pragma unroll
    for (int mt = 0; mt < 2; mt++) {
        #pragma unroll
        for (int nt = 0; nt < 8; nt++) {
            int row0 = bm + warp_m * 32 + mt * 16 + g;
            int row1 = row0 + 8;
            int col  = bn + warp_n * 64 + nt * 8 + tg * 2;
            float2 bb = *(const float2*)&bias[col];
            float v0 = acc[mt][nt][0] + bb.x;
            float v1 = acc[mt][nt][1] + bb.y;
            float v2 = acc[mt][nt][2] + bb.x;
            float v3 = acc[mt][nt][3] + bb.y;
            if (EPI == EPI_GELU) {
                v0 = gelu_f(v0); v1 = gelu_f(v1);
                v2 = gelu_f(v2); v3 = gelu_f(v3);
            }
            if (EPI == EPI_ADD) {
                float* C = (float*)Cout;
                float2 r0 = *(const float2*)&res[(size_t)row0 * N + col];
                float2 r1 = *(const float2*)&res[(size_t)row1 * N + col];
                v0 += r0.x; v1 += r0.y; v2 += r1.x; v3 += r1.y;
                *(float2*)&C[(size_t)row0 * N + col] = make_float2(v0, v1);
                *(float2*)&C[(size_t)row1 * N + col] = make_float2(v2, v3);
            } else {
                __half* C = (__half*)Cout;
                *(__half2*)&C[(size_t)row0 * N + col] = __floats2half2_rn(v0, v1);
                *(__half2*)&C[(size_t)row1 * N + col] = __floats2half2_rn(v2, v3);
            }
        }
    }
}

template<int EPI>
__global__ __launch_bounds__(256, 2) void h_gemm_kernel(
    const __half* __restrict__ A, const __half* __restrict__ W,
    const float* __restrict__ bias, const float* __restrict__ res,
    void* __restrict__ Cout, int M, int N, int K)
{
    h_gemm_body<EPI>(A, W, bias, res, Cout, M, N, K);
}

__global__ __launch_bounds__(256, 2) void h_qkv_kernel(
    const __half* __restrict__ A, const __half* __restrict__ wt,
    const float* __restrict__ bq, const float* __restrict__ bk, const float* __restrict__ bv,
    __half* __restrict__ Cq, __half* __restrict__ Ck, __half* __restrict__ Cv)
{
    const __half* W   = wt + (size_t)blockIdx.z * (768 * 768);
    const float*  bia = (blockIdx.z == 0) ? bq : (blockIdx.z == 1) ? bk : bv;
    __half*       C   = (blockIdx.z == 0) ? Cq : (blockIdx.z == 1) ? Ck : Cv;
    h_gemm_body<EPI_NONE>(A, W, bia, nullptr, (void*)C, NROWS, D_, D_);
}

// ---------------------------------------------------------------------------
// Fused attention, register-resident flash style (validated R9).
// ---------------------------------------------------------------------------
#define LQ 72
struct AttnSmem {
    __half Qh[128][LQ];
    __half Kh[64][LQ];
    __half Vh[64][LQ];
};

__global__ __launch_bounds__(256) void attn_kernel(
    const __half* __restrict__ q, const __half* __restrict__ k,
    const __half* __restrict__ v, __half* __restrict__ ctx)
{
    __shared__ AttnSmem S;
    int bb = blockIdx.z, hh = blockIdx.y;
    int q0 = blockIdx.x * 128;
    int tid = threadIdx.x;
    int lane = tid & 31, wid = tid >> 5;
    int g = lane >> 2, tg = lane & 3;
    int m0 = wid * 16;

    {
        const __half2 sc = __half2half2(__float2half(0.125f));
        #pragma unroll
        for (int i = 0; i < 4; i++) {
            int cid = tid + i * 256;
            int row = cid >> 3, c = cid & 7;
            const __half* gq = q + ((size_t)((bb*S_ + q0 + row)*H_ + hh))*DH_ + c*8;
            uint4 t = *(const uint4*)gq;
            __half2* hp = (__half2*)&t;
            #pragma unroll
            for (int j = 0; j < 4; j++) hp[j] = __hmul2(hp[j], sc);
            *(uint4*)&S.Qh[row][c*8] = t;
        }
    }

    int arow = (lane & 7) + ((lane >> 3) & 1) * 8;
    int acol = ((lane >> 4) & 1) * 8;
    int brow = (lane & 7) + ((lane >> 4) & 1) * 8;
    int bcol = ((lane >> 3) & 1) * 8;

    unsigned q_lm = (unsigned)__cvta_generic_to_shared(&S.Qh[m0 + arow][acol]);
    unsigned k_lm[4], v_lm[4][4];
    #pragma unroll
    for (int p = 0; p < 4; p++)
        k_lm[p] = (unsigned)__cvta_generic_to_shared(&S.Kh[p*16 + brow][bcol]);
    #pragma unroll
    for (int ks = 0; ks < 4; ks++)
        #pragma unroll
        for (int dp = 0; dp < 4; dp++)
            v_lm[ks][dp] = (unsigned)__cvta_generic_to_shared(
                &S.Vh[ks*16 + arow][dp*16 + acol]);

    float m_r[2] = {-1e30f, -1e30f};
    float l_r[2] = {0.f, 0.f};
    float o[8][4];
    #pragma unroll
    for (int nt = 0; nt < 8; nt++)
        #pragma unroll
        for (int i = 0; i < 4; i++) o[nt][i] = 0.f;

    __syncthreads();

    unsigned aq[4][4];
    #pragma unroll
    for (int ks = 0; ks < 4; ks++)
        ldsm_x4(aq[ks][0], aq[ks][1], aq[ks][2], aq[ks][3], q_lm + ks*32);

    for (int kt = 0; kt < S_/64; kt++) {
        int k0g = kt * 64;
        #pragma unroll
        for (int i = 0; i < 2; i++) {
            int cid = tid + i * 256;
            int row = cid >> 3, c = cid & 7;
            size_t base = ((size_t)((bb*S_ + k0g + row)*H_ + hh))*DH_ + c*8;
            *(uint4*)&S.Kh[row][c*8] = *(const uint4*)(k + base);
            *(uint4*)&S.Vh[row][c*8] = *(const uint4*)(v + base);
        }
        __syncthreads();

        float s[8][4];
        #pragma unroll
        for (int nt = 0; nt < 8; nt++)
            #pragma unroll
            for (int i = 0; i < 4; i++) s[nt][i] = 0.f;
        #pragma unroll
        for (int ks = 0; ks < 4; ks++) {
            unsigned bf[8][2];
            #pragma unroll
            for (int p = 0; p < 4; p++)
                ldsm_x4(bf[2*p][0], bf[2*p][1], bf[2*p+1][0], bf[2*p+1][1],
                        k_lm[p] + ks*32);
            #pragma unroll
            for (int nt = 0; nt < 8; nt++)
                mma_f16(s[nt], aq[ks], bf[nt]);
        }

        #pragma unroll
        for (int r = 0; r < 2; r++) {
            float mx = -1e30f;
            #pragma unroll
            for (int nt = 0; nt < 8; nt++)
                mx = fmaxf(mx, fmaxf(s[nt][2*r], s[nt][2*r+1]));
            mx = fmaxf(mx, __shfl_xor_sync(0xffffffffu, mx, 1));
            mx = fmaxf(mx, __shfl_xor_sync(0xffffffffu, mx, 2));
            float mn = fmaxf(m_r[r], mx);
            float cr = __expf(m_r[r] - mn);
            m_r[r] = mn;
            float ls = 0.f;
            #pragma unroll
            for (int nt = 0; nt < 8; nt++) {
                float p0 = __expf(s[nt][2*r    ] - mn);
                float p1 = __expf(s[nt][2*r + 1] - mn);
                s[nt][2*r] = p0; s[nt][2*r+1] = p1;
                ls += p0 + p1;
            }
            ls += __shfl_xor_sync(0xffffffffu, ls, 1);
            ls += __shfl_xor_sync(0xffffffffu, ls, 2);
            l_r[r] = l_r[r] * cr + ls;
            #pragma unroll
            for (int nt = 0; nt < 8; nt++) {
                o[nt][2*r] *= cr; o[nt][2*r+1] *= cr;
            }
        }

        unsigned pa[4][4];
        #pragma unroll
        for (int ks = 0; ks < 4; ks++) {
            pa[ks][0] = pack_h2(s[2*ks  ][0], s[2*ks  ][1]);
            pa[ks][1] = pack_h2(s[2*ks  ][2], s[2*ks  ][3]);
            pa[ks][2] = pack_h2(s[2*ks+1][0], s[2*ks+1][1]);
            pa[ks][3] = pack_h2(s[2*ks+1][2], s[2*ks+1][3]);
        }

        #pragma unroll
        for (int ks = 0; ks < 4; ks++) {
            unsigned vf[8][2];
            #pragma unroll
            for (int dp = 0; dp < 4; dp++)
                ldsm_x4_trans(vf[2*dp][0], vf[2*dp][1], vf[2*dp+1][0], vf[2*dp+1][1],
                              v_lm[ks][dp]);
            #pragma unroll
            for (int nt = 0; nt < 8; nt++)
                mma_f16(o[nt], pa[ks], vf[nt]);
        }
        __syncthreads();
    }

    float inv0 = 1.0f / l_r[0];
    float inv1 = 1.0f / l_r[1];
    int row0 = bb*S_ + q0 + m0 + g;
    int row1 = row0 + 8;
    #pragma unroll
    for (int nt = 0; nt < 8; nt++) {
        int d = nt * 8 + tg * 2;
        *(__half2*)&ctx[((size_t)(row0*H_ + hh))*DH_ + d] =
            __floats2half2_rn(o[nt][0] * inv0, o[nt][1] * inv0);
        *(__half2*)&ctx[((size_t)(row1*H_ + hh))*DH_ + d] =
            __floats2half2_rn(o[nt][2] * inv1, o[nt][3] * inv1);
    }
}

// ---------------------------------------------------------------------------
// Launcher
// ---------------------------------------------------------------------------
extern "C" void kernel_launch(void* const* d_in, const int* in_sizes, int n_in,
                              void* d_out, int out_size)
{
    const float* x   = (const float*)d_in[0];
    const float* Wq  = (const float*)d_in[1];
    const float* bq  = (const float*)d_in[2];
    const float* Wk  = (const float*)d_in[3];
    const float* bk  = (const float*)d_in[4];
    const float* Wv  = (const float*)d_in[5];
    const float* bv  = (const float*)d_in[6];
    const float* Wo  = (const float*)d_in[7];
    const float* bo  = (const float*)d_in[8];
    const float* g1  = (const float*)d_in[9];
    const float* be1 = (const float*)d_in[10];
    const float* g2  = (const float*)d_in[11];
    const float* be2 = (const float*)d_in[12];
    const float* W1  = (const float*)d_in[13];
    const float* b1  = (const float*)d_in[14];
    const float* W2  = (const float*)d_in[15];
    const float* b2  = (const float*)d_in[16];
    float* out = (float*)d_out;

    __half *h, *q, *k, *v, *ctx, *ln2, *act, *wt;
    float *x2;
    cudaGetSymbolAddress((void**)&h,   g_h);
    cudaGetSymbolAddress((void**)&q,   g_q);
    cudaGetSymbolAddress((void**)&k,   g_k);
    cudaGetSymbolAddress((void**)&v,   g_v);
    cudaGetSymbolAddress((void**)&ctx, g_ctx);
    cudaGetSymbolAddress((void**)&x2,  g_x2);
    cudaGetSymbolAddress((void**)&ln2, g_ln2);
    cudaGetSymbolAddress((void**)&act, g_act);
    cudaGetSymbolAddress((void**)&wt,  g_wt);

    cudaFuncSetAttribute(h_gemm_kernel<EPI_ADD>,
                         cudaFuncAttributeMaxDynamicSharedMemorySize, GEMM_SMEM_BYTES);
    cudaFuncSetAttribute(h_gemm_kernel<EPI_GELU>,
                         cudaFuncAttributeMaxDynamicSharedMemorySize, GEMM_SMEM_BYTES);
    cudaFuncSetAttribute(h_qkv_kernel,
                         cudaFuncAttributeMaxDynamicSharedMemorySize, GEMM_SMEM_BYTES);

    // 0. weight fp32->fp16 convert (natural layout), single launch
    convert_w_kernel<<<2048, 256>>>(Wq, Wk, Wv, Wo, W1, W2, wt);

    // 1. pre-LN -> fp16 h
    ln_kernel<<<NROWS/8, 256>>>(x, g1, be1, h);
    // 2. QKV (fp16 mma, batched) -> fp16 q,k,v
    dim3 gqkv(D_/128, NROWS/128, 3);
    h_qkv_kernel<<<gqkv, 256, GEMM_SMEM_BYTES>>>(h, wt, bq, bk, bv, q, k, v);
    // 3. fused attention (register flash, fp16 mma) -> fp16 ctx
    dim3 gat(S_/128, H_, B_);
    attn_kernel<<<gat, 256>>>(q, k, v, ctx);
    // 4. Wo projection + residual -> fp32 x2
    dim3 go(D_/128, NROWS/128);
    h_gemm_kernel<EPI_ADD><<<go, 256, GEMM_SMEM_BYTES>>>(ctx, wt + WT_O, bo, x, (void*)x2, NROWS, D_, D_);
    // 5. LN2 -> fp16 ln2
    ln_kernel<<<NROWS/8, 256>>>(x2, g2, be2, ln2);
    // 6. MLP up + exact GELU -> fp16 act
    dim3 gup(F_/128, NROWS/128);
    h_gemm_kernel<EPI_GELU><<<gup, 256, GEMM_SMEM_BYTES>>>(ln2, wt + WT_W1, b1, nullptr, (void*)act, NROWS, F_, D_);
    // 7. MLP down + bias + residual -> fp32 out
    dim3 gdn(D_/128, NROWS/128);
    h_gemm_kernel<EPI_ADD><<<gdn, 256, GEMM_SMEM_BYTES>>>(act, wt + WT_W2, b2, x2, (void*)out, NROWS, D_, F_);
}